// round 9
// baseline (speedup 1.0000x reference)
#include <cuda_runtime.h>
#include <cuda_bf16.h>
#include <math.h>
#include <stdint.h>

// ---------------------------------------------------------------------------
// Problem constants
// ---------------------------------------------------------------------------
#define NTOK   8192
#define INDIM  1024
#define DMODEL 512
#define NHEADS 8
#define DH     64
#define MLAND  256
#define LWIN   33
#define NP     8448          // padded attention length
#define NHTOK  8282          // tokens incl cls
#define PADF   166
#define HSQ    91
#define NFEAT  8281
#define NWRAP  89
#define EPSLN  1e-5f

#define FLAG_RELU 1
#define FLAG_ACC  2

// ---------------------------------------------------------------------------
// Scratch (device globals)
// ---------------------------------------------------------------------------
__device__ float g_H  [NHTOK * DMODEL];
__device__ float g_H2 [NHTOK * DMODEL];
__device__ float g_XP [NP * DMODEL];
__device__ float g_QKV[NP * 3 * DMODEL];
__device__ float g_QL [NHEADS * MLAND * DH];
__device__ float g_KL [NHEADS * MLAND * DH];
__device__ float g_A2 [NHEADS * MLAND * MLAND];
__device__ float g_Z0 [NHEADS * MLAND * MLAND];
__device__ float g_Z1 [NHEADS * MLAND * MLAND];
__device__ float g_W1 [NHEADS * MLAND * MLAND];
__device__ float g_W2 [NHEADS * MLAND * MLAND];
__device__ float g_W3 [NHEADS * MLAND * MLAND];
__device__ float g_PS [NHEADS];
__device__ float g_A3V[NHEADS * MLAND * DH];
__device__ float g_S  [NHEADS * MLAND * NP];     // S3 logits
__device__ float g_S2 [NHEADS * NP * MLAND];     // S1 logits (side stream)
__device__ float g_PVP[8 * NHEADS * MLAND * DH]; // split-K partials
// bf16 hi/lo staging
__device__ __nv_bfloat16 g_AH[NP * INDIM];       // reused: Qh [8][NP][64] + Kh [8][NP][64]; later out-proj A
__device__ __nv_bfloat16 g_AL[NP * INDIM];
__device__ __nv_bfloat16 g_WH[3 * DMODEL * DMODEL];
__device__ __nv_bfloat16 g_WL[3 * DMODEL * DMODEL];
__device__ __nv_bfloat16 g_QLH[NHEADS * MLAND * DH];
__device__ __nv_bfloat16 g_QLL[NHEADS * MLAND * DH];
__device__ __nv_bfloat16 g_KLH[NHEADS * MLAND * DH];
__device__ __nv_bfloat16 g_KLL[NHEADS * MLAND * DH];
__device__ __nv_bfloat16 g_VH [NHEADS * NP * DH];
__device__ __nv_bfloat16 g_VL [NHEADS * NP * DH];
__device__ __nv_bfloat16 g_P3H[NHEADS * MLAND * NP];
__device__ __nv_bfloat16 g_P3L[NHEADS * MLAND * NP];
__device__ __nv_bfloat16 g_P1H[NHEADS * NP * MLAND];
__device__ __nv_bfloat16 g_P1L[NHEADS * NP * MLAND];
__device__ __nv_bfloat16 g_BmH[NHEADS * MLAND * DH];
__device__ __nv_bfloat16 g_BmL[NHEADS * MLAND * DH];

#define QKOFF (NHEADS * NP * DH)

// ---------------------------------------------------------------------------
// warp-mma helpers (sm_80+ PTX)
// ---------------------------------------------------------------------------
__device__ __forceinline__ uint32_t smem_u32(const void* p)
{
    uint32_t a;
    asm("{ .reg .u64 t; cvta.to.shared.u64 t, %1; cvt.u32.u64 %0, t; }" : "=r"(a) : "l"(p));
    return a;
}
__device__ __forceinline__ void ldsm_x4(uint32_t* r, uint32_t addr)
{
    asm volatile("ldmatrix.sync.aligned.m8n8.x4.shared.b16 {%0,%1,%2,%3}, [%4];"
                 : "=r"(r[0]), "=r"(r[1]), "=r"(r[2]), "=r"(r[3]) : "r"(addr));
}
__device__ __forceinline__ void ldsm_x2(uint32_t* r, uint32_t addr)
{
    asm volatile("ldmatrix.sync.aligned.m8n8.x2.shared.b16 {%0,%1}, [%2];"
                 : "=r"(r[0]), "=r"(r[1]) : "r"(addr));
}
__device__ __forceinline__ void ldsm_x2_trans(uint32_t* r, uint32_t addr)
{
    asm volatile("ldmatrix.sync.aligned.m8n8.x2.trans.shared.b16 {%0,%1}, [%2];"
                 : "=r"(r[0]), "=r"(r[1]) : "r"(addr));
}
__device__ __forceinline__ void mma_bf16(float* d, const uint32_t* a, const uint32_t* b)
{
    asm volatile("mma.sync.aligned.m16n8k16.row.col.f32.bf16.bf16.f32 "
                 "{%0,%1,%2,%3}, {%4,%5,%6,%7}, {%8,%9}, {%0,%1,%2,%3};"
                 : "+f"(d[0]), "+f"(d[1]), "+f"(d[2]), "+f"(d[3])
                 : "r"(a[0]), "r"(a[1]), "r"(a[2]), "r"(a[3]), "r"(b[0]), "r"(b[1]));
}

// ---------------------------------------------------------------------------
// Weight convert+transpose: W [K][N] f32 -> Whi/Wlo [N][K] bf16
// ---------------------------------------------------------------------------
__global__ void wconv_kernel(const float* __restrict__ W,
                             __nv_bfloat16* __restrict__ Whi, __nv_bfloat16* __restrict__ Wlo,
                             int K, int N)
{
    __shared__ float tl[32][33];
    int kb = blockIdx.y * 32, nb = blockIdx.x * 32;
    int t = threadIdx.x;
    for (int i = t; i < 1024; i += 256) {
        int r = i >> 5, c = i & 31;
        tl[r][c] = W[(size_t)(kb + r) * N + nb + c];
    }
    __syncthreads();
    for (int i = t; i < 1024; i += 256) {
        int n = i >> 5, k = i & 31;
        float v = tl[k][n];
        __nv_bfloat16 h = __float2bfloat16(v);
        float lo = v - __bfloat162float(h);
        size_t o = (size_t)(nb + n) * K + kb + k;
        Whi[o] = h;
        Wlo[o] = __float2bfloat16(lo);
    }
}

// ---------------------------------------------------------------------------
// Activation convert
// ---------------------------------------------------------------------------
__global__ void aconv_kernel(const float* __restrict__ A,
                             __nv_bfloat16* __restrict__ Ahi, __nv_bfloat16* __restrict__ Alo,
                             int Min, int Kn)
{
    int r = blockIdx.x;
    size_t base = (size_t)r * Kn;
    if (r >= Min) {
        __nv_bfloat162 z = __float2bfloat162_rn(0.f);
        for (int c = threadIdx.x * 2; c < Kn; c += 256) {
            *reinterpret_cast<__nv_bfloat162*>(Ahi + base + c) = z;
            *reinterpret_cast<__nv_bfloat162*>(Alo + base + c) = z;
        }
        return;
    }
    for (int c = threadIdx.x * 2; c < Kn; c += 256) {
        float2 v = *reinterpret_cast<const float2*>(A + base + c);
        __nv_bfloat16 h0 = __float2bfloat16(v.x);
        __nv_bfloat16 h1 = __float2bfloat16(v.y);
        float l0 = v.x - __bfloat162float(h0);
        float l1 = v.y - __bfloat162float(h1);
        __nv_bfloat162 hp; hp.x = h0; hp.y = h1;
        __nv_bfloat162 lp; lp.x = __float2bfloat16(l0); lp.y = __float2bfloat16(l1);
        *reinterpret_cast<__nv_bfloat162*>(Ahi + base + c) = hp;
        *reinterpret_cast<__nv_bfloat162*>(Alo + base + c) = lp;
    }
}

// ---------------------------------------------------------------------------
// Q/K/V split: QKV f32 -> Q,K per-head hi/lo (into BH/BL) + V per-head hi/lo
// ---------------------------------------------------------------------------
__global__ void qk_split_kernel(const float* __restrict__ QKV,
                                __nv_bfloat16* __restrict__ BH, __nv_bfloat16* __restrict__ BL,
                                __nv_bfloat16* __restrict__ VH, __nv_bfloat16* __restrict__ VL)
{
    int n = blockIdx.x;
    int t = threadIdx.x;
    for (int i = t; i < 1536; i += 256) {
        int part = i >> 9;            // 0=q, 1=k, 2=v
        int hd = i & 511;
        int h = hd >> 6, d = hd & 63;
        float v = QKV[(size_t)n * (3 * DMODEL) + part * DMODEL + hd];
        __nv_bfloat16 hi = __float2bfloat16(v);
        __nv_bfloat16 lo = __float2bfloat16(v - __bfloat162float(hi));
        size_t o = (size_t)h * NP * DH + (size_t)n * DH + d;
        if (part < 2) {
            BH[(size_t)part * QKOFF + o] = hi;
            BL[(size_t)part * QKOFF + o] = lo;
        } else {
            VH[o] = hi;
            VL[o] = lo;
        }
    }
}

// ---------------------------------------------------------------------------
// warp-MMA GEMM: C[M][N] = op(A @ B^T); 128x128 CTA tile
// ---------------------------------------------------------------------------
#define TCB_STR  72
#define TCG_SMEM (4 * 128 * TCB_STR * 2)  // 73728 bytes

__global__ void __launch_bounds__(256)
tc_gemm_kernel(const __nv_bfloat16* __restrict__ Ahi, const __nv_bfloat16* __restrict__ Alo,
               const __nv_bfloat16* __restrict__ Bhi, const __nv_bfloat16* __restrict__ Blo,
               float* __restrict__ C, const float* __restrict__ bias,
               int Mn, int Nn, int Kn, int flags, int scale_cols, float scale)
{
    extern __shared__ __nv_bfloat16 smb[];
    __nv_bfloat16* sAh = smb;
    __nv_bfloat16* sAl = smb + 128 * TCB_STR;
    __nv_bfloat16* sBh = smb + 2 * 128 * TCB_STR;
    __nv_bfloat16* sBl = smb + 3 * 128 * TCB_STR;

    const int t = threadIdx.x, lane = t & 31, wid = t >> 5;
    const int m0 = blockIdx.y * 128, n0 = blockIdx.x * 128;
    const int wm = (wid & 3) * 32;
    const int wn = (wid >> 2) * 64;

    const uint32_t sAh_u = smem_u32(sAh), sAl_u = smem_u32(sAl);
    const uint32_t sBh_u = smem_u32(sBh), sBl_u = smem_u32(sBl);

    const int a_row = (lane & 7) + ((lane >> 3) & 1) * 8;
    const int a_col = (lane >> 4) * 8;
    const int b_row = lane & 7;
    const int b_col = ((lane >> 3) & 1) * 8;

    float acc[2][8][4];
#pragma unroll
    for (int i = 0; i < 2; i++)
#pragma unroll
        for (int j = 0; j < 8; j++)
#pragma unroll
            for (int k = 0; k < 4; k++) acc[i][j][k] = 0.f;

    for (int k0 = 0; k0 < Kn; k0 += 64) {
        for (int i = t; i < 1024; i += 256) {
            int r = i >> 3, kg = (i & 7) << 3;
            int off = r * TCB_STR + kg;
            size_t ga = (size_t)(m0 + r) * Kn + k0 + kg;
            size_t gb = (size_t)(n0 + r) * Kn + k0 + kg;
            *reinterpret_cast<uint4*>(sAh + off) = *reinterpret_cast<const uint4*>(Ahi + ga);
            *reinterpret_cast<uint4*>(sAl + off) = *reinterpret_cast<const uint4*>(Alo + ga);
            *reinterpret_cast<uint4*>(sBh + off) = *reinterpret_cast<const uint4*>(Bhi + gb);
            *reinterpret_cast<uint4*>(sBl + off) = *reinterpret_cast<const uint4*>(Blo + gb);
        }
        __syncthreads();
#pragma unroll
        for (int ks = 0; ks < 4; ks++) {
            const int kl = ks * 16;
            uint32_t ah[2][4], al[2][4];
#pragma unroll
            for (int mt = 0; mt < 2; mt++) {
                uint32_t off = (uint32_t)((wm + mt * 16 + a_row) * TCB_STR + kl + a_col) * 2;
                ldsm_x4(ah[mt], sAh_u + off);
                ldsm_x4(al[mt], sAl_u + off);
            }
#pragma unroll
            for (int ng = 0; ng < 2; ng++) {
                uint32_t bh[4][2], bl[4][2];
#pragma unroll
                for (int nt = 0; nt < 4; nt++) {
                    uint32_t off = (uint32_t)((wn + ng * 32 + nt * 8 + b_row) * TCB_STR + kl + b_col) * 2;
                    ldsm_x2(bh[nt], sBh_u + off);
                    ldsm_x2(bl[nt], sBl_u + off);
                }
#pragma unroll
                for (int mt = 0; mt < 2; mt++)
#pragma unroll
                    for (int nt = 0; nt < 4; nt++) {
                        float* d = acc[mt][ng * 4 + nt];
                        mma_bf16(d, ah[mt], bh[nt]);
                        mma_bf16(d, ah[mt], bl[nt]);
                        mma_bf16(d, al[mt], bh[nt]);
                    }
            }
        }
        __syncthreads();
    }

    const bool relu = (flags & FLAG_RELU) != 0;
    const bool accu = (flags & FLAG_ACC) != 0;
#pragma unroll
    for (int mt = 0; mt < 2; mt++) {
        int rbase = m0 + wm + mt * 16 + (lane >> 2);
#pragma unroll
        for (int nt = 0; nt < 8; nt++) {
            int c0 = n0 + wn + nt * 8 + (lane & 3) * 2;
#pragma unroll
            for (int half = 0; half < 2; half++) {
                int row = rbase + half * 8;
                if (row >= Mn) continue;
                float v0 = acc[mt][nt][half * 2 + 0];
                float v1 = acc[mt][nt][half * 2 + 1];
                if (c0 < scale_cols)     v0 *= scale;
                if (c0 + 1 < scale_cols) v1 *= scale;
                if (bias) { v0 += bias[c0]; v1 += bias[c0 + 1]; }
                if (relu) { v0 = fmaxf(v0, 0.f); v1 = fmaxf(v1, 0.f); }
                size_t o = (size_t)row * Nn + c0;
                if (accu) { C[o] += v0; C[o + 1] += v1; }
                else      { C[o] = v0;  C[o + 1] = v1; }
            }
        }
    }
}

// ---------------------------------------------------------------------------
// Batched logits MMA (K=64, one chunk): C[b][m][n] = A[b] @ B[b]^T
// ---------------------------------------------------------------------------
__global__ void __launch_bounds__(256)
slogits_kernel(const __nv_bfloat16* __restrict__ Ahi, const __nv_bfloat16* __restrict__ Alo,
               const __nv_bfloat16* __restrict__ Bhi, const __nv_bfloat16* __restrict__ Blo,
               float* __restrict__ C,
               size_t strideA, size_t strideB, size_t strideC, int ldc)
{
    extern __shared__ __nv_bfloat16 smb[];
    __nv_bfloat16* sAh = smb;
    __nv_bfloat16* sAl = smb + 128 * TCB_STR;
    __nv_bfloat16* sBh = smb + 2 * 128 * TCB_STR;
    __nv_bfloat16* sBl = smb + 3 * 128 * TCB_STR;

    const int t = threadIdx.x, lane = t & 31, wid = t >> 5;
    const int m0 = blockIdx.y * 128, n0 = blockIdx.x * 128;
    const int b = blockIdx.z;
    const __nv_bfloat16* Ah = Ahi + (size_t)b * strideA;
    const __nv_bfloat16* Al = Alo + (size_t)b * strideA;
    const __nv_bfloat16* Bh = Bhi + (size_t)b * strideB;
    const __nv_bfloat16* Bl = Blo + (size_t)b * strideB;
    float* Cb = C + (size_t)b * strideC;

    const int wm = (wid & 3) * 32;
    const int wn = (wid >> 2) * 64;

    const uint32_t sAh_u = smem_u32(sAh), sAl_u = smem_u32(sAl);
    const uint32_t sBh_u = smem_u32(sBh), sBl_u = smem_u32(sBl);

    const int a_row = (lane & 7) + ((lane >> 3) & 1) * 8;
    const int a_col = (lane >> 4) * 8;
    const int b_row = lane & 7;
    const int b_col = ((lane >> 3) & 1) * 8;

    float acc[2][8][4];
#pragma unroll
    for (int i = 0; i < 2; i++)
#pragma unroll
        for (int j = 0; j < 8; j++)
#pragma unroll
            for (int k = 0; k < 4; k++) acc[i][j][k] = 0.f;

    for (int i = t; i < 1024; i += 256) {
        int r = i >> 3, kg = (i & 7) << 3;
        int off = r * TCB_STR + kg;
        size_t ga = (size_t)(m0 + r) * DH + kg;
        size_t gb = (size_t)(n0 + r) * DH + kg;
        *reinterpret_cast<uint4*>(sAh + off) = *reinterpret_cast<const uint4*>(Ah + ga);
        *reinterpret_cast<uint4*>(sAl + off) = *reinterpret_cast<const uint4*>(Al + ga);
        *reinterpret_cast<uint4*>(sBh + off) = *reinterpret_cast<const uint4*>(Bh + gb);
        *reinterpret_cast<uint4*>(sBl + off) = *reinterpret_cast<const uint4*>(Bl + gb);
    }
    __syncthreads();
#pragma unroll
    for (int ks = 0; ks < 4; ks++) {
        const int kl = ks * 16;
        uint32_t ah[2][4], al[2][4];
#pragma unroll
        for (int mt = 0; mt < 2; mt++) {
            uint32_t off = (uint32_t)((wm + mt * 16 + a_row) * TCB_STR + kl + a_col) * 2;
            ldsm_x4(ah[mt], sAh_u + off);
            ldsm_x4(al[mt], sAl_u + off);
        }
#pragma unroll
        for (int ng = 0; ng < 2; ng++) {
            uint32_t bh[4][2], bl[4][2];
#pragma unroll
            for (int nt = 0; nt < 4; nt++) {
                uint32_t off = (uint32_t)((wn + ng * 32 + nt * 8 + b_row) * TCB_STR + kl + b_col) * 2;
                ldsm_x2(bh[nt], sBh_u + off);
                ldsm_x2(bl[nt], sBl_u + off);
            }
#pragma unroll
            for (int mt = 0; mt < 2; mt++)
#pragma unroll
                for (int nt = 0; nt < 4; nt++) {
                    float* d = acc[mt][nt + ng * 4];
                    mma_bf16(d, ah[mt], bh[nt]);
                    mma_bf16(d, ah[mt], bl[nt]);
                    mma_bf16(d, al[mt], bh[nt]);
                }
        }
    }

#pragma unroll
    for (int mt = 0; mt < 2; mt++) {
        int rbase = m0 + wm + mt * 16 + (lane >> 2);
#pragma unroll
        for (int nt = 0; nt < 8; nt++) {
            int c0 = n0 + wn + nt * 8 + (lane & 3) * 2;
#pragma unroll
            for (int half = 0; half < 2; half++) {
                int row = rbase + half * 8;
                size_t o = (size_t)row * ldc + c0;
                Cb[o]     = acc[mt][nt][half * 2 + 0];
                Cb[o + 1] = acc[mt][nt][half * 2 + 1];
            }
        }
    }
}

// ---------------------------------------------------------------------------
// pgemm: C = P @ B; P hi/lo [M][K] row-major, B hi/lo [K][64] row-major
// (B via ldmatrix.trans). CTA 128x64; 8 warps (4m x 2n).
// mode 0: split-K partial -> PVP
// mode 1: full-K; fused depthwise conv on V; write bf16 hi/lo into OutH/OutL
//         at (row - PADF)*DMODEL + head*64 + col (skip rows < PADF)
// ---------------------------------------------------------------------------
#define PG_PH  0
#define PG_PL  (128 * TCB_STR)
#define PG_BH  (2 * 128 * TCB_STR)
#define PG_BL  (2 * 128 * TCB_STR + 64 * TCB_STR)
#define PG_SMEM ((2 * 128 * TCB_STR + 2 * 64 * TCB_STR) * 2)   // 55296 bytes

__global__ void __launch_bounds__(256)
pgemm_kernel(const __nv_bfloat16* __restrict__ Phi, const __nv_bfloat16* __restrict__ Plo,
             const __nv_bfloat16* __restrict__ Bhi, const __nv_bfloat16* __restrict__ Blo,
             float* __restrict__ Cout,
             __nv_bfloat16* __restrict__ OutH, __nv_bfloat16* __restrict__ OutL,
             const float* __restrict__ QKV, const float* __restrict__ Wc,
             int Pld, size_t pHeadStride, size_t bHeadStride,
             int chunksPerSliceBase, int mode)
{
    extern __shared__ __nv_bfloat16 smb[];
    __nv_bfloat16* sPh = smb + PG_PH;
    __nv_bfloat16* sPl = smb + PG_PL;
    __nv_bfloat16* sBh = smb + PG_BH;
    __nv_bfloat16* sBl = smb + PG_BL;

    const int t = threadIdx.x, lane = t & 31, wid = t >> 5;
    const int m0 = blockIdx.x * 128;
    const int kslice = blockIdx.y;
    const int head = blockIdx.z;

    int c0, nch;
    if (mode == 0) {
        if (kslice < 4) { c0 = kslice * (chunksPerSliceBase + 1); nch = chunksPerSliceBase + 1; }
        else { c0 = 4 * (chunksPerSliceBase + 1) + (kslice - 4) * chunksPerSliceBase; nch = chunksPerSliceBase; }
    } else {
        c0 = 0; nch = chunksPerSliceBase;
    }

    const __nv_bfloat16* Ph = Phi + (size_t)head * pHeadStride;
    const __nv_bfloat16* Pl = Plo + (size_t)head * pHeadStride;
    const __nv_bfloat16* Bh = Bhi + (size_t)head * bHeadStride;
    const __nv_bfloat16* Bl = Blo + (size_t)head * bHeadStride;

    const int wm = (wid & 3) * 32;
    const int wn = (wid >> 2) * 32;

    const uint32_t sPh_u = smem_u32(sPh), sPl_u = smem_u32(sPl);
    const uint32_t sBh_u = smem_u32(sBh), sBl_u = smem_u32(sBl);

    const int a_row = (lane & 7) + ((lane >> 3) & 1) * 8;
    const int a_col = (lane >> 4) * 8;
    const int bt_k = lane & 15;

    float acc[2][4][4];
#pragma unroll
    for (int i = 0; i < 2; i++)
#pragma unroll
        for (int j = 0; j < 4; j++)
#pragma unroll
            for (int k = 0; k < 4; k++) acc[i][j][k] = 0.f;

    for (int ci = 0; ci < nch; ci++) {
        int k0 = (c0 + ci) << 6;
        for (int i = t; i < 1024; i += 256) {
            int r = i >> 3, kg = (i & 7) << 3;
            int off = r * TCB_STR + kg;
            size_t gp = (size_t)(m0 + r) * Pld + k0 + kg;
            *reinterpret_cast<uint4*>(sPh + off) = *reinterpret_cast<const uint4*>(Ph + gp);
            *reinterpret_cast<uint4*>(sPl + off) = *reinterpret_cast<const uint4*>(Pl + gp);
        }
        for (int i = t; i < 512; i += 256) {
            int r = i >> 3, kg = (i & 7) << 3;
            int off = r * TCB_STR + kg;
            size_t gb = (size_t)(k0 + r) * 64 + kg;
            *reinterpret_cast<uint4*>(sBh + off) = *reinterpret_cast<const uint4*>(Bh + gb);
            *reinterpret_cast<uint4*>(sBl + off) = *reinterpret_cast<const uint4*>(Bl + gb);
        }
        __syncthreads();
#pragma unroll
        for (int ks = 0; ks < 4; ks++) {
            const int kl = ks * 16;
            uint32_t ph[2][4], pl[2][4];
#pragma unroll
            for (int mt = 0; mt < 2; mt++) {
                uint32_t off = (uint32_t)((wm + mt * 16 + a_row) * TCB_STR + kl + a_col) * 2;
                ldsm_x4(ph[mt], sPh_u + off);
                ldsm_x4(pl[mt], sPl_u + off);
            }
            uint32_t bh[4][2], bl[4][2];
#pragma unroll
            for (int nt = 0; nt < 4; nt++) {
                uint32_t off = (uint32_t)((kl + bt_k) * TCB_STR + wn + nt * 8) * 2;
                ldsm_x2_trans(bh[nt], sBh_u + off);
                ldsm_x2_trans(bl[nt], sBl_u + off);
            }
#pragma unroll
            for (int mt = 0; mt < 2; mt++)
#pragma unroll
                for (int nt = 0; nt < 4; nt++) {
                    float* d = acc[mt][nt];
                    mma_bf16(d, ph[mt], bh[nt]);
                    mma_bf16(d, ph[mt], bl[nt]);
                    mma_bf16(d, pl[mt], bh[nt]);
                }
        }
        __syncthreads();
    }

    if (mode == 0) {
#pragma unroll
        for (int mt = 0; mt < 2; mt++) {
            int rbase = m0 + wm + mt * 16 + (lane >> 2);
#pragma unroll
            for (int nt = 0; nt < 4; nt++) {
                int c0c = wn + nt * 8 + (lane & 3) * 2;
#pragma unroll
                for (int half = 0; half < 2; half++) {
                    int row = rbase + half * 8;
                    size_t o = (((size_t)kslice * NHEADS + head) * MLAND + row) * 64 + c0c;
                    Cout[o]     = acc[mt][nt][half * 2 + 0];
                    Cout[o + 1] = acc[mt][nt][half * 2 + 1];
                }
            }
        }
        return;
    }

    // mode 1: fused depthwise conv + bf16 hi/lo output
    float* Vc = reinterpret_cast<float*>(smb);       // 160 x 64 f32 (40 KB)
    float* ws = Vc + 160 * 64;                       // 33 weights
    if (t < 33) ws[t] = Wc[head * LWIN + t];
    for (int lin = t; lin < 160 * 64; lin += 256) {
        int r = lin >> 6, c = lin & 63;
        int n = m0 - 16 + r;
        Vc[lin] = (n >= 0 && n < NP)
                    ? QKV[(size_t)n * (3 * DMODEL) + 2 * DMODEL + head * DH + c] : 0.f;
    }
    __syncthreads();

#pragma unroll
    for (int mt = 0; mt < 2; mt++) {
        int rbase = m0 + wm + mt * 16 + (lane >> 2);
#pragma unroll
        for (int nt = 0; nt < 4; nt++) {
            int c0c = wn + nt * 8 + (lane & 3) * 2;
#pragma unroll
            for (int half = 0; half < 2; half++) {
                int row = rbase + half * 8;
                if (row < PADF) continue;
                int lr = row - m0;
                float cv0 = 0.f, cv1 = 0.f;
#pragma unroll
                for (int k = 0; k < LWIN; k++) {
                    float w = ws[k];
                    cv0 += w * Vc[(lr + k) * 64 + c0c];
                    cv1 += w * Vc[(lr + k) * 64 + c0c + 1];
                }
                float v0 = acc[mt][nt][half * 2 + 0] + cv0;
                float v1 = acc[mt][nt][half * 2 + 1] + cv1;
                size_t o = (size_t)(row - PADF) * DMODEL + head * DH + c0c;
                __nv_bfloat16 h0 = __float2bfloat16(v0);
                __nv_bfloat16 h1 = __float2bfloat16(v1);
                OutH[o]     = h0;
                OutH[o + 1] = h1;
                OutL[o]     = __float2bfloat16(v0 - __bfloat162float(h0));
                OutL[o + 1] = __float2bfloat16(v1 - __bfloat162float(h1));
            }
        }
    }
}

// ---------------------------------------------------------------------------
// split-K reduction: A3V = sum over 8 slices
// ---------------------------------------------------------------------------
__global__ void pvred_kernel(const float* __restrict__ PVP, float* __restrict__ A3V)
{
    int h = blockIdx.x & 7, seg = blockIdx.x >> 3;
    int idx = seg * 2048 + threadIdx.x * 8;
    for (int j = 0; j < 8; j++) {
        int li = idx + j;
        float s = 0.f;
#pragma unroll
        for (int sl = 0; sl < 8; sl++)
            s += PVP[(((size_t)sl * NHEADS + h) * MLAND * 64) + li];
        A3V[(size_t)h * MLAND * 64 + li] = s;
    }
}

// ---------------------------------------------------------------------------
// p3 softmax: S3 [h][m][NP] -> normalized P hi/lo (block per row)
// ---------------------------------------------------------------------------
__global__ void p3_kernel(const float* __restrict__ S,
                          __nv_bfloat16* __restrict__ PH, __nv_bfloat16* __restrict__ PL)
{
    int m = blockIdx.x, h = blockIdx.y;
    int t = threadIdx.x;
    const float* row = S + ((size_t)h * MLAND + m) * NP;
    float vals[33];
    float mx = -1e30f;
#pragma unroll
    for (int i = 0; i < 33; i++) {
        vals[i] = row[i * 256 + t];
        mx = fmaxf(mx, vals[i]);
    }
    __shared__ float red[256];
    red[t] = mx; __syncthreads();
    for (int o = 128; o > 0; o >>= 1) {
        if (t < o) red[t] = fmaxf(red[t], red[t + o]);
        __syncthreads();
    }
    mx = red[0]; __syncthreads();
    float sum = 0.f;
#pragma unroll
    for (int i = 0; i < 33; i++) {
        vals[i] = __expf(vals[i] - mx);
        sum += vals[i];
    }
    red[t] = sum; __syncthreads();
    for (int o = 128; o > 0; o >>= 1) {
        if (t < o) red[t] += red[t + o];
        __syncthreads();
    }
    float inv = 1.0f / red[0];
    __nv_bfloat16* ph = PH + ((size_t)h * MLAND + m) * NP;
    __nv_bfloat16* pl = PL + ((size_t)h * MLAND + m) * NP;
#pragma unroll
    for (int i = 0; i < 33; i++) {
        float p = vals[i] * inv;
        __nv_bfloat16 hi = __float2bfloat16(p);
        ph[i * 256 + t] = hi;
        pl[i * 256 + t] = __float2bfloat16(p - __bfloat162float(hi));
    }
}

// ---------------------------------------------------------------------------
// p1 softmax: S1 [h][n][256] -> normalized P hi/lo (warp per row)
// ---------------------------------------------------------------------------
__global__ void p1_kernel(const float* __restrict__ S,
                          __nv_bfloat16* __restrict__ PH, __nv_bfloat16* __restrict__ PL)
{
    int row = blockIdx.x * 8 + (threadIdx.x >> 5);
    int lane = threadIdx.x & 31;
    const float* r = S + (size_t)row * MLAND;
    float a[8];
#pragma unroll
    for (int k = 0; k < 8; k++) a[k] = r[lane + k * 32];
    float m = a[0];
#pragma unroll
    for (int k = 1; k < 8; k++) m = fmaxf(m, a[k]);
    for (int o = 16; o > 0; o >>= 1) m = fmaxf(m, __shfl_xor_sync(0xffffffffu, m, o));
    float s = 0.f;
#pragma unroll
    for (int k = 0; k < 8; k++) { a[k] = __expf(a[k] - m); s += a[k]; }
    for (int o = 16; o > 0; o >>= 1) s += __shfl_xor_sync(0xffffffffu, s, o);
    float inv = 1.0f / s;
    __nv_bfloat16* ph = PH + (size_t)row * MLAND;
    __nv_bfloat16* pl = PL + (size_t)row * MLAND;
#pragma unroll
    for (int k = 0; k < 8; k++) {
        float p = a[k] * inv;
        __nv_bfloat16 hi = __float2bfloat16(p);
        ph[lane + k * 32] = hi;
        pl[lane + k * 32] = __float2bfloat16(p - __bfloat162float(hi));
    }
}

// ---------------------------------------------------------------------------
// Assemble h rows: cls + wrap
// ---------------------------------------------------------------------------
__global__ void assemble_kernel(const float* __restrict__ cls, float* __restrict__ H)
{
    int j = blockIdx.x;
    int c = threadIdx.x;
    if (j == 0) H[c] = cls[c];
    else        H[(size_t)(NTOK + j) * DMODEL + c] = H[(size_t)j * DMODEL + c];
}

// ---------------------------------------------------------------------------
// LayerNorm into padded XP
// ---------------------------------------------------------------------------
__global__ void ln_pad_kernel(const float* __restrict__ Hin, float* __restrict__ XP,
                              const float* __restrict__ g, const float* __restrict__ b)
{
    int row = blockIdx.x;
    int tid = threadIdx.x;
    if (row < PADF) {
        XP[(size_t)row * DMODEL + tid] = 0.f;
        XP[(size_t)row * DMODEL + tid + 256] = 0.f;
        return;
    }
    const float* x = Hin + (size_t)(row - PADF) * DMODEL;
    float v0 = x[tid], v1 = x[tid + 256];
    __shared__ float s1[256], s2[256];
    s1[tid] = v0 + v1;
    s2[tid] = v0 * v0 + v1 * v1;
    __syncthreads();
    for (int o = 128; o > 0; o >>= 1) {
        if (tid < o) { s1[tid] += s1[tid + o]; s2[tid] += s2[tid + o]; }
        __syncthreads();
    }
    float mean = s1[0] * (1.f / DMODEL);
    float var  = s2[0] * (1.f / DMODEL) - mean * mean;
    float rs = rsqrtf(var + EPSLN);
    XP[(size_t)row * DMODEL + tid]       = (v0 - mean) * rs * g[tid] + b[tid];
    XP[(size_t)row * DMODEL + tid + 256] = (v1 - mean) * rs * g[tid + 256] + b[tid + 256];
}

// ---------------------------------------------------------------------------
// Landmarks: means of 33-groups; f32 QL/KL + bf16 hi/lo copies
// ---------------------------------------------------------------------------
__global__ void landmarks_kernel(const float* __restrict__ QKV,
                                 float* __restrict__ QL, float* __restrict__ KL,
                                 __nv_bfloat16* __restrict__ QLH, __nv_bfloat16* __restrict__ QLL,
                                 __nv_bfloat16* __restrict__ KLH, __nv_bfloat16* __restrict__ KLL)
{
    int hm = blockIdx.x;
    int h = hm >> 8, m = hm & 255;
    int tid = threadIdx.x;
    int d = tid & 63;
    int off = (tid < 64) ? 0 : DMODEL;
    size_t base = (size_t)(m * LWIN) * (3 * DMODEL) + off + h * DH + d;
    float s = 0.f;
#pragma unroll
    for (int j = 0; j < LWIN; j++) s += QKV[base + (size_t)j * (3 * DMODEL)];
    s *= (1.0f / LWIN);
    __nv_bfloat16 hi = __float2bfloat16(s);
    __nv_bfloat16 lo = __float2bfloat16(s - __bfloat162float(hi));
    size_t o = (size_t)(h * MLAND + m) * DH + d;
    if (tid < 64) {
        QL[o] = s; QLH[o] = hi; QLL[o] = lo;
    } else {
        KL[o] = s; KLH[o] = hi; KLL[o] = lo;
    }
}

// ---------------------------------------------------------------------------
// a2 = softmax(q_l @ k_l^T)
// ---------------------------------------------------------------------------
__global__ void a2_kernel(const float* __restrict__ QL, const float* __restrict__ KL,
                          float* __restrict__ A2)
{
    int m = blockIdx.x, h = blockIdx.y;
    int tid = threadIdx.x;
    __shared__ float q[64];
    __shared__ float red[256];
    if (tid < 64) q[tid] = QL[(size_t)(h * MLAND + m) * DH + tid];
    __syncthreads();
    const float* kr = KL + (size_t)(h * MLAND + tid) * DH;
    float s = 0.f;
#pragma unroll
    for (int i = 0; i < 16; i++) {
        float4 kv = reinterpret_cast<const float4*>(kr)[i];
        float4 qv = reinterpret_cast<const float4*>(q)[i];
        s += kv.x * qv.x + kv.y * qv.y + kv.z * qv.z + kv.w * qv.w;
    }
    red[tid] = s; __syncthreads();
    for (int o = 128; o > 0; o >>= 1) {
        if (tid < o) red[tid] = fmaxf(red[tid], red[tid + o]);
        __syncthreads();
    }
    float mx = red[0]; __syncthreads();
    float e = __expf(s - mx);
    red[tid] = e; __syncthreads();
    for (int o = 128; o > 0; o >>= 1) {
        if (tid < o) red[tid] += red[tid + o];
        __syncthreads();
    }
    float sm = red[0];
    A2[(size_t)(h * MLAND + m) * MLAND + tid] = e / sm;
}

// ---------------------------------------------------------------------------
// pinv chain
// ---------------------------------------------------------------------------
__global__ void pinv_scale_kernel(const float* __restrict__ A2, float* __restrict__ PS)
{
    int h = blockIdx.x;
    int t = threadIdx.x;
    int w = t >> 5, lane = t & 31;
    const float* Ah = A2 + (size_t)h * 65536;
    __shared__ float rs[256];
    __shared__ float cs2[256];
    for (int r = w; r < 256; r += 8) {
        float s = 0.f;
        for (int j = lane; j < 256; j += 32) s += fabsf(Ah[r * 256 + j]);
        for (int o = 16; o > 0; o >>= 1) s += __shfl_xor_sync(0xffffffffu, s, o);
        if (lane == 0) rs[r] = s;
    }
    float cs = 0.f;
    for (int i = 0; i < 256; i++) cs += fabsf(Ah[i * 256 + t]);
    cs2[t] = cs;
    __syncthreads();
    for (int o = 128; o > 0; o >>= 1) {
        if (t < o) { rs[t] = fmaxf(rs[t], rs[t + o]); cs2[t] = fmaxf(cs2[t], cs2[t + o]); }
        __syncthreads();
    }
    if (t == 0) PS[h] = 1.0f / (rs[0] * cs2[0]);
}

__global__ void pinv_tr_kernel(const float* __restrict__ A2, const float* __restrict__ PS,
                               float* __restrict__ Z0)
{
    __shared__ float tl[64][65];
    int h = blockIdx.y;
    int seg = blockIdx.x;
    int bi = (seg >> 2) * 64, bj = (seg & 3) * 64;
    int t = threadIdx.x;
    float inv = PS[h];
    const float* Ah = A2 + (size_t)h * 65536;
    float* Zh = Z0 + (size_t)h * 65536;
    for (int lin = t; lin < 4096; lin += 256) {
        int r = lin >> 6, c = lin & 63;
        tl[r][c] = Ah[(size_t)(bi + r) * 256 + bj + c];
    }
    __syncthreads();
    for (int lin = t; lin < 4096; lin += 256) {
        int r = lin >> 6, c = lin & 63;
        Zh[(size_t)(bj + r) * 256 + bi + c] = tl[c][r] * inv;
    }
}

__global__ void nk256_kernel(const float* __restrict__ A, const float* __restrict__ B,
                             float* __restrict__ C, float alpha, float gamma)
{
    const float* Ah = A + (size_t)blockIdx.z * 65536;
    const float* Bh = B + (size_t)blockIdx.z * 65536;
    float* Ch = C + (size_t)blockIdx.z * 65536;
    __shared__ float As[16][64];
    __shared__ float Bs[16][64];
    const int bm = blockIdx.y * 64;
    const int bn = blockIdx.x * 64;
    const int tid = threadIdx.x;
    const int tx = tid & 15, ty = tid >> 4;
    const int row0 = ty * 4, col0 = tx * 4;
    float acc[4][4];
#pragma unroll
    for (int i = 0; i < 4; i++)
#pragma unroll
        for (int j = 0; j < 4; j++) acc[i][j] = 0.f;

    for (int k0 = 0; k0 < 256; k0 += 16) {
        {
            int ar = tid >> 2;
            int ac = (tid & 3) << 2;
            float4 v = *reinterpret_cast<const float4*>(Ah + (size_t)(bm + ar) * 256 + k0 + ac);
            As[ac + 0][ar] = v.x; As[ac + 1][ar] = v.y;
            As[ac + 2][ar] = v.z; As[ac + 3][ar] = v.w;
        }
        {
            int br = tid >> 4;
            int bc = (tid & 15) << 2;
            float4 v = *reinterpret_cast<const float4*>(Bh + (size_t)(k0 + br) * 256 + bn + bc);
            *reinterpret_cast<float4*>(&Bs[br][bc]) = v;
        }
        __syncthreads();
#pragma unroll
        for (int k = 0; k < 16; k++) {
            float a[4], b[4];
            *reinterpret_cast<float4*>(a) = *reinterpret_cast<const float4*>(&As[k][row0]);
            *reinterpret_cast<float4*>(b) = *reinterpret_cast<const float4*>(&Bs[k][col0]);
#pragma unroll
            for (int i = 0; i < 4; i++)
#pragma unroll
                for (int j = 0; j < 4; j++) acc[i][j] += a[i] * b[j];
        }
        __syncthreads();
    }
#pragma unroll
    for (int i = 0; i < 4; i++)
#pragma unroll
        for (int j = 0; j < 4; j++) {
            size_t o = (size_t)(bm + row0 + i) * 256 + bn + col0 + j;
            Ch[o] = alpha * acc[i][j] + gamma * Ah[o];
        }
}

// ---------------------------------------------------------------------------
// Bm = pinv(a2) @ a3v  -> bf16 hi/lo
// ---------------------------------------------------------------------------
__global__ void bmat_kernel(const float* __restrict__ Z, const float* __restrict__ A3V,
                            __nv_bfloat16* __restrict__ BmH, __nv_bfloat16* __restrict__ BmL)
{
    int h = blockIdx.y;
    int m0 = blockIdx.x * 4;
    __shared__ float zs[4][256];
    int tid = threadIdx.x;
    int r = tid >> 6, d = tid & 63;
    for (int lin = tid; lin < 1024; lin += 256) {
        int rr = lin >> 8, k = lin & 255;
        zs[rr][k] = Z[(size_t)h * 65536 + (size_t)(m0 + rr) * 256 + k];
    }
    __syncthreads();
    float acc = 0.f;
    for (int k = 0; k < 256; k++)
        acc += zs[r][k] * A3V[(size_t)(h * MLAND + k) * DH + d];
    size_t o = (size_t)(h * MLAND + m0 + r) * DH + d;
    __nv_bfloat16 hi = __float2bfloat16(acc);
    BmH[o] = hi;
    BmL[o] = __float2bfloat16(acc - __bfloat162float(hi));
}

// ---------------------------------------------------------------------------
// PPEG tiled
// ---------------------------------------------------------------------------
#define PPEG_TILE (14 * 14 * 64)
#define PPEG_W7   PPEG_TILE
#define PPEG_W5   (PPEG_W7 + 64 * 49)
#define PPEG_W3   (PPEG_W5 + 64 * 25)
#define PPEG_TOT  (PPEG_W3 + 64 * 9)

__global__ void ppeg_tile_kernel(const float* __restrict__ Hin, float* __restrict__ Hout,
                                 const float* __restrict__ w7, const float* __restrict__ b7,
                                 const float* __restrict__ w5, const float* __restrict__ b5,
                                 const float* __restrict__ w3, const float* __restrict__ b3)
{
    extern __shared__ float sm[];
    float* tile = sm;
    float* ws7 = sm + PPEG_W7;
    float* ws5 = sm + PPEG_W5;
    float* ws3 = sm + PPEG_W3;

    int ti = blockIdx.x;
    int ty0 = (ti / 12) * 8, tx0 = (ti % 12) * 8;
    int cg = blockIdx.y * 64;
    int t = threadIdx.x;

    for (int lin = t; lin < PPEG_TILE; lin += 256) {
        int p = lin >> 6, c = lin & 63;
        int gy = ty0 + p / 14 - 3;
        int gx = tx0 + p % 14 - 3;
        float v = 0.f;
        if ((unsigned)gy < (unsigned)HSQ && (unsigned)gx < (unsigned)HSQ)
            v = Hin[(size_t)(1 + gy * HSQ + gx) * DMODEL + cg + c];
        tile[lin] = v;
    }
    for (int lin = t; lin < 64 * 49; lin += 256) ws7[lin] = w7[(size_t)cg * 49 + lin];
    for (int lin = t; lin < 64 * 25; lin += 256) ws5[lin] = w5[(size_t)cg * 25 + lin];
    for (int lin = t; lin < 64 * 9;  lin += 256) ws3[lin] = w3[(size_t)cg * 9 + lin];
    __syncthreads();

    int c = t & 63, pg = t >> 6;
    float bsum = b7[cg + c] + b5[cg + c] + b3[cg + c];
    for (int q = 0; q < 16; q++) {
        int p = pg * 16 + q;
        int oy = p >> 3, ox = p & 7;
        int gy = ty0 + oy, gx = tx0 + ox;
        if (gy >= HSQ || gx >= HSQ) continue;
        float acc = tile[((oy + 3) * 14 + ox + 3) * 64 + c] + bsum;
#pragma unroll
        for (int a = 0; a < 7; a++)
#pragma unroll
            for (int bq = 0; bq < 7; bq++)
                acc += ws7[c * 49 + a * 7 + bq] * tile[((oy + a) * 14 + ox + bq) * 64 + c];
#pragma unroll
        for (int a = 0; a < 5; a++)
#pragma unroll
            for (int bq = 0; bq < 5; bq++)
                acc += ws5[c * 25 + a * 5 + bq] * tile[((oy + a + 1) * 14 + ox + bq + 1) * 64 + c];
#pragma unroll
        for (int a = 0; a < 3; a++)
#pragma unroll
            for (int bq = 0; bq < 3; bq++)
                acc += ws3[c * 9 + a * 3 + bq] * tile[((oy + a + 2) * 14 + ox + bq + 2) * 64 + c];
        Hout[(size_t)(1 + gy * HSQ + gx) * DMODEL + cg + c] = acc;
    }
}

__global__ void copy_row0_kernel(const float* __restrict__ Hin, float* __restrict__ Hout)
{
    Hout[threadIdx.x] = Hin[threadIdx.x];
}

// ---------------------------------------------------------------------------
// Final head
// ---------------------------------------------------------------------------
__global__ void final_kernel(const float* __restrict__ H, const float* __restrict__ g,
                             const float* __restrict__ b, const float* __restrict__ w,
                             const float* __restrict__ bias2, float* __restrict__ out,
                             int out_size)
{
    int c = threadIdx.x;
    __shared__ float s1[512], s2[512];
    float x = H[c];
    s1[c] = x; s2[c] = x * x;
    __syncthreads();
    for (int o = 256; o > 0; o >>= 1) {
        if (c < o) { s1[c] += s1[c + o]; s2[c] += s2[c + o]; }
        __syncthreads();
    }
    float mean = s1[0] * (1.f / DMODEL);
    float var  = s2[0] * (1.f / DMODEL) - mean * mean;
    float e = (x - mean) * rsqrtf(var + EPSLN) * g[c] + b[c];
    __syncthreads();
    s1[c] = e * w[c * 2 + 0];
    s2[c] = e * w[c * 2 + 1];
    __syncthreads();
    for (int o = 256; o > 0; o >>= 1) {
        if (c < o) { s1[c] += s1[c + o]; s2[c] += s2[c + o]; }
        __syncthreads();
    }
    float l0 = s1[0] + bias2[0];
    float l1 = s2[0] + bias2[1];
    if (c == 0) {
        float m = fmaxf(l0, l1);
        float e0 = expf(l0 - m), e1 = expf(l1 - m);
        float ss = e0 + e1;
        if (out_size > 0) out[0] = l0;
        if (out_size > 1) out[1] = l1;
        if (out_size > 2) out[2] = e0 / ss;
        if (out_size > 3) out[3] = e1 / ss;
        if (out_size > 4) out[4] = (l1 > l0) ? 1.0f : 0.0f;
    }
    if (5 + c < out_size) out[5 + c] = e;
}

// ---------------------------------------------------------------------------
// Host orchestration
// ---------------------------------------------------------------------------
static float* symaddr(const void* sym)
{
    void* p = nullptr;
    cudaGetSymbolAddress(&p, sym);
    return (float*)p;
}
static __nv_bfloat16* symaddr_bf(const void* sym)
{
    void* p = nullptr;
    cudaGetSymbolAddress(&p, sym);
    return (__nv_bfloat16*)p;
}

static cudaStream_t g_side  = nullptr;
static cudaStream_t g_side2 = nullptr;
static cudaEvent_t  g_evf   = nullptr;
static cudaEvent_t  g_evj   = nullptr;
static cudaEvent_t  g_evf2  = nullptr;
static cudaEvent_t  g_evj2  = nullptr;

extern "C" void kernel_launch(void* const* d_in, const int* in_sizes, int n_in,
                              void* d_out, int out_size)
{
    if (!g_side) {
        cudaStreamCreateWithFlags(&g_side,  cudaStreamNonBlocking);
        cudaStreamCreateWithFlags(&g_side2, cudaStreamNonBlocking);
        cudaEventCreateWithFlags(&g_evf,  cudaEventDisableTiming);
        cudaEventCreateWithFlags(&g_evj,  cudaEventDisableTiming);
        cudaEventCreateWithFlags(&g_evf2, cudaEventDisableTiming);
        cudaEventCreateWithFlags(&g_evj2, cudaEventDisableTiming);
    }

    const float* x       = (const float*)d_in[0];
    const float* fc1_w   = (const float*)d_in[1];
    const float* fc1_b   = (const float*)d_in[2];
    const float* cls     = (const float*)d_in[3];
    const float* ln1_g   = (const float*)d_in[4];
    const float* ln1_b   = (const float*)d_in[5];
    const float* qkv1_w  = (const float*)d_in[6];
    const float* out1_w  = (const float*)d_in[7];
    const float* out1_b  = (const float*)d_in[8];
    const float* conv1_w = (const float*)d_in[9];
    const float* ln2_g   = (const float*)d_in[10];
    const float* ln2_b   = (const float*)d_in[11];
    const float* qkv2_w  = (const float*)d_in[12];
    const float* out2_w  = (const float*)d_in[13];
    const float* out2_b  = (const float*)d_in[14];
    const float* conv2_w = (const float*)d_in[15];
    const float* pg7_w   = (const float*)d_in[16];
    const float* pg7_b   = (const float*)d_in[17];
    const float* pg5_w   = (const float*)d_in[18];
    const float* pg5_b   = (const float*)d_in[19];
    const float* pg3_w   = (const float*)d_in[20];
    const float* pg3_b   = (const float*)d_in[21];
    const float* norm_g  = (const float*)d_in[22];
    const float* norm_b  = (const float*)d_in[23];
    const float* fc2_w   = (const float*)d_in[24];
    const float* fc2_b   = (const float*)d_in[25];

    float* H   = symaddr(g_H);
    float* H2  = symaddr(g_H2);
    float* XP  = symaddr(g_XP);
    float* QKV = symaddr(g_QKV);
    float* QL  = symaddr(g_QL);
    float* KL  = symaddr(g_KL);
    float* A2  = symaddr(g_A2);
    float* Z0  = symaddr(g_Z0);
    float* Z1  = symaddr(g_Z1);
    float* W1  = symaddr(g_W1);
    float* W2  = symaddr(g_W2);
    float* W3  = symaddr(g_W3);
    float* PS  = symaddr(g_PS);
    float* A3V = symaddr(g_A3V);
    float* S   = symaddr(g_S);
    float* S2  = symaddr(g_S2);
    float* PVP = symaddr(g_PVP);
    __nv_bfloat16* AH  = symaddr_bf(g_AH);
    __nv_bfloat16* AL  = symaddr_bf(g_AL);
    __nv_bfloat16* WH  = symaddr_bf(g_WH);
    __nv_bfloat16* WL  = symaddr_bf(g_WL);
    __nv_bfloat16* QLH = symaddr_bf(g_QLH);
    __nv_bfloat16* QLL = symaddr_bf(g_QLL);
    __nv_bfloat16* KLH = symaddr_bf(g_KLH);
    __nv_bfloat16* KLL = symaddr_bf(g_KLL);
    __nv_bfloat16* VH  = symaddr_bf(g_VH);
    __nv_bfloat16* VL  = symaddr_bf(g_VL);
    __nv_bfloat16* P3H = symaddr_bf(g_P3H);
    __nv_bfloat16* P3L = symaddr_bf(g_P3L);
    __nv_bfloat16* P1H = symaddr_bf(g_P1H);
    __nv_bfloat16* P1L = symaddr_bf(g_P1L);
    __nv_bfloat16* BmH = symaddr_bf(g_BmH);
    __nv_bfloat16* BmL = symaddr_bf(g_BmL);

    const int PPEG_SMEM = PPEG_TOT * 4;
    cudaFuncSetAttribute(ppeg_tile_kernel, cudaFuncAttributeMaxDynamicSharedMemorySize, PPEG_SMEM);
    cudaFuncSetAttribute(tc_gemm_kernel,  cudaFuncAttributeMaxDynamicSharedMemorySize, TCG_SMEM);
    cudaFuncSetAttribute(slogits_kernel,  cudaFuncAttributeMaxDynamicSharedMemorySize, TCG_SMEM);
    cudaFuncSetAttribute(pgemm_kernel,    cudaFuncAttributeMaxDynamicSharedMemorySize, PG_SMEM);

    // ---- fc1 + relu via tensor cores ----
    wconv_kernel<<<dim3(DMODEL / 32, INDIM / 32), 256>>>(fc1_w, WH, WL, INDIM, DMODEL);
    aconv_kernel<<<NTOK, 128>>>(x, AH, AL, NTOK, INDIM);
    tc_gemm_kernel<<<dim3(DMODEL / 128, NTOK / 128), 256, TCG_SMEM>>>(
        AH, AL, WH, WL, H + DMODEL, fc1_b, NTOK, DMODEL, INDIM, FLAG_RELU, 0, 1.f);
    assemble_kernel<<<NWRAP + 1, DMODEL>>>(cls, H);

    auto attn = [&](float* Hbuf, const float* lng, const float* lnb, const float* qkvw,
                    const float* outw, const float* outb, const float* convw) {
        ln_pad_kernel<<<NP, 256>>>(Hbuf, XP, lng, lnb);
        wconv_kernel<<<dim3(3 * DMODEL / 32, DMODEL / 32), 256>>>(qkvw, WH, WL, DMODEL, 3 * DMODEL);
        aconv_kernel<<<NP, 128>>>(XP, AH, AL, NP, DMODEL);
        tc_gemm_kernel<<<dim3(3 * DMODEL / 128, NP / 128), 256, TCG_SMEM>>>(
            AH, AL, WH, WL, QKV, nullptr, NP, 3 * DMODEL, DMODEL, 0, DMODEL, 0.125f);
        qk_split_kernel<<<NP, 256>>>(QKV, AH, AL, VH, VL);
        landmarks_kernel<<<NHEADS * MLAND, 128>>>(QKV, QL, KL, QLH, QLL, KLH, KLL);

        // fork side2: S1 = Q @ KL^T -> softmax (independent of everything below)
        cudaEventRecord(g_evf2, 0);
        cudaStreamWaitEvent(g_side2, g_evf2, 0);
        slogits_kernel<<<dim3(MLAND / 128, NP / 128, NHEADS), 256, TCG_SMEM, g_side2>>>(
            AH, AL, KLH, KLL, S2,
            (size_t)NP * DH, (size_t)MLAND * DH, (size_t)NP * MLAND, MLAND);
        p1_kernel<<<NP * NHEADS / 8, 256, 0, g_side2>>>(S2, P1H, P1L);
        cudaEventRecord(g_evj2, g_side2);

        a2_kernel<<<dim3(MLAND, NHEADS), 256>>>(QL, KL, A2);

        // fork side1: pinv chain
        cudaEventRecord(g_evf, 0);
        cudaStreamWaitEvent(g_side, g_evf, 0);
        pinv_scale_kernel<<<NHEADS, 256, 0, g_side>>>(A2, PS);
        pinv_tr_kernel<<<dim3(16, NHEADS), 256, 0, g_side>>>(A2, PS, Z0);
        float* zi = Z0;
        float* zo = Z1;
        for (int it = 0; it < 6; it++) {
            nk256_kernel<<<dim3(4, 4, NHEADS), 256, 0, g_side>>>(A2, zi, W1, 1.f, 0.f);
            nk256_kernel<<<dim3(4, 4, NHEADS), 256, 0, g_side>>>(W1, W1, W2, -1.f, 7.f);
            nk256_kernel<<<dim3(4, 4, NHEADS), 256, 0, g_side>>>(W1, W2, W3, -1.f, 15.f);
            nk256_kernel<<<dim3(4, 4, NHEADS), 256, 0, g_side>>>(zi, W3, zo, -0.25f, 3.25f);
            float* t = zi; zi = zo; zo = t;
        }
        cudaEventRecord(g_evj, g_side);

        // main: S3 = QL @ K^T -> softmax -> A3V = P3 @ V (split-K MMA)
        slogits_kernel<<<dim3(NP / 128, MLAND / 128, NHEADS), 256, TCG_SMEM>>>(
            QLH, QLL, AH + QKOFF, AL + QKOFF, S,
            (size_t)MLAND * DH, (size_t)NP * DH, (size_t)MLAND * NP, NP);
        p3_kernel<<<dim3(MLAND, NHEADS), 256>>>(S, P3H, P3L);
        pgemm_kernel<<<dim3(MLAND / 128, 8, NHEADS), 256, PG_SMEM>>>(
            P3H, P3L, VH, VL, PVP, nullptr, nullptr, nullptr, nullptr,
            NP, (size_t)MLAND * NP, (size_t)NP * DH, 16, 0);
        pvred_kernel<<<64, 256>>>(PVP, A3V);

        // join pinv + S1; Bm; out tile = P1 @ Bm + conv -> AH/AL hi-lo
        cudaStreamWaitEvent(0, g_evj, 0);
        bmat_kernel<<<dim3(MLAND / 4, NHEADS), 256>>>(zi, A3V, BmH, BmL);
        cudaStreamWaitEvent(0, g_evj2, 0);
        pgemm_kernel<<<dim3(NP / 128, 1, NHEADS), 256, PG_SMEM>>>(
            P1H, P1L, BmH, BmL, nullptr, AH, AL, QKV, convw,
            MLAND, (size_t)NP * MLAND, (size_t)MLAND * DH, 4, 1);

        // out projection (accumulate into Hbuf) straight from AH/AL
        wconv_kernel<<<dim3(DMODEL / 32, DMODEL / 32), 256>>>(outw, WH, WL, DMODEL, DMODEL);
        tc_gemm_kernel<<<dim3(DMODEL / 128, 65), 256, TCG_SMEM>>>(
            AH, AL, WH, WL, Hbuf, outb, NHTOK, DMODEL, DMODEL, FLAG_ACC, 0, 1.f);
    };

    attn(H, ln1_g, ln1_b, qkv1_w, out1_w, out1_b, conv1_w);

    ppeg_tile_kernel<<<dim3(144, NHEADS), 256, PPEG_SMEM>>>(
        H, H2, pg7_w, pg7_b, pg5_w, pg5_b, pg3_w, pg3_b);
    copy_row0_kernel<<<1, DMODEL>>>(H, H2);

    attn(H2, ln2_g, ln2_b, qkv2_w, out2_w, out2_b, conv2_w);

    final_kernel<<<1, DMODEL>>>(H2, norm_g, norm_b, fc2_w, fc2_b, (float*)d_out, out_size);
}

// round 12
// speedup vs baseline: 1.1123x; 1.1123x over previous
#include <cuda_runtime.h>
#include <cuda_bf16.h>
#include <math.h>
#include <stdint.h>

// ---------------------------------------------------------------------------
// Problem constants
// ---------------------------------------------------------------------------
#define NTOK   8192
#define INDIM  1024
#define DMODEL 512
#define NHEADS 8
#define DH     64
#define MLAND  256
#define LWIN   33
#define NP     8448          // padded attention length
#define NHTOK  8282          // tokens incl cls
#define PADF   166
#define HSQ    91
#define NFEAT  8281
#define NWRAP  89
#define EPSLN  1e-5f

#define FLAG_RELU 1
#define FLAG_ACC  2

// ---------------------------------------------------------------------------
// Scratch (device globals)
// ---------------------------------------------------------------------------
__device__ float g_H  [NHTOK * DMODEL];
__device__ float g_H2 [NHTOK * DMODEL];
__device__ float g_XP [NP * DMODEL];
__device__ float g_QKV[NP * 3 * DMODEL];
__device__ float g_QL [NHEADS * MLAND * DH];
__device__ float g_KL [NHEADS * MLAND * DH];
__device__ float g_A2 [NHEADS * MLAND * MLAND];
__device__ float g_Z0 [NHEADS * MLAND * MLAND];
__device__ float g_Z1 [NHEADS * MLAND * MLAND];
__device__ float g_W1 [NHEADS * MLAND * MLAND];
__device__ float g_W2 [NHEADS * MLAND * MLAND];
__device__ float g_W3 [NHEADS * MLAND * MLAND];
__device__ float g_PS [NHEADS];
__device__ float g_A3V[NHEADS * MLAND * DH];
__device__ float g_O  [NP * DMODEL];
__device__ float g_S  [NHEADS * NP * MLAND];     // logits scratch (S3 then S1)
__device__ float g_PVP[8 * NHEADS * MLAND * DH]; // split-K partials
// bf16 hi/lo staging
__device__ __nv_bfloat16 g_AH[NP * INDIM];       // reused: Qh [8][NP][64] + Kh [8][NP][64]
__device__ __nv_bfloat16 g_AL[NP * INDIM];
__device__ __nv_bfloat16 g_WH[3 * DMODEL * DMODEL];
__device__ __nv_bfloat16 g_WL[3 * DMODEL * DMODEL];
__device__ __nv_bfloat16 g_QLH[NHEADS * MLAND * DH];
__device__ __nv_bfloat16 g_QLL[NHEADS * MLAND * DH];
__device__ __nv_bfloat16 g_KLH[NHEADS * MLAND * DH];
__device__ __nv_bfloat16 g_KLL[NHEADS * MLAND * DH];
__device__ __nv_bfloat16 g_VH [NHEADS * NP * DH];
__device__ __nv_bfloat16 g_VL [NHEADS * NP * DH];
__device__ __nv_bfloat16 g_PH [NHEADS * NP * MLAND];
__device__ __nv_bfloat16 g_PL [NHEADS * NP * MLAND];
__device__ __nv_bfloat16 g_BmH[NHEADS * MLAND * DH];
__device__ __nv_bfloat16 g_BmL[NHEADS * MLAND * DH];

#define QKOFF (NHEADS * NP * DH)

// ---------------------------------------------------------------------------
// warp-mma helpers (sm_80+ PTX)
// ---------------------------------------------------------------------------
__device__ __forceinline__ uint32_t smem_u32(const void* p)
{
    uint32_t a;
    asm("{ .reg .u64 t; cvta.to.shared.u64 t, %1; cvt.u32.u64 %0, t; }" : "=r"(a) : "l"(p));
    return a;
}
__device__ __forceinline__ void ldsm_x4(uint32_t* r, uint32_t addr)
{
    asm volatile("ldmatrix.sync.aligned.m8n8.x4.shared.b16 {%0,%1,%2,%3}, [%4];"
                 : "=r"(r[0]), "=r"(r[1]), "=r"(r[2]), "=r"(r[3]) : "r"(addr));
}
__device__ __forceinline__ void ldsm_x2(uint32_t* r, uint32_t addr)
{
    asm volatile("ldmatrix.sync.aligned.m8n8.x2.shared.b16 {%0,%1}, [%2];"
                 : "=r"(r[0]), "=r"(r[1]) : "r"(addr));
}
__device__ __forceinline__ void ldsm_x2_trans(uint32_t* r, uint32_t addr)
{
    asm volatile("ldmatrix.sync.aligned.m8n8.x2.trans.shared.b16 {%0,%1}, [%2];"
                 : "=r"(r[0]), "=r"(r[1]) : "r"(addr));
}
__device__ __forceinline__ void mma_bf16(float* d, const uint32_t* a, const uint32_t* b)
{
    asm volatile("mma.sync.aligned.m16n8k16.row.col.f32.bf16.bf16.f32 "
                 "{%0,%1,%2,%3}, {%4,%5,%6,%7}, {%8,%9}, {%0,%1,%2,%3};"
                 : "+f"(d[0]), "+f"(d[1]), "+f"(d[2]), "+f"(d[3])
                 : "r"(a[0]), "r"(a[1]), "r"(a[2]), "r"(a[3]), "r"(b[0]), "r"(b[1]));
}
__device__ __forceinline__ void cp_async16(uint32_t smem_addr, const void* gptr)
{
    asm volatile("cp.async.ca.shared.global [%0], [%1], 16;"
                 :: "r"(smem_addr), "l"(gptr));
}
__device__ __forceinline__ void cp_commit()
{
    asm volatile("cp.async.commit_group;" ::: "memory");
}
__device__ __forceinline__ void cp_wait1()
{
    asm volatile("cp.async.wait_group 1;" ::: "memory");
}

// ---------------------------------------------------------------------------
// Weight convert+transpose: W [K][N] f32 -> Whi/Wlo [N][K] bf16
// ---------------------------------------------------------------------------
__global__ void wconv_kernel(const float* __restrict__ W,
                             __nv_bfloat16* __restrict__ Whi, __nv_bfloat16* __restrict__ Wlo,
                             int K, int N)
{
    __shared__ float tl[32][33];
    int kb = blockIdx.y * 32, nb = blockIdx.x * 32;
    int t = threadIdx.x;
    for (int i = t; i < 1024; i += 256) {
        int r = i >> 5, c = i & 31;
        tl[r][c] = W[(size_t)(kb + r) * N + nb + c];
    }
    __syncthreads();
    for (int i = t; i < 1024; i += 256) {
        int n = i >> 5, k = i & 31;
        float v = tl[k][n];
        __nv_bfloat16 h = __float2bfloat16(v);
        float lo = v - __bfloat162float(h);
        size_t o = (size_t)(nb + n) * K + kb + k;
        Whi[o] = h;
        Wlo[o] = __float2bfloat16(lo);
    }
}

// ---------------------------------------------------------------------------
// Activation convert
// ---------------------------------------------------------------------------
__global__ void aconv_kernel(const float* __restrict__ A,
                             __nv_bfloat16* __restrict__ Ahi, __nv_bfloat16* __restrict__ Alo,
                             int Min, int Kn)
{
    int r = blockIdx.x;
    size_t base = (size_t)r * Kn;
    if (r >= Min) {
        __nv_bfloat162 z = __float2bfloat162_rn(0.f);
        for (int c = threadIdx.x * 2; c < Kn; c += 256) {
            *reinterpret_cast<__nv_bfloat162*>(Ahi + base + c) = z;
            *reinterpret_cast<__nv_bfloat162*>(Alo + base + c) = z;
        }
        return;
    }
    for (int c = threadIdx.x * 2; c < Kn; c += 256) {
        float2 v = *reinterpret_cast<const float2*>(A + base + c);
        __nv_bfloat16 h0 = __float2bfloat16(v.x);
        __nv_bfloat16 h1 = __float2bfloat16(v.y);
        float l0 = v.x - __bfloat162float(h0);
        float l1 = v.y - __bfloat162float(h1);
        __nv_bfloat162 hp; hp.x = h0; hp.y = h1;
        __nv_bfloat162 lp; lp.x = __float2bfloat16(l0); lp.y = __float2bfloat16(l1);
        *reinterpret_cast<__nv_bfloat162*>(Ahi + base + c) = hp;
        *reinterpret_cast<__nv_bfloat162*>(Alo + base + c) = lp;
    }
}

// ---------------------------------------------------------------------------
// Q/K/V split
// ---------------------------------------------------------------------------
__global__ void qk_split_kernel(const float* __restrict__ QKV,
                                __nv_bfloat16* __restrict__ BH, __nv_bfloat16* __restrict__ BL,
                                __nv_bfloat16* __restrict__ VH, __nv_bfloat16* __restrict__ VL)
{
    int n = blockIdx.x;
    int t = threadIdx.x;
    for (int i = t; i < 1536; i += 256) {
        int part = i >> 9;
        int hd = i & 511;
        int h = hd >> 6, d = hd & 63;
        float v = QKV[(size_t)n * (3 * DMODEL) + part * DMODEL + hd];
        __nv_bfloat16 hi = __float2bfloat16(v);
        __nv_bfloat16 lo = __float2bfloat16(v - __bfloat162float(hi));
        size_t o = (size_t)h * NP * DH + (size_t)n * DH + d;
        if (part < 2) {
            BH[(size_t)part * QKOFF + o] = hi;
            BL[(size_t)part * QKOFF + o] = lo;
        } else {
            VH[o] = hi;
            VL[o] = lo;
        }
    }
}

// ---------------------------------------------------------------------------
// warp-MMA GEMM with cp.async double-buffered K-chunks of 32.
// C[M][N] = op(A @ B^T); 128x128 CTA tile, 8 warps (4x2).
// Loader: 2048 16B transfers/chunk = 8/thread = 4 arrays x 2 slots;
// slot s in {t, t+256}: r = s>>2 in [0,128), kg = (s&3)<<3 in {0,8,16,24}.
// ---------------------------------------------------------------------------
#define TCP_STR  40                         // bf16 row stride (80 B, 16B-aligned)
#define TCP_BUF  (4 * 128 * TCP_STR)        // elements per buffer (20480)
#define TCG_SMEM (2 * TCP_BUF * 2)          // 81920 bytes

__global__ void __launch_bounds__(256)
tc_gemm_kernel(const __nv_bfloat16* __restrict__ Ahi, const __nv_bfloat16* __restrict__ Alo,
               const __nv_bfloat16* __restrict__ Bhi, const __nv_bfloat16* __restrict__ Blo,
               float* __restrict__ C, const float* __restrict__ bias,
               int Mn, int Nn, int Kn, int flags, int scale_cols, float scale)
{
    extern __shared__ __nv_bfloat16 smb[];
    const int t = threadIdx.x, lane = t & 31, wid = t >> 5;
    const int m0 = blockIdx.y * 128, n0 = blockIdx.x * 128;
    const int wm = (wid & 3) * 32;
    const int wn = (wid >> 2) * 64;

    const uint32_t smem_base = smem_u32(smb);

    const int a_row = (lane & 7) + ((lane >> 3) & 1) * 8;
    const int a_col = (lane >> 4) * 8;
    const int b_row = lane & 7;
    const int b_col = ((lane >> 3) & 1) * 8;

    const int nchunks = Kn >> 5;            // K-chunks of 32

    // slot decomposition (see header comment)
    const int r1 = t >> 2,        kg1 = (t & 3) << 3;
    const int r2 = (t >> 2) + 64, kg2 = kg1;

    auto issue = [&](int ci, int buf) {
        int k0 = ci << 5;
        uint32_t bb = smem_base + (uint32_t)buf * TCP_BUF * 2;
        const __nv_bfloat16* gsrc[4] = {
            Ahi + (size_t)m0 * Kn, Alo + (size_t)m0 * Kn,
            Bhi + (size_t)n0 * Kn, Blo + (size_t)n0 * Kn };
#pragma unroll
        for (int arr = 0; arr < 4; arr++) {
            uint32_t sb = bb + (uint32_t)arr * 128 * TCP_STR * 2;
            cp_async16(sb + (uint32_t)(r1 * TCP_STR + kg1) * 2,
                       gsrc[arr] + (size_t)r1 * Kn + k0 + kg1);
            cp_async16(sb + (uint32_t)(r2 * TCP_STR + kg2) * 2,
                       gsrc[arr] + (size_t)r2 * Kn + k0 + kg2);
        }
    };

    float acc[2][8][4];
#pragma unroll
    for (int i = 0; i < 2; i++)
#pragma unroll
        for (int j = 0; j < 8; j++)
#pragma unroll
            for (int k = 0; k < 4; k++) acc[i][j][k] = 0.f;

    // prologue: chunks 0 and 1
    issue(0, 0); cp_commit();
    if (nchunks > 1) issue(1, 1);
    cp_commit();

    for (int ci = 0; ci < nchunks; ci++) {
        cp_wait1();
        __syncthreads();
        const int buf = ci & 1;
        uint32_t bb = smem_base + (uint32_t)buf * TCP_BUF * 2;
        uint32_t sAh_u = bb;
        uint32_t sAl_u = bb + 128 * TCP_STR * 2;
        uint32_t sBh_u = bb + 2 * 128 * TCP_STR * 2;
        uint32_t sBl_u = bb + 3 * 128 * TCP_STR * 2;
#pragma unroll
        for (int ks = 0; ks < 2; ks++) {
            const int kl = ks * 16;
            uint32_t ah[2][4], al[2][4];
#pragma unroll
            for (int mt = 0; mt < 2; mt++) {
                uint32_t off = (uint32_t)((wm + mt * 16 + a_row) * TCP_STR + kl + a_col) * 2;
                ldsm_x4(ah[mt], sAh_u + off);
                ldsm_x4(al[mt], sAl_u + off);
            }
#pragma unroll
            for (int ng = 0; ng < 2; ng++) {
                uint32_t bh[4][2], bl[4][2];
#pragma unroll
                for (int nt = 0; nt < 4; nt++) {
                    uint32_t off = (uint32_t)((wn + ng * 32 + nt * 8 + b_row) * TCP_STR + kl + b_col) * 2;
                    ldsm_x2(bh[nt], sBh_u + off);
                    ldsm_x2(bl[nt], sBl_u + off);
                }
#pragma unroll
                for (int mt = 0; mt < 2; mt++)
#pragma unroll
                    for (int nt = 0; nt < 4; nt++) {
                        float* d = acc[mt][ng * 4 + nt];
                        mma_bf16(d, ah[mt], bh[nt]);
                        mma_bf16(d, ah[mt], bl[nt]);
                        mma_bf16(d, al[mt], bh[nt]);
                    }
            }
        }
        __syncthreads();
        if (ci + 2 < nchunks) issue(ci + 2, buf);
        cp_commit();
    }

    const bool relu = (flags & FLAG_RELU) != 0;
    const bool accu = (flags & FLAG_ACC) != 0;
#pragma unroll
    for (int mt = 0; mt < 2; mt++) {
        int rbase = m0 + wm + mt * 16 + (lane >> 2);
#pragma unroll
        for (int nt = 0; nt < 8; nt++) {
            int c0 = n0 + wn + nt * 8 + (lane & 3) * 2;
#pragma unroll
            for (int half = 0; half < 2; half++) {
                int row = rbase + half * 8;
                if (row >= Mn) continue;
                float v0 = acc[mt][nt][half * 2 + 0];
                float v1 = acc[mt][nt][half * 2 + 1];
                if (c0 < scale_cols)     v0 *= scale;
                if (c0 + 1 < scale_cols) v1 *= scale;
                if (bias) { v0 += bias[c0]; v1 += bias[c0 + 1]; }
                if (relu) { v0 = fmaxf(v0, 0.f); v1 = fmaxf(v1, 0.f); }
                size_t o = (size_t)row * Nn + c0;
                if (accu) { C[o] += v0; C[o + 1] += v1; }
                else      { C[o] = v0;  C[o + 1] = v1; }
            }
        }
    }
}

// ---------------------------------------------------------------------------
// Batched logits MMA (K=64, one chunk): C[b][m][n] = A[b] @ B[b]^T
// ---------------------------------------------------------------------------
#define TCB_STR  72
#define SLOG_SMEM (4 * 128 * TCB_STR * 2)   // 73728 bytes

__global__ void __launch_bounds__(256)
slogits_kernel(const __nv_bfloat16* __restrict__ Ahi, const __nv_bfloat16* __restrict__ Alo,
               const __nv_bfloat16* __restrict__ Bhi, const __nv_bfloat16* __restrict__ Blo,
               float* __restrict__ C,
               size_t strideA, size_t strideB, size_t strideC, int ldc)
{
    extern __shared__ __nv_bfloat16 smb[];
    __nv_bfloat16* sAh = smb;
    __nv_bfloat16* sAl = smb + 128 * TCB_STR;
    __nv_bfloat16* sBh = smb + 2 * 128 * TCB_STR;
    __nv_bfloat16* sBl = smb + 3 * 128 * TCB_STR;

    const int t = threadIdx.x, lane = t & 31, wid = t >> 5;
    const int m0 = blockIdx.y * 128, n0 = blockIdx.x * 128;
    const int b = blockIdx.z;
    const __nv_bfloat16* Ah = Ahi + (size_t)b * strideA;
    const __nv_bfloat16* Al = Alo + (size_t)b * strideA;
    const __nv_bfloat16* Bh = Bhi + (size_t)b * strideB;
    const __nv_bfloat16* Bl = Blo + (size_t)b * strideB;
    float* Cb = C + (size_t)b * strideC;

    const int wm = (wid & 3) * 32;
    const int wn = (wid >> 2) * 64;

    const uint32_t sAh_u = smem_u32(sAh), sAl_u = smem_u32(sAl);
    const uint32_t sBh_u = smem_u32(sBh), sBl_u = smem_u32(sBl);

    const int a_row = (lane & 7) + ((lane >> 3) & 1) * 8;
    const int a_col = (lane >> 4) * 8;
    const int b_row = lane & 7;
    const int b_col = ((lane >> 3) & 1) * 8;

    float acc[2][8][4];
#pragma unroll
    for (int i = 0; i < 2; i++)
#pragma unroll
        for (int j = 0; j < 8; j++)
#pragma unroll
            for (int k = 0; k < 4; k++) acc[i][j][k] = 0.f;

    for (int i = t; i < 1024; i += 256) {
        int r = i >> 3, kg = (i & 7) << 3;
        int off = r * TCB_STR + kg;
        size_t ga = (size_t)(m0 + r) * DH + kg;
        size_t gb = (size_t)(n0 + r) * DH + kg;
        *reinterpret_cast<uint4*>(sAh + off) = *reinterpret_cast<const uint4*>(Ah + ga);
        *reinterpret_cast<uint4*>(sAl + off) = *reinterpret_cast<const uint4*>(Al + ga);
        *reinterpret_cast<uint4*>(sBh + off) = *reinterpret_cast<const uint4*>(Bh + gb);
        *reinterpret_cast<uint4*>(sBl + off) = *reinterpret_cast<const uint4*>(Bl + gb);
    }
    __syncthreads();
#pragma unroll
    for (int ks = 0; ks < 4; ks++) {
        const int kl = ks * 16;
        uint32_t ah[2][4], al[2][4];
#pragma unroll
        for (int mt = 0; mt < 2; mt++) {
            uint32_t off = (uint32_t)((wm + mt * 16 + a_row) * TCB_STR + kl + a_col) * 2;
            ldsm_x4(ah[mt], sAh_u + off);
            ldsm_x4(al[mt], sAl_u + off);
        }
#pragma unroll
        for (int ng = 0; ng < 2; ng++) {
            uint32_t bh[4][2], bl[4][2];
#pragma unroll
            for (int nt = 0; nt < 4; nt++) {
                uint32_t off = (uint32_t)((wn + ng * 32 + nt * 8 + b_row) * TCB_STR + kl + b_col) * 2;
                ldsm_x2(bh[nt], sBh_u + off);
                ldsm_x2(bl[nt], sBl_u + off);
            }
#pragma unroll
            for (int mt = 0; mt < 2; mt++)
#pragma unroll
                for (int nt = 0; nt < 4; nt++) {
                    float* d = acc[mt][nt + ng * 4];
                    mma_bf16(d, ah[mt], bh[nt]);
                    mma_bf16(d, ah[mt], bl[nt]);
                    mma_bf16(d, al[mt], bh[nt]);
                }
        }
    }

#pragma unroll
    for (int mt = 0; mt < 2; mt++) {
        int rbase = m0 + wm + mt * 16 + (lane >> 2);
#pragma unroll
        for (int nt = 0; nt < 8; nt++) {
            int c0 = n0 + wn + nt * 8 + (lane & 3) * 2;
#pragma unroll
            for (int half = 0; half < 2; half++) {
                int row = rbase + half * 8;
                size_t o = (size_t)row * ldc + c0;
                Cb[o]     = acc[mt][nt][half * 2 + 0];
                Cb[o + 1] = acc[mt][nt][half * 2 + 1];
            }
        }
    }
}

// ---------------------------------------------------------------------------
// pgemm: C = P @ B; P hi/lo [M][K] row-major, B hi/lo [K][64] row-major
// (B via ldmatrix.trans). CTA 128x64; 8 warps (4m x 2n).
// mode 0: split-K partial -> PVP ; mode 1: full-K -> O
// ---------------------------------------------------------------------------
#define PG_PH  0
#define PG_PL  (128 * TCB_STR)
#define PG_BH  (2 * 128 * TCB_STR)
#define PG_BL  (2 * 128 * TCB_STR + 64 * TCB_STR)
#define PG_SMEM ((2 * 128 * TCB_STR + 2 * 64 * TCB_STR) * 2)   // 55296 bytes

__global__ void __launch_bounds__(256)
pgemm_kernel(const __nv_bfloat16* __restrict__ Phi, const __nv_bfloat16* __restrict__ Plo,
             const __nv_bfloat16* __restrict__ Bhi, const __nv_bfloat16* __restrict__ Blo,
             float* __restrict__ Cout,
             int Pld, size_t pHeadStride, size_t bHeadStride,
             int chunksPerSliceBase, int mode)
{
    extern __shared__ __nv_bfloat16 smb[];
    __nv_bfloat16* sPh = smb + PG_PH;
    __nv_bfloat16* sPl = smb + PG_PL;
    __nv_bfloat16* sBh = smb + PG_BH;
    __nv_bfloat16* sBl = smb + PG_BL;

    const int t = threadIdx.x, lane = t & 31, wid = t >> 5;
    const int m0 = blockIdx.x * 128;
    const int kslice = blockIdx.y;
    const int head = blockIdx.z;

    int c0, nch;
    if (mode == 0) {
        if (kslice < 4) { c0 = kslice * (chunksPerSliceBase + 1); nch = chunksPerSliceBase + 1; }
        else { c0 = 4 * (chunksPerSliceBase + 1) + (kslice - 4) * chunksPerSliceBase; nch = chunksPerSliceBase; }
    } else {
        c0 = 0; nch = chunksPerSliceBase;
    }

    const __nv_bfloat16* Ph = Phi + (size_t)head * pHeadStride;
    const __nv_bfloat16* Pl = Plo + (size_t)head * pHeadStride;
    const __nv_bfloat16* Bh = Bhi + (size_t)head * bHeadStride;
    const __nv_bfloat16* Bl = Blo + (size_t)head * bHeadStride;

    const int wm = (wid & 3) * 32;
    const int wn = (wid >> 2) * 32;

    const uint32_t sPh_u = smem_u32(sPh), sPl_u = smem_u32(sPl);
    const uint32_t sBh_u = smem_u32(sBh), sBl_u = smem_u32(sBl);

    const int a_row = (lane & 7) + ((lane >> 3) & 1) * 8;
    const int a_col = (lane >> 4) * 8;
    const int bt_k = lane & 15;

    float acc[2][4][4];
#pragma unroll
    for (int i = 0; i < 2; i++)
#pragma unroll
        for (int j = 0; j < 4; j++)
#pragma unroll
            for (int k = 0; k < 4; k++) acc[i][j][k] = 0.f;

    for (int ci = 0; ci < nch; ci++) {
        int k0 = (c0 + ci) << 6;
        for (int i = t; i < 1024; i += 256) {
            int r = i >> 3, kg = (i & 7) << 3;
            int off = r * TCB_STR + kg;
            size_t gp = (size_t)(m0 + r) * Pld + k0 + kg;
            *reinterpret_cast<uint4*>(sPh + off) = *reinterpret_cast<const uint4*>(Ph + gp);
            *reinterpret_cast<uint4*>(sPl + off) = *reinterpret_cast<const uint4*>(Pl + gp);
        }
        for (int i = t; i < 512; i += 256) {
            int r = i >> 3, kg = (i & 7) << 3;
            int off = r * TCB_STR + kg;
            size_t gb = (size_t)(k0 + r) * 64 + kg;
            *reinterpret_cast<uint4*>(sBh + off) = *reinterpret_cast<const uint4*>(Bh + gb);
            *reinterpret_cast<uint4*>(sBl + off) = *reinterpret_cast<const uint4*>(Bl + gb);
        }
        __syncthreads();
#pragma unroll
        for (int ks = 0; ks < 4; ks++) {
            const int kl = ks * 16;
            uint32_t ph[2][4], pl[2][4];
#pragma unroll
            for (int mt = 0; mt < 2; mt++) {
                uint32_t off = (uint32_t)((wm + mt * 16 + a_row) * TCB_STR + kl + a_col) * 2;
                ldsm_x4(ph[mt], sPh_u + off);
                ldsm_x4(pl[mt], sPl_u + off);
            }
            uint32_t bh[4][2], bl[4][2];
#pragma unroll
            for (int nt = 0; nt < 4; nt++) {
                uint32_t off = (uint32_t)((kl + bt_k) * TCB_STR + wn + nt * 8) * 2;
                ldsm_x2_trans(bh[nt], sBh_u + off);
                ldsm_x2_trans(bl[nt], sBl_u + off);
            }
#pragma unroll
            for (int mt = 0; mt < 2; mt++)
#pragma unroll
                for (int nt = 0; nt < 4; nt++) {
                    float* d = acc[mt][nt];
                    mma_bf16(d, ph[mt], bh[nt]);
                    mma_bf16(d, ph[mt], bl[nt]);
                    mma_bf16(d, pl[mt], bh[nt]);
                }
        }
        __syncthreads();
    }

#pragma unroll
    for (int mt = 0; mt < 2; mt++) {
        int rbase = m0 + wm + mt * 16 + (lane >> 2);
#pragma unroll
        for (int nt = 0; nt < 4; nt++) {
            int c0c = wn + nt * 8 + (lane & 3) * 2;
#pragma unroll
            for (int half = 0; half < 2; half++) {
                int row = rbase + half * 8;
                float v0 = acc[mt][nt][half * 2 + 0];
                float v1 = acc[mt][nt][half * 2 + 1];
                if (mode == 0) {
                    size_t o = (((size_t)kslice * NHEADS + head) * MLAND + row) * 64 + c0c;
                    Cout[o] = v0; Cout[o + 1] = v1;
                } else {
                    size_t o = (size_t)row * DMODEL + head * 64 + c0c;
                    Cout[o] = v0; Cout[o + 1] = v1;
                }
            }
        }
    }
}

// ---------------------------------------------------------------------------
// split-K reduction: A3V = sum over 8 slices
// ---------------------------------------------------------------------------
__global__ void pvred_kernel(const float* __restrict__ PVP, float* __restrict__ A3V)
{
    int h = blockIdx.x & 7, seg = blockIdx.x >> 3;
    int idx = seg * 2048 + threadIdx.x * 8;
    for (int j = 0; j < 8; j++) {
        int li = idx + j;
        float s = 0.f;
#pragma unroll
        for (int sl = 0; sl < 8; sl++)
            s += PVP[(((size_t)sl * NHEADS + h) * MLAND * 64) + li];
        A3V[(size_t)h * MLAND * 64 + li] = s;
    }
}

// ---------------------------------------------------------------------------
// p3 softmax: S3 [h][m][NP] -> normalized P hi/lo (block per row)
// ---------------------------------------------------------------------------
__global__ void p3_kernel(const float* __restrict__ S,
                          __nv_bfloat16* __restrict__ PH, __nv_bfloat16* __restrict__ PL)
{
    int m = blockIdx.x, h = blockIdx.y;
    int t = threadIdx.x;
    const float* row = S + ((size_t)h * MLAND + m) * NP;
    float vals[33];
    float mx = -1e30f;
#pragma unroll
    for (int i = 0; i < 33; i++) {
        vals[i] = row[i * 256 + t];
        mx = fmaxf(mx, vals[i]);
    }
    __shared__ float red[256];
    red[t] = mx; __syncthreads();
    for (int o = 128; o > 0; o >>= 1) {
        if (t < o) red[t] = fmaxf(red[t], red[t + o]);
        __syncthreads();
    }
    mx = red[0]; __syncthreads();
    float sum = 0.f;
#pragma unroll
    for (int i = 0; i < 33; i++) {
        vals[i] = __expf(vals[i] - mx);
        sum += vals[i];
    }
    red[t] = sum; __syncthreads();
    for (int o = 128; o > 0; o >>= 1) {
        if (t < o) red[t] += red[t + o];
        __syncthreads();
    }
    float inv = 1.0f / red[0];
    __nv_bfloat16* ph = PH + ((size_t)h * MLAND + m) * NP;
    __nv_bfloat16* pl = PL + ((size_t)h * MLAND + m) * NP;
#pragma unroll
    for (int i = 0; i < 33; i++) {
        float p = vals[i] * inv;
        __nv_bfloat16 hi = __float2bfloat16(p);
        ph[i * 256 + t] = hi;
        pl[i * 256 + t] = __float2bfloat16(p - __bfloat162float(hi));
    }
}

// ---------------------------------------------------------------------------
// p1 softmax: S1 [h][n][256] -> normalized P hi/lo (warp per row)
// ---------------------------------------------------------------------------
__global__ void p1_kernel(const float* __restrict__ S,
                          __nv_bfloat16* __restrict__ PH, __nv_bfloat16* __restrict__ PL)
{
    int row = blockIdx.x * 8 + (threadIdx.x >> 5);
    int lane = threadIdx.x & 31;
    const float* r = S + (size_t)row * MLAND;
    float a[8];
#pragma unroll
    for (int k = 0; k < 8; k++) a[k] = r[lane + k * 32];
    float m = a[0];
#pragma unroll
    for (int k = 1; k < 8; k++) m = fmaxf(m, a[k]);
    for (int o = 16; o > 0; o >>= 1) m = fmaxf(m, __shfl_xor_sync(0xffffffffu, m, o));
    float s = 0.f;
#pragma unroll
    for (int k = 0; k < 8; k++) { a[k] = __expf(a[k] - m); s += a[k]; }
    for (int o = 16; o > 0; o >>= 1) s += __shfl_xor_sync(0xffffffffu, s, o);
    float inv = 1.0f / s;
    __nv_bfloat16* ph = PH + (size_t)row * MLAND;
    __nv_bfloat16* pl = PL + (size_t)row * MLAND;
#pragma unroll
    for (int k = 0; k < 8; k++) {
        float p = a[k] * inv;
        __nv_bfloat16 hi = __float2bfloat16(p);
        ph[lane + k * 32] = hi;
        pl[lane + k * 32] = __float2bfloat16(p - __bfloat162float(hi));
    }
}

// ---------------------------------------------------------------------------
// Assemble h rows: cls + wrap
// ---------------------------------------------------------------------------
__global__ void assemble_kernel(const float* __restrict__ cls, float* __restrict__ H)
{
    int j = blockIdx.x;
    int c = threadIdx.x;
    if (j == 0) H[c] = cls[c];
    else        H[(size_t)(NTOK + j) * DMODEL + c] = H[(size_t)j * DMODEL + c];
}

// ---------------------------------------------------------------------------
// LayerNorm into padded XP
// ---------------------------------------------------------------------------
__global__ void ln_pad_kernel(const float* __restrict__ Hin, float* __restrict__ XP,
                              const float* __restrict__ g, const float* __restrict__ b)
{
    int row = blockIdx.x;
    int tid = threadIdx.x;
    if (row < PADF) {
        XP[(size_t)row * DMODEL + tid] = 0.f;
        XP[(size_t)row * DMODEL + tid + 256] = 0.f;
        return;
    }
    const float* x = Hin + (size_t)(row - PADF) * DMODEL;
    float v0 = x[tid], v1 = x[tid + 256];
    __shared__ float s1[256], s2[256];
    s1[tid] = v0 + v1;
    s2[tid] = v0 * v0 + v1 * v1;
    __syncthreads();
    for (int o = 128; o > 0; o >>= 1) {
        if (tid < o) { s1[tid] += s1[tid + o]; s2[tid] += s2[tid + o]; }
        __syncthreads();
    }
    float mean = s1[0] * (1.f / DMODEL);
    float var  = s2[0] * (1.f / DMODEL) - mean * mean;
    float rs = rsqrtf(var + EPSLN);
    XP[(size_t)row * DMODEL + tid]       = (v0 - mean) * rs * g[tid] + b[tid];
    XP[(size_t)row * DMODEL + tid + 256] = (v1 - mean) * rs * g[tid + 256] + b[tid + 256];
}

// ---------------------------------------------------------------------------
// Landmarks: means of 33-groups; f32 QL/KL + bf16 hi/lo copies
// ---------------------------------------------------------------------------
__global__ void landmarks_kernel(const float* __restrict__ QKV,
                                 float* __restrict__ QL, float* __restrict__ KL,
                                 __nv_bfloat16* __restrict__ QLH, __nv_bfloat16* __restrict__ QLL,
                                 __nv_bfloat16* __restrict__ KLH, __nv_bfloat16* __restrict__ KLL)
{
    int hm = blockIdx.x;
    int h = hm >> 8, m = hm & 255;
    int tid = threadIdx.x;
    int d = tid & 63;
    int off = (tid < 64) ? 0 : DMODEL;
    size_t base = (size_t)(m * LWIN) * (3 * DMODEL) + off + h * DH + d;
    float s = 0.f;
#pragma unroll
    for (int j = 0; j < LWIN; j++) s += QKV[base + (size_t)j * (3 * DMODEL)];
    s *= (1.0f / LWIN);
    __nv_bfloat16 hi = __float2bfloat16(s);
    __nv_bfloat16 lo = __float2bfloat16(s - __bfloat162float(hi));
    size_t o = (size_t)(h * MLAND + m) * DH + d;
    if (tid < 64) {
        QL[o] = s; QLH[o] = hi; QLL[o] = lo;
    } else {
        KL[o] = s; KLH[o] = hi; KLL[o] = lo;
    }
}

// ---------------------------------------------------------------------------
// a2 = softmax(q_l @ k_l^T)
// ---------------------------------------------------------------------------
__global__ void a2_kernel(const float* __restrict__ QL, const float* __restrict__ KL,
                          float* __restrict__ A2)
{
    int m = blockIdx.x, h = blockIdx.y;
    int tid = threadIdx.x;
    __shared__ float q[64];
    __shared__ float red[256];
    if (tid < 64) q[tid] = QL[(size_t)(h * MLAND + m) * DH + tid];
    __syncthreads();
    const float* kr = KL + (size_t)(h * MLAND + tid) * DH;
    float s = 0.f;
#pragma unroll
    for (int i = 0; i < 16; i++) {
        float4 kv = reinterpret_cast<const float4*>(kr)[i];
        float4 qv = reinterpret_cast<const float4*>(q)[i];
        s += kv.x * qv.x + kv.y * qv.y + kv.z * qv.z + kv.w * qv.w;
    }
    red[tid] = s; __syncthreads();
    for (int o = 128; o > 0; o >>= 1) {
        if (tid < o) red[tid] = fmaxf(red[tid], red[tid + o]);
        __syncthreads();
    }
    float mx = red[0]; __syncthreads();
    float e = __expf(s - mx);
    red[tid] = e; __syncthreads();
    for (int o = 128; o > 0; o >>= 1) {
        if (tid < o) red[tid] += red[tid + o];
        __syncthreads();
    }
    float sm = red[0];
    A2[(size_t)(h * MLAND + m) * MLAND + tid] = e / sm;
}

// ---------------------------------------------------------------------------
// pinv chain
// ---------------------------------------------------------------------------
__global__ void pinv_scale_kernel(const float* __restrict__ A2, float* __restrict__ PS)
{
    int h = blockIdx.x;
    int t = threadIdx.x;
    int w = t >> 5, lane = t & 31;
    const float* Ah = A2 + (size_t)h * 65536;
    __shared__ float rs[256];
    __shared__ float cs2[256];
    for (int r = w; r < 256; r += 8) {
        float s = 0.f;
        for (int j = lane; j < 256; j += 32) s += fabsf(Ah[r * 256 + j]);
        for (int o = 16; o > 0; o >>= 1) s += __shfl_xor_sync(0xffffffffu, s, o);
        if (lane == 0) rs[r] = s;
    }
    float cs = 0.f;
    for (int i = 0; i < 256; i++) cs += fabsf(Ah[i * 256 + t]);
    cs2[t] = cs;
    __syncthreads();
    for (int o = 128; o > 0; o >>= 1) {
        if (t < o) { rs[t] = fmaxf(rs[t], rs[t + o]); cs2[t] = fmaxf(cs2[t], cs2[t + o]); }
        __syncthreads();
    }
    if (t == 0) PS[h] = 1.0f / (rs[0] * cs2[0]);
}

__global__ void pinv_tr_kernel(const float* __restrict__ A2, const float* __restrict__ PS,
                               float* __restrict__ Z0)
{
    __shared__ float tl[64][65];
    int h = blockIdx.y;
    int seg = blockIdx.x;
    int bi = (seg >> 2) * 64, bj = (seg & 3) * 64;
    int t = threadIdx.x;
    float inv = PS[h];
    const float* Ah = A2 + (size_t)h * 65536;
    float* Zh = Z0 + (size_t)h * 65536;
    for (int lin = t; lin < 4096; lin += 256) {
        int r = lin >> 6, c = lin & 63;
        tl[r][c] = Ah[(size_t)(bi + r) * 256 + bj + c];
    }
    __syncthreads();
    for (int lin = t; lin < 4096; lin += 256) {
        int r = lin >> 6, c = lin & 63;
        Zh[(size_t)(bj + r) * 256 + bi + c] = tl[c][r] * inv;
    }
}

__global__ void nk256_kernel(const float* __restrict__ A, const float* __restrict__ B,
                             float* __restrict__ C, float alpha, float gamma)
{
    const float* Ah = A + (size_t)blockIdx.z * 65536;
    const float* Bh = B + (size_t)blockIdx.z * 65536;
    float* Ch = C + (size_t)blockIdx.z * 65536;
    __shared__ float As[16][64];
    __shared__ float Bs[16][64];
    const int bm = blockIdx.y * 64;
    const int bn = blockIdx.x * 64;
    const int tid = threadIdx.x;
    const int tx = tid & 15, ty = tid >> 4;
    const int row0 = ty * 4, col0 = tx * 4;
    float acc[4][4];
#pragma unroll
    for (int i = 0; i < 4; i++)
#pragma unroll
        for (int j = 0; j < 4; j++) acc[i][j] = 0.f;

    for (int k0 = 0; k0 < 256; k0 += 16) {
        {
            int ar = tid >> 2;
            int ac = (tid & 3) << 2;
            float4 v = *reinterpret_cast<const float4*>(Ah + (size_t)(bm + ar) * 256 + k0 + ac);
            As[ac + 0][ar] = v.x; As[ac + 1][ar] = v.y;
            As[ac + 2][ar] = v.z; As[ac + 3][ar] = v.w;
        }
        {
            int br = tid >> 4;
            int bc = (tid & 15) << 2;
            float4 v = *reinterpret_cast<const float4*>(Bh + (size_t)(k0 + br) * 256 + bn + bc);
            *reinterpret_cast<float4*>(&Bs[br][bc]) = v;
        }
        __syncthreads();
#pragma unroll
        for (int k = 0; k < 16; k++) {
            float a[4], b[4];
            *reinterpret_cast<float4*>(a) = *reinterpret_cast<const float4*>(&As[k][row0]);
            *reinterpret_cast<float4*>(b) = *reinterpret_cast<const float4*>(&Bs[k][col0]);
#pragma unroll
            for (int i = 0; i < 4; i++)
#pragma unroll
                for (int j = 0; j < 4; j++) acc[i][j] += a[i] * b[j];
        }
        __syncthreads();
    }
#pragma unroll
    for (int i = 0; i < 4; i++)
#pragma unroll
        for (int j = 0; j < 4; j++) {
            size_t o = (size_t)(bm + row0 + i) * 256 + bn + col0 + j;
            Ch[o] = alpha * acc[i][j] + gamma * Ah[o];
        }
}

// ---------------------------------------------------------------------------
// Bm = pinv(a2) @ a3v  -> bf16 hi/lo
// ---------------------------------------------------------------------------
__global__ void bmat_kernel(const float* __restrict__ Z, const float* __restrict__ A3V,
                            __nv_bfloat16* __restrict__ BmH, __nv_bfloat16* __restrict__ BmL)
{
    int h = blockIdx.y;
    int m0 = blockIdx.x * 4;
    __shared__ float zs[4][256];
    int tid = threadIdx.x;
    int r = tid >> 6, d = tid & 63;
    for (int lin = tid; lin < 1024; lin += 256) {
        int rr = lin >> 8, k = lin & 255;
        zs[rr][k] = Z[(size_t)h * 65536 + (size_t)(m0 + rr) * 256 + k];
    }
    __syncthreads();
    float acc = 0.f;
    for (int k = 0; k < 256; k++)
        acc += zs[r][k] * A3V[(size_t)(h * MLAND + k) * DH + d];
    size_t o = (size_t)(h * MLAND + m0 + r) * DH + d;
    __nv_bfloat16 hi = __float2bfloat16(acc);
    BmH[o] = hi;
    BmL[o] = __float2bfloat16(acc - __bfloat162float(hi));
}

// ---------------------------------------------------------------------------
// Depthwise seq-conv (k=33) on v, tiled in smem; adds into O
// ---------------------------------------------------------------------------
__global__ void conv_tile_kernel(const float* __restrict__ QKV, const float* __restrict__ W,
                                 float* __restrict__ O)
{
    __shared__ float vs[160 * 64];
    __shared__ float ws[33];
    int h = blockIdx.y;
    int n0 = blockIdx.x * 128;
    int t = threadIdx.x;
    if (t < 33) ws[t] = W[h * LWIN + t];
    for (int lin = t; lin < 160 * 64; lin += 256) {
        int r = lin >> 6, c = lin & 63;
        int n = n0 + r - 16;
        vs[lin] = (n >= 0 && n < NP)
                    ? QKV[(size_t)n * (3 * DMODEL) + 2 * DMODEL + h * DH + c] : 0.f;
    }
    __syncthreads();
    int c = t & 63, rg = t >> 6;
    for (int q = 0; q < 32; q++) {
        int r = rg * 32 + q;
        float acc = 0.f;
#pragma unroll
        for (int k = 0; k < LWIN; k++) acc += ws[k] * vs[(r + k) * 64 + c];
        O[(size_t)(n0 + r) * DMODEL + h * DH + c] += acc;
    }
}

// ---------------------------------------------------------------------------
// PPEG tiled
// ---------------------------------------------------------------------------
#define PPEG_TILE (14 * 14 * 64)
#define PPEG_W7   PPEG_TILE
#define PPEG_W5   (PPEG_W7 + 64 * 49)
#define PPEG_W3   (PPEG_W5 + 64 * 25)
#define PPEG_TOT  (PPEG_W3 + 64 * 9)

__global__ void ppeg_tile_kernel(const float* __restrict__ Hin, float* __restrict__ Hout,
                                 const float* __restrict__ w7, const float* __restrict__ b7,
                                 const float* __restrict__ w5, const float* __restrict__ b5,
                                 const float* __restrict__ w3, const float* __restrict__ b3)
{
    extern __shared__ float sm[];
    float* tile = sm;
    float* ws7 = sm + PPEG_W7;
    float* ws5 = sm + PPEG_W5;
    float* ws3 = sm + PPEG_W3;

    int ti = blockIdx.x;
    int ty0 = (ti / 12) * 8, tx0 = (ti % 12) * 8;
    int cg = blockIdx.y * 64;
    int t = threadIdx.x;

    for (int lin = t; lin < PPEG_TILE; lin += 256) {
        int p = lin >> 6, c = lin & 63;
        int gy = ty0 + p / 14 - 3;
        int gx = tx0 + p % 14 - 3;
        float v = 0.f;
        if ((unsigned)gy < (unsigned)HSQ && (unsigned)gx < (unsigned)HSQ)
            v = Hin[(size_t)(1 + gy * HSQ + gx) * DMODEL + cg + c];
        tile[lin] = v;
    }
    for (int lin = t; lin < 64 * 49; lin += 256) ws7[lin] = w7[(size_t)cg * 49 + lin];
    for (int lin = t; lin < 64 * 25; lin += 256) ws5[lin] = w5[(size_t)cg * 25 + lin];
    for (int lin = t; lin < 64 * 9;  lin += 256) ws3[lin] = w3[(size_t)cg * 9 + lin];
    __syncthreads();

    int c = t & 63, pg = t >> 6;
    float bsum = b7[cg + c] + b5[cg + c] + b3[cg + c];
    for (int q = 0; q < 16; q++) {
        int p = pg * 16 + q;
        int oy = p >> 3, ox = p & 7;
        int gy = ty0 + oy, gx = tx0 + ox;
        if (gy >= HSQ || gx >= HSQ) continue;
        float acc = tile[((oy + 3) * 14 + ox + 3) * 64 + c] + bsum;
#pragma unroll
        for (int a = 0; a < 7; a++)
#pragma unroll
            for (int bq = 0; bq < 7; bq++)
                acc += ws7[c * 49 + a * 7 + bq] * tile[((oy + a) * 14 + ox + bq) * 64 + c];
#pragma unroll
        for (int a = 0; a < 5; a++)
#pragma unroll
            for (int bq = 0; bq < 5; bq++)
                acc += ws5[c * 25 + a * 5 + bq] * tile[((oy + a + 1) * 14 + ox + bq + 1) * 64 + c];
#pragma unroll
        for (int a = 0; a < 3; a++)
#pragma unroll
            for (int bq = 0; bq < 3; bq++)
                acc += ws3[c * 9 + a * 3 + bq] * tile[((oy + a + 2) * 14 + ox + bq + 2) * 64 + c];
        Hout[(size_t)(1 + gy * HSQ + gx) * DMODEL + cg + c] = acc;
    }
}

__global__ void copy_row0_kernel(const float* __restrict__ Hin, float* __restrict__ Hout)
{
    Hout[threadIdx.x] = Hin[threadIdx.x];
}

// ---------------------------------------------------------------------------
// Final head
// ---------------------------------------------------------------------------
__global__ void final_kernel(const float* __restrict__ H, const float* __restrict__ g,
                             const float* __restrict__ b, const float* __restrict__ w,
                             const float* __restrict__ bias2, float* __restrict__ out,
                             int out_size)
{
    int c = threadIdx.x;
    __shared__ float s1[512], s2[512];
    float x = H[c];
    s1[c] = x; s2[c] = x * x;
    __syncthreads();
    for (int o = 256; o > 0; o >>= 1) {
        if (c < o) { s1[c] += s1[c + o]; s2[c] += s2[c + o]; }
        __syncthreads();
    }
    float mean = s1[0] * (1.f / DMODEL);
    float var  = s2[0] * (1.f / DMODEL) - mean * mean;
    float e = (x - mean) * rsqrtf(var + EPSLN) * g[c] + b[c];
    __syncthreads();
    s1[c] = e * w[c * 2 + 0];
    s2[c] = e * w[c * 2 + 1];
    __syncthreads();
    for (int o = 256; o > 0; o >>= 1) {
        if (c < o) { s1[c] += s1[c + o]; s2[c] += s2[c + o]; }
        __syncthreads();
    }
    float l0 = s1[0] + bias2[0];
    float l1 = s2[0] + bias2[1];
    if (c == 0) {
        float m = fmaxf(l0, l1);
        float e0 = expf(l0 - m), e1 = expf(l1 - m);
        float ss = e0 + e1;
        if (out_size > 0) out[0] = l0;
        if (out_size > 1) out[1] = l1;
        if (out_size > 2) out[2] = e0 / ss;
        if (out_size > 3) out[3] = e1 / ss;
        if (out_size > 4) out[4] = (l1 > l0) ? 1.0f : 0.0f;
    }
    if (5 + c < out_size) out[5 + c] = e;
}

// ---------------------------------------------------------------------------
// Host orchestration
// ---------------------------------------------------------------------------
static float* symaddr(const void* sym)
{
    void* p = nullptr;
    cudaGetSymbolAddress(&p, sym);
    return (float*)p;
}
static __nv_bfloat16* symaddr_bf(const void* sym)
{
    void* p = nullptr;
    cudaGetSymbolAddress(&p, sym);
    return (__nv_bfloat16*)p;
}

static cudaStream_t g_side = nullptr;
static cudaEvent_t  g_evf  = nullptr;
static cudaEvent_t  g_evj  = nullptr;

extern "C" void kernel_launch(void* const* d_in, const int* in_sizes, int n_in,
                              void* d_out, int out_size)
{
    if (!g_side) {
        cudaStreamCreateWithFlags(&g_side, cudaStreamNonBlocking);
        cudaEventCreateWithFlags(&g_evf, cudaEventDisableTiming);
        cudaEventCreateWithFlags(&g_evj, cudaEventDisableTiming);
    }

    const float* x       = (const float*)d_in[0];
    const float* fc1_w   = (const float*)d_in[1];
    const float* fc1_b   = (const float*)d_in[2];
    const float* cls     = (const float*)d_in[3];
    const float* ln1_g   = (const float*)d_in[4];
    const float* ln1_b   = (const float*)d_in[5];
    const float* qkv1_w  = (const float*)d_in[6];
    const float* out1_w  = (const float*)d_in[7];
    const float* out1_b  = (const float*)d_in[8];
    const float* conv1_w = (const float*)d_in[9];
    const float* ln2_g   = (const float*)d_in[10];
    const float* ln2_b   = (const float*)d_in[11];
    const float* qkv2_w  = (const float*)d_in[12];
    const float* out2_w  = (const float*)d_in[13];
    const float* out2_b  = (const float*)d_in[14];
    const float* conv2_w = (const float*)d_in[15];
    const float* pg7_w   = (const float*)d_in[16];
    const float* pg7_b   = (const float*)d_in[17];
    const float* pg5_w   = (const float*)d_in[18];
    const float* pg5_b   = (const float*)d_in[19];
    const float* pg3_w   = (const float*)d_in[20];
    const float* pg3_b   = (const float*)d_in[21];
    const float* norm_g  = (const float*)d_in[22];
    const float* norm_b  = (const float*)d_in[23];
    const float* fc2_w   = (const float*)d_in[24];
    const float* fc2_b   = (const float*)d_in[25];

    float* H   = symaddr(g_H);
    float* H2  = symaddr(g_H2);
    float* XP  = symaddr(g_XP);
    float* QKV = symaddr(g_QKV);
    float* QL  = symaddr(g_QL);
    float* KL  = symaddr(g_KL);
    float* A2  = symaddr(g_A2);
    float* Z0  = symaddr(g_Z0);
    float* Z1  = symaddr(g_Z1);
    float* W1  = symaddr(g_W1);
    float* W2  = symaddr(g_W2);
    float* W3  = symaddr(g_W3);
    float* PS  = symaddr(g_PS);
    float* A3V = symaddr(g_A3V);
    float* O   = symaddr(g_O);
    float* S   = symaddr(g_S);
    float* PVP = symaddr(g_PVP);
    __nv_bfloat16* AH  = symaddr_bf(g_AH);
    __nv_bfloat16* AL  = symaddr_bf(g_AL);
    __nv_bfloat16* WH  = symaddr_bf(g_WH);
    __nv_bfloat16* WL  = symaddr_bf(g_WL);
    __nv_bfloat16* QLH = symaddr_bf(g_QLH);
    __nv_bfloat16* QLL = symaddr_bf(g_QLL);
    __nv_bfloat16* KLH = symaddr_bf(g_KLH);
    __nv_bfloat16* KLL = symaddr_bf(g_KLL);
    __nv_bfloat16* VH  = symaddr_bf(g_VH);
    __nv_bfloat16* VL  = symaddr_bf(g_VL);
    __nv_bfloat16* PH  = symaddr_bf(g_PH);
    __nv_bfloat16* PL  = symaddr_bf(g_PL);
    __nv_bfloat16* BmH = symaddr_bf(g_BmH);
    __nv_bfloat16* BmL = symaddr_bf(g_BmL);

    const int PPEG_SMEM = PPEG_TOT * 4;
    cudaFuncSetAttribute(ppeg_tile_kernel, cudaFuncAttributeMaxDynamicSharedMemorySize, PPEG_SMEM);
    cudaFuncSetAttribute(tc_gemm_kernel,  cudaFuncAttributeMaxDynamicSharedMemorySize, TCG_SMEM);
    cudaFuncSetAttribute(slogits_kernel,  cudaFuncAttributeMaxDynamicSharedMemorySize, SLOG_SMEM);
    cudaFuncSetAttribute(pgemm_kernel,    cudaFuncAttributeMaxDynamicSharedMemorySize, PG_SMEM);

    // ---- fc1 + relu via tensor cores ----
    wconv_kernel<<<dim3(DMODEL / 32, INDIM / 32), 256>>>(fc1_w, WH, WL, INDIM, DMODEL);
    aconv_kernel<<<NTOK, 128>>>(x, AH, AL, NTOK, INDIM);
    tc_gemm_kernel<<<dim3(DMODEL / 128, NTOK / 128), 256, TCG_SMEM>>>(
        AH, AL, WH, WL, H + DMODEL, fc1_b, NTOK, DMODEL, INDIM, FLAG_RELU, 0, 1.f);
    assemble_kernel<<<NWRAP + 1, DMODEL>>>(cls, H);

    auto attn = [&](float* Hbuf, const float* lng, const float* lnb, const float* qkvw,
                    const float* outw, const float* outb, const float* convw) {
        ln_pad_kernel<<<NP, 256>>>(Hbuf, XP, lng, lnb);
        wconv_kernel<<<dim3(3 * DMODEL / 32, DMODEL / 32), 256>>>(qkvw, WH, WL, DMODEL, 3 * DMODEL);
        aconv_kernel<<<NP, 128>>>(XP, AH, AL, NP, DMODEL);
        tc_gemm_kernel<<<dim3(3 * DMODEL / 128, NP / 128), 256, TCG_SMEM>>>(
            AH, AL, WH, WL, QKV, nullptr, NP, 3 * DMODEL, DMODEL, 0, DMODEL, 0.125f);
        qk_split_kernel<<<NP, 256>>>(QKV, AH, AL, VH, VL);
        landmarks_kernel<<<NHEADS * MLAND, 128>>>(QKV, QL, KL, QLH, QLL, KLH, KLL);
        a2_kernel<<<dim3(MLAND, NHEADS), 256>>>(QL, KL, A2);

        // fork: pinv chain on side stream
        cudaEventRecord(g_evf, 0);
        cudaStreamWaitEvent(g_side, g_evf, 0);
        pinv_scale_kernel<<<NHEADS, 256, 0, g_side>>>(A2, PS);
        pinv_tr_kernel<<<dim3(16, NHEADS), 256, 0, g_side>>>(A2, PS, Z0);
        float* zi = Z0;
        float* zo = Z1;
        for (int it = 0; it < 6; it++) {
            nk256_kernel<<<dim3(4, 4, NHEADS), 256, 0, g_side>>>(A2, zi, W1, 1.f, 0.f);
            nk256_kernel<<<dim3(4, 4, NHEADS), 256, 0, g_side>>>(W1, W1, W2, -1.f, 7.f);
            nk256_kernel<<<dim3(4, 4, NHEADS), 256, 0, g_side>>>(W1, W2, W3, -1.f, 15.f);
            nk256_kernel<<<dim3(4, 4, NHEADS), 256, 0, g_side>>>(zi, W3, zo, -0.25f, 3.25f);
            float* t = zi; zi = zo; zo = t;
        }
        cudaEventRecord(g_evj, g_side);

        // S3 = QL @ K^T -> softmax -> A3V = P3 @ V (split-K MMA)
        slogits_kernel<<<dim3(NP / 128, MLAND / 128, NHEADS), 256, SLOG_SMEM>>>(
            QLH, QLL, AH + QKOFF, AL + QKOFF, S,
            (size_t)MLAND * DH, (size_t)NP * DH, (size_t)MLAND * NP, NP);
        p3_kernel<<<dim3(MLAND, NHEADS), 256>>>(S, PH, PL);
        pgemm_kernel<<<dim3(MLAND / 128, 8, NHEADS), 256, PG_SMEM>>>(
            PH, PL, VH, VL, PVP, NP, (size_t)MLAND * NP, (size_t)NP * DH, 16, 0);
        pvred_kernel<<<64, 256>>>(PVP, A3V);

        // S1 = Q @ KL^T -> softmax
        slogits_kernel<<<dim3(MLAND / 128, NP / 128, NHEADS), 256, SLOG_SMEM>>>(
            AH, AL, KLH, KLL, S,
            (size_t)NP * DH, (size_t)MLAND * DH, (size_t)NP * MLAND, MLAND);
        p1_kernel<<<NP * NHEADS / 8, 256>>>(S, PH, PL);

        // join pinv; Bm; O = P1 @ Bm; += conv
        cudaStreamWaitEvent(0, g_evj, 0);
        bmat_kernel<<<dim3(MLAND / 4, NHEADS), 256>>>(zi, A3V, BmH, BmL);
        pgemm_kernel<<<dim3(NP / 128, 1, NHEADS), 256, PG_SMEM>>>(
            PH, PL, BmH, BmL, O, MLAND, (size_t)NP * MLAND, (size_t)MLAND * DH, 4, 1);
        conv_tile_kernel<<<dim3(NP / 128, NHEADS), 256>>>(QKV, convw, O);

        // out projection (accumulate into Hbuf)
        wconv_kernel<<<dim3(DMODEL / 32, DMODEL / 32), 256>>>(outw, WH, WL, DMODEL, DMODEL);
        aconv_kernel<<<8320, 128>>>(O + (size_t)PADF * DMODEL, AH, AL, NHTOK, DMODEL);
        tc_gemm_kernel<<<dim3(DMODEL / 128, 65), 256, TCG_SMEM>>>(
            AH, AL, WH, WL, Hbuf, outb, NHTOK, DMODEL, DMODEL, FLAG_ACC, 0, 1.f);
    };

    attn(H, ln1_g, ln1_b, qkv1_w, out1_w, out1_b, conv1_w);

    ppeg_tile_kernel<<<dim3(144, NHEADS), 256, PPEG_SMEM>>>(
        H, H2, pg7_w, pg7_b, pg5_w, pg5_b, pg3_w, pg3_b);
    copy_row0_kernel<<<1, DMODEL>>>(H, H2);

    attn(H2, ln2_g, ln2_b, qkv2_w, out2_w, out2_b, conv2_w);

    final_kernel<<<1, DMODEL>>>(H2, norm_g, norm_b, fc2_w, fc2_b, (float*)d_out, out_size);
}

// round 13
// speedup vs baseline: 1.1433x; 1.0279x over previous
#include <cuda_runtime.h>
#include <cuda_bf16.h>
#include <math.h>
#include <stdint.h>

// ---------------------------------------------------------------------------
// Problem constants
// ---------------------------------------------------------------------------
#define NTOK   8192
#define INDIM  1024
#define DMODEL 512
#define NHEADS 8
#define DH     64
#define MLAND  256
#define LWIN   33
#define NP     8448          // padded attention length
#define NHTOK  8282          // tokens incl cls
#define PADF   166
#define HSQ    91
#define NFEAT  8281
#define NWRAP  89
#define EPSLN  1e-5f

#define FLAG_RELU 1
#define FLAG_ACC  2

// ---------------------------------------------------------------------------
// Scratch (device globals)
// ---------------------------------------------------------------------------
__device__ float g_H  [NHTOK * DMODEL];
__device__ float g_H2 [NHTOK * DMODEL];
__device__ float g_QKV[NP * 3 * DMODEL];
__device__ float g_QL [NHEADS * MLAND * DH];
__device__ float g_KL [NHEADS * MLAND * DH];
__device__ float g_A2 [NHEADS * MLAND * MLAND];
__device__ float g_Z0 [NHEADS * MLAND * MLAND];
__device__ float g_Z1 [NHEADS * MLAND * MLAND];
__device__ float g_W1 [NHEADS * MLAND * MLAND];
__device__ float g_W2 [NHEADS * MLAND * MLAND];
__device__ float g_W3 [NHEADS * MLAND * MLAND];
__device__ float g_PS [NHEADS];
__device__ float g_A3V[NHEADS * MLAND * DH];
__device__ float g_O  [NP * DMODEL];
__device__ float g_S  [NHEADS * NP * MLAND];     // logits scratch (S3 then S1)
__device__ float g_PVP[8 * NHEADS * MLAND * DH]; // split-K partials
// bf16 hi/lo staging
__device__ __nv_bfloat16 g_AH[NP * INDIM];       // reused: Qh [8][NP][64] + Kh [8][NP][64]
__device__ __nv_bfloat16 g_AL[NP * INDIM];
__device__ __nv_bfloat16 g_WH[3 * DMODEL * DMODEL];
__device__ __nv_bfloat16 g_WL[3 * DMODEL * DMODEL];
__device__ __nv_bfloat16 g_QLH[NHEADS * MLAND * DH];
__device__ __nv_bfloat16 g_QLL[NHEADS * MLAND * DH];
__device__ __nv_bfloat16 g_KLH[NHEADS * MLAND * DH];
__device__ __nv_bfloat16 g_KLL[NHEADS * MLAND * DH];
__device__ __nv_bfloat16 g_VH [NHEADS * NP * DH];
__device__ __nv_bfloat16 g_VL [NHEADS * NP * DH];
__device__ __nv_bfloat16 g_PH [NHEADS * NP * MLAND];
__device__ __nv_bfloat16 g_PL [NHEADS * NP * MLAND];
__device__ __nv_bfloat16 g_BmH[NHEADS * MLAND * DH];
__device__ __nv_bfloat16 g_BmL[NHEADS * MLAND * DH];

#define QKOFF (NHEADS * NP * DH)

// ---------------------------------------------------------------------------
// warp-mma helpers (sm_80+ PTX)
// ---------------------------------------------------------------------------
__device__ __forceinline__ uint32_t smem_u32(const void* p)
{
    uint32_t a;
    asm("{ .reg .u64 t; cvta.to.shared.u64 t, %1; cvt.u32.u64 %0, t; }" : "=r"(a) : "l"(p));
    return a;
}
__device__ __forceinline__ void ldsm_x4(uint32_t* r, uint32_t addr)
{
    asm volatile("ldmatrix.sync.aligned.m8n8.x4.shared.b16 {%0,%1,%2,%3}, [%4];"
                 : "=r"(r[0]), "=r"(r[1]), "=r"(r[2]), "=r"(r[3]) : "r"(addr));
}
__device__ __forceinline__ void ldsm_x2(uint32_t* r, uint32_t addr)
{
    asm volatile("ldmatrix.sync.aligned.m8n8.x2.shared.b16 {%0,%1}, [%2];"
                 : "=r"(r[0]), "=r"(r[1]) : "r"(addr));
}
__device__ __forceinline__ void ldsm_x2_trans(uint32_t* r, uint32_t addr)
{
    asm volatile("ldmatrix.sync.aligned.m8n8.x2.trans.shared.b16 {%0,%1}, [%2];"
                 : "=r"(r[0]), "=r"(r[1]) : "r"(addr));
}
__device__ __forceinline__ void mma_bf16(float* d, const uint32_t* a, const uint32_t* b)
{
    asm volatile("mma.sync.aligned.m16n8k16.row.col.f32.bf16.bf16.f32 "
                 "{%0,%1,%2,%3}, {%4,%5,%6,%7}, {%8,%9}, {%0,%1,%2,%3};"
                 : "+f"(d[0]), "+f"(d[1]), "+f"(d[2]), "+f"(d[3])
                 : "r"(a[0]), "r"(a[1]), "r"(a[2]), "r"(a[3]), "r"(b[0]), "r"(b[1]));
}
__device__ __forceinline__ void cp_async16(uint32_t smem_addr, const void* gptr)
{
    asm volatile("cp.async.ca.shared.global [%0], [%1], 16;"
                 :: "r"(smem_addr), "l"(gptr));
}
__device__ __forceinline__ void cp_commit()
{
    asm volatile("cp.async.commit_group;" ::: "memory");
}
__device__ __forceinline__ void cp_wait1()
{
    asm volatile("cp.async.wait_group 1;" ::: "memory");
}

// ---------------------------------------------------------------------------
// Weight convert+transpose: W [K][N] f32 -> Whi/Wlo [N][K] bf16
// ---------------------------------------------------------------------------
__global__ void wconv_kernel(const float* __restrict__ W,
                             __nv_bfloat16* __restrict__ Whi, __nv_bfloat16* __restrict__ Wlo,
                             int K, int N)
{
    __shared__ float tl[32][33];
    int kb = blockIdx.y * 32, nb = blockIdx.x * 32;
    int t = threadIdx.x;
    for (int i = t; i < 1024; i += 256) {
        int r = i >> 5, c = i & 31;
        tl[r][c] = W[(size_t)(kb + r) * N + nb + c];
    }
    __syncthreads();
    for (int i = t; i < 1024; i += 256) {
        int n = i >> 5, k = i & 31;
        float v = tl[k][n];
        __nv_bfloat16 h = __float2bfloat16(v);
        float lo = v - __bfloat162float(h);
        size_t o = (size_t)(nb + n) * K + kb + k;
        Whi[o] = h;
        Wlo[o] = __float2bfloat16(lo);
    }
}

// ---------------------------------------------------------------------------
// Activation convert (f32 -> hi/lo bf16, zero pad rows)
// ---------------------------------------------------------------------------
__global__ void aconv_kernel(const float* __restrict__ A,
                             __nv_bfloat16* __restrict__ Ahi, __nv_bfloat16* __restrict__ Alo,
                             int Min, int Kn)
{
    int r = blockIdx.x;
    size_t base = (size_t)r * Kn;
    if (r >= Min) {
        __nv_bfloat162 z = __float2bfloat162_rn(0.f);
        for (int c = threadIdx.x * 2; c < Kn; c += 256) {
            *reinterpret_cast<__nv_bfloat162*>(Ahi + base + c) = z;
            *reinterpret_cast<__nv_bfloat162*>(Alo + base + c) = z;
        }
        return;
    }
    for (int c = threadIdx.x * 2; c < Kn; c += 256) {
        float2 v = *reinterpret_cast<const float2*>(A + base + c);
        __nv_bfloat16 h0 = __float2bfloat16(v.x);
        __nv_bfloat16 h1 = __float2bfloat16(v.y);
        float l0 = v.x - __bfloat162float(h0);
        float l1 = v.y - __bfloat162float(h1);
        __nv_bfloat162 hp; hp.x = h0; hp.y = h1;
        __nv_bfloat162 lp; lp.x = __float2bfloat16(l0); lp.y = __float2bfloat16(l1);
        *reinterpret_cast<__nv_bfloat162*>(Ahi + base + c) = hp;
        *reinterpret_cast<__nv_bfloat162*>(Alo + base + c) = lp;
    }
}

// ---------------------------------------------------------------------------
// Fused LayerNorm + bf16 hi/lo conversion: H -> AH/AL (padded rows = 0)
// ---------------------------------------------------------------------------
__global__ void lnconv_kernel(const float* __restrict__ Hin,
                              __nv_bfloat16* __restrict__ Ahi, __nv_bfloat16* __restrict__ Alo,
                              const float* __restrict__ g, const float* __restrict__ b)
{
    int row = blockIdx.x;
    int tid = threadIdx.x;
    size_t base = (size_t)row * DMODEL;
    if (row < PADF) {
        __nv_bfloat16 z = __float2bfloat16(0.f);
        Ahi[base + tid] = z; Ahi[base + tid + 256] = z;
        Alo[base + tid] = z; Alo[base + tid + 256] = z;
        return;
    }
    const float* x = Hin + (size_t)(row - PADF) * DMODEL;
    float v0 = x[tid], v1 = x[tid + 256];
    __shared__ float s1[256], s2[256];
    s1[tid] = v0 + v1;
    s2[tid] = v0 * v0 + v1 * v1;
    __syncthreads();
    for (int o = 128; o > 0; o >>= 1) {
        if (tid < o) { s1[tid] += s1[tid + o]; s2[tid] += s2[tid + o]; }
        __syncthreads();
    }
    float mean = s1[0] * (1.f / DMODEL);
    float var  = s2[0] * (1.f / DMODEL) - mean * mean;
    float rs = rsqrtf(var + EPSLN);
    float y0 = (v0 - mean) * rs * g[tid] + b[tid];
    float y1 = (v1 - mean) * rs * g[tid + 256] + b[tid + 256];
    __nv_bfloat16 h0 = __float2bfloat16(y0);
    __nv_bfloat16 h1 = __float2bfloat16(y1);
    Ahi[base + tid]       = h0;
    Ahi[base + tid + 256] = h1;
    Alo[base + tid]       = __float2bfloat16(y0 - __bfloat162float(h0));
    Alo[base + tid + 256] = __float2bfloat16(y1 - __bfloat162float(h1));
}

// ---------------------------------------------------------------------------
// Q/K/V split
// ---------------------------------------------------------------------------
__global__ void qk_split_kernel(const float* __restrict__ QKV,
                                __nv_bfloat16* __restrict__ BH, __nv_bfloat16* __restrict__ BL,
                                __nv_bfloat16* __restrict__ VH, __nv_bfloat16* __restrict__ VL)
{
    int n = blockIdx.x;
    int t = threadIdx.x;
    for (int i = t; i < 1536; i += 256) {
        int part = i >> 9;
        int hd = i & 511;
        int h = hd >> 6, d = hd & 63;
        float v = QKV[(size_t)n * (3 * DMODEL) + part * DMODEL + hd];
        __nv_bfloat16 hi = __float2bfloat16(v);
        __nv_bfloat16 lo = __float2bfloat16(v - __bfloat162float(hi));
        size_t o = (size_t)h * NP * DH + (size_t)n * DH + d;
        if (part < 2) {
            BH[(size_t)part * QKOFF + o] = hi;
            BL[(size_t)part * QKOFF + o] = lo;
        } else {
            VH[o] = hi;
            VL[o] = lo;
        }
    }
}

// ---------------------------------------------------------------------------
// warp-MMA GEMM with cp.async double-buffered K-chunks of 32.
// C[M][N] = op(A @ B^T); 128x128 CTA tile, 8 warps (4x2).
// ---------------------------------------------------------------------------
#define TCP_STR  40                         // bf16 row stride (80 B, 16B-aligned)
#define TCP_BUF  (4 * 128 * TCP_STR)        // elements per buffer (20480)
#define TCG_SMEM (2 * TCP_BUF * 2)          // 81920 bytes

__global__ void __launch_bounds__(256)
tc_gemm_kernel(const __nv_bfloat16* __restrict__ Ahi, const __nv_bfloat16* __restrict__ Alo,
               const __nv_bfloat16* __restrict__ Bhi, const __nv_bfloat16* __restrict__ Blo,
               float* __restrict__ C, const float* __restrict__ bias,
               int Mn, int Nn, int Kn, int flags, int scale_cols, float scale)
{
    extern __shared__ __nv_bfloat16 smb[];
    const int t = threadIdx.x, lane = t & 31, wid = t >> 5;
    const int m0 = blockIdx.y * 128, n0 = blockIdx.x * 128;
    const int wm = (wid & 3) * 32;
    const int wn = (wid >> 2) * 64;

    const uint32_t smem_base = smem_u32(smb);

    const int a_row = (lane & 7) + ((lane >> 3) & 1) * 8;
    const int a_col = (lane >> 4) * 8;
    const int b_row = lane & 7;
    const int b_col = ((lane >> 3) & 1) * 8;

    const int nchunks = Kn >> 5;

    const int r1 = t >> 2,        kg1 = (t & 3) << 3;
    const int r2 = (t >> 2) + 64, kg2 = kg1;

    auto issue = [&](int ci, int buf) {
        int k0 = ci << 5;
        uint32_t bb = smem_base + (uint32_t)buf * TCP_BUF * 2;
        const __nv_bfloat16* gsrc[4] = {
            Ahi + (size_t)m0 * Kn, Alo + (size_t)m0 * Kn,
            Bhi + (size_t)n0 * Kn, Blo + (size_t)n0 * Kn };
#pragma unroll
        for (int arr = 0; arr < 4; arr++) {
            uint32_t sb = bb + (uint32_t)arr * 128 * TCP_STR * 2;
            cp_async16(sb + (uint32_t)(r1 * TCP_STR + kg1) * 2,
                       gsrc[arr] + (size_t)r1 * Kn + k0 + kg1);
            cp_async16(sb + (uint32_t)(r2 * TCP_STR + kg2) * 2,
                       gsrc[arr] + (size_t)r2 * Kn + k0 + kg2);
        }
    };

    float acc[2][8][4];
#pragma unroll
    for (int i = 0; i < 2; i++)
#pragma unroll
        for (int j = 0; j < 8; j++)
#pragma unroll
            for (int k = 0; k < 4; k++) acc[i][j][k] = 0.f;

    issue(0, 0); cp_commit();
    if (nchunks > 1) issue(1, 1);
    cp_commit();

    for (int ci = 0; ci < nchunks; ci++) {
        cp_wait1();
        __syncthreads();
        const int buf = ci & 1;
        uint32_t bb = smem_base + (uint32_t)buf * TCP_BUF * 2;
        uint32_t sAh_u = bb;
        uint32_t sAl_u = bb + 128 * TCP_STR * 2;
        uint32_t sBh_u = bb + 2 * 128 * TCP_STR * 2;
        uint32_t sBl_u = bb + 3 * 128 * TCP_STR * 2;
#pragma unroll
        for (int ks = 0; ks < 2; ks++) {
            const int kl = ks * 16;
            uint32_t ah[2][4], al[2][4];
#pragma unroll
            for (int mt = 0; mt < 2; mt++) {
                uint32_t off = (uint32_t)((wm + mt * 16 + a_row) * TCP_STR + kl + a_col) * 2;
                ldsm_x4(ah[mt], sAh_u + off);
                ldsm_x4(al[mt], sAl_u + off);
            }
#pragma unroll
            for (int ng = 0; ng < 2; ng++) {
                uint32_t bh[4][2], bl[4][2];
#pragma unroll
                for (int nt = 0; nt < 4; nt++) {
                    uint32_t off = (uint32_t)((wn + ng * 32 + nt * 8 + b_row) * TCP_STR + kl + b_col) * 2;
                    ldsm_x2(bh[nt], sBh_u + off);
                    ldsm_x2(bl[nt], sBl_u + off);
                }
#pragma unroll
                for (int mt = 0; mt < 2; mt++)
#pragma unroll
                    for (int nt = 0; nt < 4; nt++) {
                        float* d = acc[mt][ng * 4 + nt];
                        mma_bf16(d, ah[mt], bh[nt]);
                        mma_bf16(d, ah[mt], bl[nt]);
                        mma_bf16(d, al[mt], bh[nt]);
                    }
            }
        }
        __syncthreads();
        if (ci + 2 < nchunks) issue(ci + 2, buf);
        cp_commit();
    }

    const bool relu = (flags & FLAG_RELU) != 0;
    const bool accu = (flags & FLAG_ACC) != 0;
#pragma unroll
    for (int mt = 0; mt < 2; mt++) {
        int rbase = m0 + wm + mt * 16 + (lane >> 2);
#pragma unroll
        for (int nt = 0; nt < 8; nt++) {
            int c0 = n0 + wn + nt * 8 + (lane & 3) * 2;
#pragma unroll
            for (int half = 0; half < 2; half++) {
                int row = rbase + half * 8;
                if (row >= Mn) continue;
                float v0 = acc[mt][nt][half * 2 + 0];
                float v1 = acc[mt][nt][half * 2 + 1];
                if (c0 < scale_cols)     v0 *= scale;
                if (c0 + 1 < scale_cols) v1 *= scale;
                if (bias) { v0 += bias[c0]; v1 += bias[c0 + 1]; }
                if (relu) { v0 = fmaxf(v0, 0.f); v1 = fmaxf(v1, 0.f); }
                size_t o = (size_t)row * Nn + c0;
                if (accu) { C[o] += v0; C[o + 1] += v1; }
                else      { C[o] = v0;  C[o + 1] = v1; }
            }
        }
    }
}

// ---------------------------------------------------------------------------
// Batched logits MMA (K=64, one chunk): C[b][m][n] = A[b] @ B[b]^T
// ---------------------------------------------------------------------------
#define TCB_STR  72
#define SLOG_SMEM (4 * 128 * TCB_STR * 2)   // 73728 bytes

__global__ void __launch_bounds__(256)
slogits_kernel(const __nv_bfloat16* __restrict__ Ahi, const __nv_bfloat16* __restrict__ Alo,
               const __nv_bfloat16* __restrict__ Bhi, const __nv_bfloat16* __restrict__ Blo,
               float* __restrict__ C,
               size_t strideA, size_t strideB, size_t strideC, int ldc)
{
    extern __shared__ __nv_bfloat16 smb[];
    __nv_bfloat16* sAh = smb;
    __nv_bfloat16* sAl = smb + 128 * TCB_STR;
    __nv_bfloat16* sBh = smb + 2 * 128 * TCB_STR;
    __nv_bfloat16* sBl = smb + 3 * 128 * TCB_STR;

    const int t = threadIdx.x, lane = t & 31, wid = t >> 5;
    const int m0 = blockIdx.y * 128, n0 = blockIdx.x * 128;
    const int b = blockIdx.z;
    const __nv_bfloat16* Ah = Ahi + (size_t)b * strideA;
    const __nv_bfloat16* Al = Alo + (size_t)b * strideA;
    const __nv_bfloat16* Bh = Bhi + (size_t)b * strideB;
    const __nv_bfloat16* Bl = Blo + (size_t)b * strideB;
    float* Cb = C + (size_t)b * strideC;

    const int wm = (wid & 3) * 32;
    const int wn = (wid >> 2) * 64;

    const uint32_t sAh_u = smem_u32(sAh), sAl_u = smem_u32(sAl);
    const uint32_t sBh_u = smem_u32(sBh), sBl_u = smem_u32(sBl);

    const int a_row = (lane & 7) + ((lane >> 3) & 1) * 8;
    const int a_col = (lane >> 4) * 8;
    const int b_row = lane & 7;
    const int b_col = ((lane >> 3) & 1) * 8;

    float acc[2][8][4];
#pragma unroll
    for (int i = 0; i < 2; i++)
#pragma unroll
        for (int j = 0; j < 8; j++)
#pragma unroll
            for (int k = 0; k < 4; k++) acc[i][j][k] = 0.f;

    for (int i = t; i < 1024; i += 256) {
        int r = i >> 3, kg = (i & 7) << 3;
        int off = r * TCB_STR + kg;
        size_t ga = (size_t)(m0 + r) * DH + kg;
        size_t gb = (size_t)(n0 + r) * DH + kg;
        *reinterpret_cast<uint4*>(sAh + off) = *reinterpret_cast<const uint4*>(Ah + ga);
        *reinterpret_cast<uint4*>(sAl + off) = *reinterpret_cast<const uint4*>(Al + ga);
        *reinterpret_cast<uint4*>(sBh + off) = *reinterpret_cast<const uint4*>(Bh + gb);
        *reinterpret_cast<uint4*>(sBl + off) = *reinterpret_cast<const uint4*>(Bl + gb);
    }
    __syncthreads();
#pragma unroll
    for (int ks = 0; ks < 4; ks++) {
        const int kl = ks * 16;
        uint32_t ah[2][4], al[2][4];
#pragma unroll
        for (int mt = 0; mt < 2; mt++) {
            uint32_t off = (uint32_t)((wm + mt * 16 + a_row) * TCB_STR + kl + a_col) * 2;
            ldsm_x4(ah[mt], sAh_u + off);
            ldsm_x4(al[mt], sAl_u + off);
        }
#pragma unroll
        for (int ng = 0; ng < 2; ng++) {
            uint32_t bh[4][2], bl[4][2];
#pragma unroll
            for (int nt = 0; nt < 4; nt++) {
                uint32_t off = (uint32_t)((wn + ng * 32 + nt * 8 + b_row) * TCB_STR + kl + b_col) * 2;
                ldsm_x2(bh[nt], sBh_u + off);
                ldsm_x2(bl[nt], sBl_u + off);
            }
#pragma unroll
            for (int mt = 0; mt < 2; mt++)
#pragma unroll
                for (int nt = 0; nt < 4; nt++) {
                    float* d = acc[mt][nt + ng * 4];
                    mma_bf16(d, ah[mt], bh[nt]);
                    mma_bf16(d, ah[mt], bl[nt]);
                    mma_bf16(d, al[mt], bh[nt]);
                }
        }
    }

#pragma unroll
    for (int mt = 0; mt < 2; mt++) {
        int rbase = m0 + wm + mt * 16 + (lane >> 2);
#pragma unroll
        for (int nt = 0; nt < 8; nt++) {
            int c0 = n0 + wn + nt * 8 + (lane & 3) * 2;
#pragma unroll
            for (int half = 0; half < 2; half++) {
                int row = rbase + half * 8;
                size_t o = (size_t)row * ldc + c0;
                Cb[o]     = acc[mt][nt][half * 2 + 0];
                Cb[o + 1] = acc[mt][nt][half * 2 + 1];
            }
        }
    }
}

// ---------------------------------------------------------------------------
// pgemm with cp.async double-buffered K-chunks of 32.
// C = P @ B; P hi/lo [M][K] row-major, B hi/lo [K][64] row-major
// (B via ldmatrix.trans). CTA 128x64; 8 warps (4m x 2n).
// mode 0: split-K partial -> PVP (uniform chunksPerSlice) ; mode 1: full-K -> O
// Per-buffer layout: Ph 128x40, Pl 128x40, Bh 32x72, Bl 32x72.
// ---------------------------------------------------------------------------
#define PGP_PSTR 40
#define PGP_BSTR 72
#define PGP_PL   (128 * PGP_PSTR)            // 5120
#define PGP_BH   (2 * 128 * PGP_PSTR)        // 10240
#define PGP_BL   (PGP_BH + 32 * PGP_BSTR)    // 12544
#define PGP_BUF  (PGP_BL + 32 * PGP_BSTR)    // 14848 elems
#define PG_SMEM  (2 * PGP_BUF * 2)           // 59392 bytes

__global__ void __launch_bounds__(256)
pgemm_kernel(const __nv_bfloat16* __restrict__ Phi, const __nv_bfloat16* __restrict__ Plo,
             const __nv_bfloat16* __restrict__ Bhi, const __nv_bfloat16* __restrict__ Blo,
             float* __restrict__ Cout,
             int Pld, size_t pHeadStride, size_t bHeadStride,
             int chunksPerSlice, int mode)
{
    extern __shared__ __nv_bfloat16 smb[];
    const int t = threadIdx.x, lane = t & 31, wid = t >> 5;
    const int m0 = blockIdx.x * 128;
    const int kslice = blockIdx.y;
    const int head = blockIdx.z;

    const int c0 = kslice * chunksPerSlice;
    const int nch = chunksPerSlice;

    const __nv_bfloat16* Ph = Phi + (size_t)head * pHeadStride;
    const __nv_bfloat16* Pl = Plo + (size_t)head * pHeadStride;
    const __nv_bfloat16* Bh = Bhi + (size_t)head * bHeadStride;
    const __nv_bfloat16* Bl = Blo + (size_t)head * bHeadStride;

    const int wm = (wid & 3) * 32;
    const int wn = (wid >> 2) * 32;

    const uint32_t smem_base = smem_u32(smb);

    const int a_row = (lane & 7) + ((lane >> 3) & 1) * 8;
    const int a_col = (lane >> 4) * 8;
    const int bt_k = lane & 15;

    // loader slots: P: r=t>>2 in [0,64) and +64, kg=(t&3)<<3 in {0,8,16,24}
    //               B: r=t>>3 in [0,32), cg=(t&7)<<3 in {0..56}
    const int pr = t >> 2, pkg = (t & 3) << 3;
    const int br = t >> 3, bcg = (t & 7) << 3;

    auto issue = [&](int ci, int buf) {
        int k0 = ci << 5;
        uint32_t bb = smem_base + (uint32_t)buf * PGP_BUF * 2;
        // P hi/lo (rows pr and pr+64)
        cp_async16(bb + (uint32_t)(pr * PGP_PSTR + pkg) * 2,
                   Ph + (size_t)(m0 + pr) * Pld + k0 + pkg);
        cp_async16(bb + (uint32_t)((pr + 64) * PGP_PSTR + pkg) * 2,
                   Ph + (size_t)(m0 + pr + 64) * Pld + k0 + pkg);
        uint32_t pl = bb + PGP_PL * 2;
        cp_async16(pl + (uint32_t)(pr * PGP_PSTR + pkg) * 2,
                   Pl + (size_t)(m0 + pr) * Pld + k0 + pkg);
        cp_async16(pl + (uint32_t)((pr + 64) * PGP_PSTR + pkg) * 2,
                   Pl + (size_t)(m0 + pr + 64) * Pld + k0 + pkg);
        // B hi/lo (32 k-rows x 64 cols)
        uint32_t bhh = bb + PGP_BH * 2;
        uint32_t bll = bb + PGP_BL * 2;
        cp_async16(bhh + (uint32_t)(br * PGP_BSTR + bcg) * 2,
                   Bh + (size_t)(k0 + br) * 64 + bcg);
        cp_async16(bll + (uint32_t)(br * PGP_BSTR + bcg) * 2,
                   Bl + (size_t)(k0 + br) * 64 + bcg);
    };

    float acc[2][4][4];
#pragma unroll
    for (int i = 0; i < 2; i++)
#pragma unroll
        for (int j = 0; j < 4; j++)
#pragma unroll
            for (int k = 0; k < 4; k++) acc[i][j][k] = 0.f;

    issue(c0, 0); cp_commit();
    if (nch > 1) issue(c0 + 1, 1);
    cp_commit();

    for (int ci = 0; ci < nch; ci++) {
        cp_wait1();
        __syncthreads();
        const int buf = ci & 1;
        uint32_t bb = smem_base + (uint32_t)buf * PGP_BUF * 2;
        uint32_t sPh_u = bb;
        uint32_t sPl_u = bb + PGP_PL * 2;
        uint32_t sBh_u = bb + PGP_BH * 2;
        uint32_t sBl_u = bb + PGP_BL * 2;
#pragma unroll
        for (int ks = 0; ks < 2; ks++) {
            const int kl = ks * 16;
            uint32_t ph[2][4], pl2[2][4];
#pragma unroll
            for (int mt = 0; mt < 2; mt++) {
                uint32_t off = (uint32_t)((wm + mt * 16 + a_row) * PGP_PSTR + kl + a_col) * 2;
                ldsm_x4(ph[mt], sPh_u + off);
                ldsm_x4(pl2[mt], sPl_u + off);
            }
            uint32_t bh[4][2], bl[4][2];
#pragma unroll
            for (int nt = 0; nt < 4; nt++) {
                uint32_t off = (uint32_t)((kl + bt_k) * PGP_BSTR + wn + nt * 8) * 2;
                ldsm_x2_trans(bh[nt], sBh_u + off);
                ldsm_x2_trans(bl[nt], sBl_u + off);
            }
#pragma unroll
            for (int mt = 0; mt < 2; mt++)
#pragma unroll
                for (int nt = 0; nt < 4; nt++) {
                    float* d = acc[mt][nt];
                    mma_bf16(d, ph[mt], bh[nt]);
                    mma_bf16(d, ph[mt], bl[nt]);
                    mma_bf16(d, pl2[mt], bh[nt]);
                }
        }
        __syncthreads();
        if (ci + 2 < nch) issue(c0 + ci + 2, buf);
        cp_commit();
    }

#pragma unroll
    for (int mt = 0; mt < 2; mt++) {
        int rbase = m0 + wm + mt * 16 + (lane >> 2);
#pragma unroll
        for (int nt = 0; nt < 4; nt++) {
            int c0c = wn + nt * 8 + (lane & 3) * 2;
#pragma unroll
            for (int half = 0; half < 2; half++) {
                int row = rbase + half * 8;
                float v0 = acc[mt][nt][half * 2 + 0];
                float v1 = acc[mt][nt][half * 2 + 1];
                if (mode == 0) {
                    size_t o = (((size_t)kslice * NHEADS + head) * MLAND + row) * 64 + c0c;
                    Cout[o] = v0; Cout[o + 1] = v1;
                } else {
                    size_t o = (size_t)row * DMODEL + head * 64 + c0c;
                    Cout[o] = v0; Cout[o + 1] = v1;
                }
            }
        }
    }
}

// ---------------------------------------------------------------------------
// split-K reduction: A3V = sum over 8 slices
// ---------------------------------------------------------------------------
__global__ void pvred_kernel(const float* __restrict__ PVP, float* __restrict__ A3V)
{
    int h = blockIdx.x & 7, seg = blockIdx.x >> 3;
    int idx = seg * 2048 + threadIdx.x * 8;
    for (int j = 0; j < 8; j++) {
        int li = idx + j;
        float s = 0.f;
#pragma unroll
        for (int sl = 0; sl < 8; sl++)
            s += PVP[(((size_t)sl * NHEADS + h) * MLAND * 64) + li];
        A3V[(size_t)h * MLAND * 64 + li] = s;
    }
}

// ---------------------------------------------------------------------------
// p3 softmax: S3 [h][m][NP] -> normalized P hi/lo (block per row)
// ---------------------------------------------------------------------------
__global__ void p3_kernel(const float* __restrict__ S,
                          __nv_bfloat16* __restrict__ PH, __nv_bfloat16* __restrict__ PL)
{
    int m = blockIdx.x, h = blockIdx.y;
    int t = threadIdx.x;
    const float* row = S + ((size_t)h * MLAND + m) * NP;
    float vals[33];
    float mx = -1e30f;
#pragma unroll
    for (int i = 0; i < 33; i++) {
        vals[i] = row[i * 256 + t];
        mx = fmaxf(mx, vals[i]);
    }
    __shared__ float red[256];
    red[t] = mx; __syncthreads();
    for (int o = 128; o > 0; o >>= 1) {
        if (t < o) red[t] = fmaxf(red[t], red[t + o]);
        __syncthreads();
    }
    mx = red[0]; __syncthreads();
    float sum = 0.f;
#pragma unroll
    for (int i = 0; i < 33; i++) {
        vals[i] = __expf(vals[i] - mx);
        sum += vals[i];
    }
    red[t] = sum; __syncthreads();
    for (int o = 128; o > 0; o >>= 1) {
        if (t < o) red[t] += red[t + o];
        __syncthreads();
    }
    float inv = 1.0f / red[0];
    __nv_bfloat16* ph = PH + ((size_t)h * MLAND + m) * NP;
    __nv_bfloat16* pl = PL + ((size_t)h * MLAND + m) * NP;
#pragma unroll
    for (int i = 0; i < 33; i++) {
        float p = vals[i] * inv;
        __nv_bfloat16 hi = __float2bfloat16(p);
        ph[i * 256 + t] = hi;
        pl[i * 256 + t] = __float2bfloat16(p - __bfloat162float(hi));
    }
}

// ---------------------------------------------------------------------------
// p1 softmax: S1 [h][n][256] -> normalized P hi/lo (warp per row)
// ---------------------------------------------------------------------------
__global__ void p1_kernel(const float* __restrict__ S,
                          __nv_bfloat16* __restrict__ PH, __nv_bfloat16* __restrict__ PL)
{
    int row = blockIdx.x * 8 + (threadIdx.x >> 5);
    int lane = threadIdx.x & 31;
    const float* r = S + (size_t)row * MLAND;
    float a[8];
#pragma unroll
    for (int k = 0; k < 8; k++) a[k] = r[lane + k * 32];
    float m = a[0];
#pragma unroll
    for (int k = 1; k < 8; k++) m = fmaxf(m, a[k]);
    for (int o = 16; o > 0; o >>= 1) m = fmaxf(m, __shfl_xor_sync(0xffffffffu, m, o));
    float s = 0.f;
#pragma unroll
    for (int k = 0; k < 8; k++) { a[k] = __expf(a[k] - m); s += a[k]; }
    for (int o = 16; o > 0; o >>= 1) s += __shfl_xor_sync(0xffffffffu, s, o);
    float inv = 1.0f / s;
    __nv_bfloat16* ph = PH + (size_t)row * MLAND;
    __nv_bfloat16* pl = PL + (size_t)row * MLAND;
#pragma unroll
    for (int k = 0; k < 8; k++) {
        float p = a[k] * inv;
        __nv_bfloat16 hi = __float2bfloat16(p);
        ph[lane + k * 32] = hi;
        pl[lane + k * 32] = __float2bfloat16(p - __bfloat162float(hi));
    }
}

// ---------------------------------------------------------------------------
// Assemble h rows: cls + wrap
// ---------------------------------------------------------------------------
__global__ void assemble_kernel(const float* __restrict__ cls, float* __restrict__ H)
{
    int j = blockIdx.x;
    int c = threadIdx.x;
    if (j == 0) H[c] = cls[c];
    else        H[(size_t)(NTOK + j) * DMODEL + c] = H[(size_t)j * DMODEL + c];
}

// ---------------------------------------------------------------------------
// Landmarks: means of 33-groups; f32 QL/KL + bf16 hi/lo copies
// ---------------------------------------------------------------------------
__global__ void landmarks_kernel(const float* __restrict__ QKV,
                                 float* __restrict__ QL, float* __restrict__ KL,
                                 __nv_bfloat16* __restrict__ QLH, __nv_bfloat16* __restrict__ QLL,
                                 __nv_bfloat16* __restrict__ KLH, __nv_bfloat16* __restrict__ KLL)
{
    int hm = blockIdx.x;
    int h = hm >> 8, m = hm & 255;
    int tid = threadIdx.x;
    int d = tid & 63;
    int off = (tid < 64) ? 0 : DMODEL;
    size_t base = (size_t)(m * LWIN) * (3 * DMODEL) + off + h * DH + d;
    float s = 0.f;
#pragma unroll
    for (int j = 0; j < LWIN; j++) s += QKV[base + (size_t)j * (3 * DMODEL)];
    s *= (1.0f / LWIN);
    __nv_bfloat16 hi = __float2bfloat16(s);
    __nv_bfloat16 lo = __float2bfloat16(s - __bfloat162float(hi));
    size_t o = (size_t)(h * MLAND + m) * DH + d;
    if (tid < 64) {
        QL[o] = s; QLH[o] = hi; QLL[o] = lo;
    } else {
        KL[o] = s; KLH[o] = hi; KLL[o] = lo;
    }
}

// ---------------------------------------------------------------------------
// a2 = softmax(q_l @ k_l^T)
// ---------------------------------------------------------------------------
__global__ void a2_kernel(const float* __restrict__ QL, const float* __restrict__ KL,
                          float* __restrict__ A2)
{
    int m = blockIdx.x, h = blockIdx.y;
    int tid = threadIdx.x;
    __shared__ float q[64];
    __shared__ float red[256];
    if (tid < 64) q[tid] = QL[(size_t)(h * MLAND + m) * DH + tid];
    __syncthreads();
    const float* kr = KL + (size_t)(h * MLAND + tid) * DH;
    float s = 0.f;
#pragma unroll
    for (int i = 0; i < 16; i++) {
        float4 kv = reinterpret_cast<const float4*>(kr)[i];
        float4 qv = reinterpret_cast<const float4*>(q)[i];
        s += kv.x * qv.x + kv.y * qv.y + kv.z * qv.z + kv.w * qv.w;
    }
    red[tid] = s; __syncthreads();
    for (int o = 128; o > 0; o >>= 1) {
        if (tid < o) red[tid] = fmaxf(red[tid], red[tid + o]);
        __syncthreads();
    }
    float mx = red[0]; __syncthreads();
    float e = __expf(s - mx);
    red[tid] = e; __syncthreads();
    for (int o = 128; o > 0; o >>= 1) {
        if (tid < o) red[tid] += red[tid + o];
        __syncthreads();
    }
    float sm = red[0];
    A2[(size_t)(h * MLAND + m) * MLAND + tid] = e / sm;
}

// ---------------------------------------------------------------------------
// pinv chain
// ---------------------------------------------------------------------------
__global__ void pinv_scale_kernel(const float* __restrict__ A2, float* __restrict__ PS)
{
    int h = blockIdx.x;
    int t = threadIdx.x;
    int w = t >> 5, lane = t & 31;
    const float* Ah = A2 + (size_t)h * 65536;
    __shared__ float rs[256];
    __shared__ float cs2[256];
    for (int r = w; r < 256; r += 8) {
        float s = 0.f;
        for (int j = lane; j < 256; j += 32) s += fabsf(Ah[r * 256 + j]);
        for (int o = 16; o > 0; o >>= 1) s += __shfl_xor_sync(0xffffffffu, s, o);
        if (lane == 0) rs[r] = s;
    }
    float cs = 0.f;
    for (int i = 0; i < 256; i++) cs += fabsf(Ah[i * 256 + t]);
    cs2[t] = cs;
    __syncthreads();
    for (int o = 128; o > 0; o >>= 1) {
        if (t < o) { rs[t] = fmaxf(rs[t], rs[t + o]); cs2[t] = fmaxf(cs2[t], cs2[t + o]); }
        __syncthreads();
    }
    if (t == 0) PS[h] = 1.0f / (rs[0] * cs2[0]);
}

__global__ void pinv_tr_kernel(const float* __restrict__ A2, const float* __restrict__ PS,
                               float* __restrict__ Z0)
{
    __shared__ float tl[64][65];
    int h = blockIdx.y;
    int seg = blockIdx.x;
    int bi = (seg >> 2) * 64, bj = (seg & 3) * 64;
    int t = threadIdx.x;
    float inv = PS[h];
    const float* Ah = A2 + (size_t)h * 65536;
    float* Zh = Z0 + (size_t)h * 65536;
    for (int lin = t; lin < 4096; lin += 256) {
        int r = lin >> 6, c = lin & 63;
        tl[r][c] = Ah[(size_t)(bi + r) * 256 + bj + c];
    }
    __syncthreads();
    for (int lin = t; lin < 4096; lin += 256) {
        int r = lin >> 6, c = lin & 63;
        Zh[(size_t)(bj + r) * 256 + bi + c] = tl[c][r] * inv;
    }
}

__global__ void nk256_kernel(const float* __restrict__ A, const float* __restrict__ B,
                             float* __restrict__ C, float alpha, float gamma)
{
    const float* Ah = A + (size_t)blockIdx.z * 65536;
    const float* Bh = B + (size_t)blockIdx.z * 65536;
    float* Ch = C + (size_t)blockIdx.z * 65536;
    __shared__ float As[16][64];
    __shared__ float Bs[16][64];
    const int bm = blockIdx.y * 64;
    const int bn = blockIdx.x * 64;
    const int tid = threadIdx.x;
    const int tx = tid & 15, ty = tid >> 4;
    const int row0 = ty * 4, col0 = tx * 4;
    float acc[4][4];
#pragma unroll
    for (int i = 0; i < 4; i++)
#pragma unroll
        for (int j = 0; j < 4; j++) acc[i][j] = 0.f;

    for (int k0 = 0; k0 < 256; k0 += 16) {
        {
            int ar = tid >> 2;
            int ac = (tid & 3) << 2;
            float4 v = *reinterpret_cast<const float4*>(Ah + (size_t)(bm + ar) * 256 + k0 + ac);
            As[ac + 0][ar] = v.x; As[ac + 1][ar] = v.y;
            As[ac + 2][ar] = v.z; As[ac + 3][ar] = v.w;
        }
        {
            int br = tid >> 4;
            int bc = (tid & 15) << 2;
            float4 v = *reinterpret_cast<const float4*>(Bh + (size_t)(k0 + br) * 256 + bn + bc);
            *reinterpret_cast<float4*>(&Bs[br][bc]) = v;
        }
        __syncthreads();
#pragma unroll
        for (int k = 0; k < 16; k++) {
            float a[4], b[4];
            *reinterpret_cast<float4*>(a) = *reinterpret_cast<const float4*>(&As[k][row0]);
            *reinterpret_cast<float4*>(b) = *reinterpret_cast<const float4*>(&Bs[k][col0]);
#pragma unroll
            for (int i = 0; i < 4; i++)
#pragma unroll
                for (int j = 0; j < 4; j++) acc[i][j] += a[i] * b[j];
        }
        __syncthreads();
    }
#pragma unroll
    for (int i = 0; i < 4; i++)
#pragma unroll
        for (int j = 0; j < 4; j++) {
            size_t o = (size_t)(bm + row0 + i) * 256 + bn + col0 + j;
            Ch[o] = alpha * acc[i][j] + gamma * Ah[o];
        }
}

// ---------------------------------------------------------------------------
// Bm = pinv(a2) @ a3v  -> bf16 hi/lo
// ---------------------------------------------------------------------------
__global__ void bmat_kernel(const float* __restrict__ Z, const float* __restrict__ A3V,
                            __nv_bfloat16* __restrict__ BmH, __nv_bfloat16* __restrict__ BmL)
{
    int h = blockIdx.y;
    int m0 = blockIdx.x * 4;
    __shared__ float zs[4][256];
    int tid = threadIdx.x;
    int r = tid >> 6, d = tid & 63;
    for (int lin = tid; lin < 1024; lin += 256) {
        int rr = lin >> 8, k = lin & 255;
        zs[rr][k] = Z[(size_t)h * 65536 + (size_t)(m0 + rr) * 256 + k];
    }
    __syncthreads();
    float acc = 0.f;
    for (int k = 0; k < 256; k++)
        acc += zs[r][k] * A3V[(size_t)(h * MLAND + k) * DH + d];
    size_t o = (size_t)(h * MLAND + m0 + r) * DH + d;
    __nv_bfloat16 hi = __float2bfloat16(acc);
    BmH[o] = hi;
    BmL[o] = __float2bfloat16(acc - __bfloat162float(hi));
}

// ---------------------------------------------------------------------------
// Depthwise seq-conv (k=33) on v, tiled in smem; adds into O
// ---------------------------------------------------------------------------
__global__ void conv_tile_kernel(const float* __restrict__ QKV, const float* __restrict__ W,
                                 float* __restrict__ O)
{
    __shared__ float vs[160 * 64];
    __shared__ float ws[33];
    int h = blockIdx.y;
    int n0 = blockIdx.x * 128;
    int t = threadIdx.x;
    if (t < 33) ws[t] = W[h * LWIN + t];
    for (int lin = t; lin < 160 * 64; lin += 256) {
        int r = lin >> 6, c = lin & 63;
        int n = n0 + r - 16;
        vs[lin] = (n >= 0 && n < NP)
                    ? QKV[(size_t)n * (3 * DMODEL) + 2 * DMODEL + h * DH + c] : 0.f;
    }
    __syncthreads();
    int c = t & 63, rg = t >> 6;
    for (int q = 0; q < 32; q++) {
        int r = rg * 32 + q;
        float acc = 0.f;
#pragma unroll
        for (int k = 0; k < LWIN; k++) acc += ws[k] * vs[(r + k) * 64 + c];
        O[(size_t)(n0 + r) * DMODEL + h * DH + c] += acc;
    }
}

// ---------------------------------------------------------------------------
// PPEG tiled
// ---------------------------------------------------------------------------
#define PPEG_TILE (14 * 14 * 64)
#define PPEG_W7   PPEG_TILE
#define PPEG_W5   (PPEG_W7 + 64 * 49)
#define PPEG_W3   (PPEG_W5 + 64 * 25)
#define PPEG_TOT  (PPEG_W3 + 64 * 9)

__global__ void ppeg_tile_kernel(const float* __restrict__ Hin, float* __restrict__ Hout,
                                 const float* __restrict__ w7, const float* __restrict__ b7,
                                 const float* __restrict__ w5, const float* __restrict__ b5,
                                 const float* __restrict__ w3, const float* __restrict__ b3)
{
    extern __shared__ float sm[];
    float* tile = sm;
    float* ws7 = sm + PPEG_W7;
    float* ws5 = sm + PPEG_W5;
    float* ws3 = sm + PPEG_W3;

    int ti = blockIdx.x;
    int ty0 = (ti / 12) * 8, tx0 = (ti % 12) * 8;
    int cg = blockIdx.y * 64;
    int t = threadIdx.x;

    for (int lin = t; lin < PPEG_TILE; lin += 256) {
        int p = lin >> 6, c = lin & 63;
        int gy = ty0 + p / 14 - 3;
        int gx = tx0 + p % 14 - 3;
        float v = 0.f;
        if ((unsigned)gy < (unsigned)HSQ && (unsigned)gx < (unsigned)HSQ)
            v = Hin[(size_t)(1 + gy * HSQ + gx) * DMODEL + cg + c];
        tile[lin] = v;
    }
    for (int lin = t; lin < 64 * 49; lin += 256) ws7[lin] = w7[(size_t)cg * 49 + lin];
    for (int lin = t; lin < 64 * 25; lin += 256) ws5[lin] = w5[(size_t)cg * 25 + lin];
    for (int lin = t; lin < 64 * 9;  lin += 256) ws3[lin] = w3[(size_t)cg * 9 + lin];
    __syncthreads();

    int c = t & 63, pg = t >> 6;
    float bsum = b7[cg + c] + b5[cg + c] + b3[cg + c];
    for (int q = 0; q < 16; q++) {
        int p = pg * 16 + q;
        int oy = p >> 3, ox = p & 7;
        int gy = ty0 + oy, gx = tx0 + ox;
        if (gy >= HSQ || gx >= HSQ) continue;
        float acc = tile[((oy + 3) * 14 + ox + 3) * 64 + c] + bsum;
#pragma unroll
        for (int a = 0; a < 7; a++)
#pragma unroll
            for (int bq = 0; bq < 7; bq++)
                acc += ws7[c * 49 + a * 7 + bq] * tile[((oy + a) * 14 + ox + bq) * 64 + c];
#pragma unroll
        for (int a = 0; a < 5; a++)
#pragma unroll
            for (int bq = 0; bq < 5; bq++)
                acc += ws5[c * 25 + a * 5 + bq] * tile[((oy + a + 1) * 14 + ox + bq + 1) * 64 + c];
#pragma unroll
        for (int a = 0; a < 3; a++)
#pragma unroll
            for (int bq = 0; bq < 3; bq++)
                acc += ws3[c * 9 + a * 3 + bq] * tile[((oy + a + 2) * 14 + ox + bq + 2) * 64 + c];
        Hout[(size_t)(1 + gy * HSQ + gx) * DMODEL + cg + c] = acc;
    }
}

__global__ void copy_row0_kernel(const float* __restrict__ Hin, float* __restrict__ Hout)
{
    Hout[threadIdx.x] = Hin[threadIdx.x];
}

// ---------------------------------------------------------------------------
// Final head
// ---------------------------------------------------------------------------
__global__ void final_kernel(const float* __restrict__ H, const float* __restrict__ g,
                             const float* __restrict__ b, const float* __restrict__ w,
                             const float* __restrict__ bias2, float* __restrict__ out,
                             int out_size)
{
    int c = threadIdx.x;
    __shared__ float s1[512], s2[512];
    float x = H[c];
    s1[c] = x; s2[c] = x * x;
    __syncthreads();
    for (int o = 256; o > 0; o >>= 1) {
        if (c < o) { s1[c] += s1[c + o]; s2[c] += s2[c + o]; }
        __syncthreads();
    }
    float mean = s1[0] * (1.f / DMODEL);
    float var  = s2[0] * (1.f / DMODEL) - mean * mean;
    float e = (x - mean) * rsqrtf(var + EPSLN) * g[c] + b[c];
    __syncthreads();
    s1[c] = e * w[c * 2 + 0];
    s2[c] = e * w[c * 2 + 1];
    __syncthreads();
    for (int o = 256; o > 0; o >>= 1) {
        if (c < o) { s1[c] += s1[c + o]; s2[c] += s2[c + o]; }
        __syncthreads();
    }
    float l0 = s1[0] + bias2[0];
    float l1 = s2[0] + bias2[1];
    if (c == 0) {
        float m = fmaxf(l0, l1);
        float e0 = expf(l0 - m), e1 = expf(l1 - m);
        float ss = e0 + e1;
        if (out_size > 0) out[0] = l0;
        if (out_size > 1) out[1] = l1;
        if (out_size > 2) out[2] = e0 / ss;
        if (out_size > 3) out[3] = e1 / ss;
        if (out_size > 4) out[4] = (l1 > l0) ? 1.0f : 0.0f;
    }
    if (5 + c < out_size) out[5 + c] = e;
}

// ---------------------------------------------------------------------------
// Host orchestration
// ---------------------------------------------------------------------------
static float* symaddr(const void* sym)
{
    void* p = nullptr;
    cudaGetSymbolAddress(&p, sym);
    return (float*)p;
}
static __nv_bfloat16* symaddr_bf(const void* sym)
{
    void* p = nullptr;
    cudaGetSymbolAddress(&p, sym);
    return (__nv_bfloat16*)p;
}

static cudaStream_t g_side = nullptr;
static cudaEvent_t  g_evf  = nullptr;
static cudaEvent_t  g_evj  = nullptr;

extern "C" void kernel_launch(void* const* d_in, const int* in_sizes, int n_in,
                              void* d_out, int out_size)
{
    if (!g_side) {
        cudaStreamCreateWithFlags(&g_side, cudaStreamNonBlocking);
        cudaEventCreateWithFlags(&g_evf, cudaEventDisableTiming);
        cudaEventCreateWithFlags(&g_evj, cudaEventDisableTiming);
    }

    const float* x       = (const float*)d_in[0];
    const float* fc1_w   = (const float*)d_in[1];
    const float* fc1_b   = (const float*)d_in[2];
    const float* cls     = (const float*)d_in[3];
    const float* ln1_g   = (const float*)d_in[4];
    const float* ln1_b   = (const float*)d_in[5];
    const float* qkv1_w  = (const float*)d_in[6];
    const float* out1_w  = (const float*)d_in[7];
    const float* out1_b  = (const float*)d_in[8];
    const float* conv1_w = (const float*)d_in[9];
    const float* ln2_g   = (const float*)d_in[10];
    const float* ln2_b   = (const float*)d_in[11];
    const float* qkv2_w  = (const float*)d_in[12];
    const float* out2_w  = (const float*)d_in[13];
    const float* out2_b  = (const float*)d_in[14];
    const float* conv2_w = (const float*)d_in[15];
    const float* pg7_w   = (const float*)d_in[16];
    const float* pg7_b   = (const float*)d_in[17];
    const float* pg5_w   = (const float*)d_in[18];
    const float* pg5_b   = (const float*)d_in[19];
    const float* pg3_w   = (const float*)d_in[20];
    const float* pg3_b   = (const float*)d_in[21];
    const float* norm_g  = (const float*)d_in[22];
    const float* norm_b  = (const float*)d_in[23];
    const float* fc2_w   = (const float*)d_in[24];
    const float* fc2_b   = (const float*)d_in[25];

    float* H   = symaddr(g_H);
    float* H2  = symaddr(g_H2);
    float* QKV = symaddr(g_QKV);
    float* QL  = symaddr(g_QL);
    float* KL  = symaddr(g_KL);
    float* A2  = symaddr(g_A2);
    float* Z0  = symaddr(g_Z0);
    float* Z1  = symaddr(g_Z1);
    float* W1  = symaddr(g_W1);
    float* W2  = symaddr(g_W2);
    float* W3  = symaddr(g_W3);
    float* PS  = symaddr(g_PS);
    float* A3V = symaddr(g_A3V);
    float* O   = symaddr(g_O);
    float* S   = symaddr(g_S);
    float* PVP = symaddr(g_PVP);
    __nv_bfloat16* AH  = symaddr_bf(g_AH);
    __nv_bfloat16* AL  = symaddr_bf(g_AL);
    __nv_bfloat16* WH  = symaddr_bf(g_WH);
    __nv_bfloat16* WL  = symaddr_bf(g_WL);
    __nv_bfloat16* QLH = symaddr_bf(g_QLH);
    __nv_bfloat16* QLL = symaddr_bf(g_QLL);
    __nv_bfloat16* KLH = symaddr_bf(g_KLH);
    __nv_bfloat16* KLL = symaddr_bf(g_KLL);
    __nv_bfloat16* VH  = symaddr_bf(g_VH);
    __nv_bfloat16* VL  = symaddr_bf(g_VL);
    __nv_bfloat16* PH  = symaddr_bf(g_PH);
    __nv_bfloat16* PL  = symaddr_bf(g_PL);
    __nv_bfloat16* BmH = symaddr_bf(g_BmH);
    __nv_bfloat16* BmL = symaddr_bf(g_BmL);

    const int PPEG_SMEM = PPEG_TOT * 4;
    cudaFuncSetAttribute(ppeg_tile_kernel, cudaFuncAttributeMaxDynamicSharedMemorySize, PPEG_SMEM);
    cudaFuncSetAttribute(tc_gemm_kernel,  cudaFuncAttributeMaxDynamicSharedMemorySize, TCG_SMEM);
    cudaFuncSetAttribute(slogits_kernel,  cudaFuncAttributeMaxDynamicSharedMemorySize, SLOG_SMEM);
    cudaFuncSetAttribute(pgemm_kernel,    cudaFuncAttributeMaxDynamicSharedMemorySize, PG_SMEM);

    // ---- fc1 + relu via tensor cores ----
    wconv_kernel<<<dim3(DMODEL / 32, INDIM / 32), 256>>>(fc1_w, WH, WL, INDIM, DMODEL);
    aconv_kernel<<<NTOK, 128>>>(x, AH, AL, NTOK, INDIM);
    tc_gemm_kernel<<<dim3(DMODEL / 128, NTOK / 128), 256, TCG_SMEM>>>(
        AH, AL, WH, WL, H + DMODEL, fc1_b, NTOK, DMODEL, INDIM, FLAG_RELU, 0, 1.f);
    assemble_kernel<<<NWRAP + 1, DMODEL>>>(cls, H);

    auto attn = [&](float* Hbuf, const float* lng, const float* lnb, const float* qkvw,
                    const float* outw, const float* outb, const float* convw) {
        // fused LN + hi/lo conversion straight into AH/AL
        lnconv_kernel<<<NP, 256>>>(Hbuf, AH, AL, lng, lnb);
        wconv_kernel<<<dim3(3 * DMODEL / 32, DMODEL / 32), 256>>>(qkvw, WH, WL, DMODEL, 3 * DMODEL);
        tc_gemm_kernel<<<dim3(3 * DMODEL / 128, NP / 128), 256, TCG_SMEM>>>(
            AH, AL, WH, WL, QKV, nullptr, NP, 3 * DMODEL, DMODEL, 0, DMODEL, 0.125f);
        qk_split_kernel<<<NP, 256>>>(QKV, AH, AL, VH, VL);
        landmarks_kernel<<<NHEADS * MLAND, 128>>>(QKV, QL, KL, QLH, QLL, KLH, KLL);
        a2_kernel<<<dim3(MLAND, NHEADS), 256>>>(QL, KL, A2);

        // fork: pinv chain on side stream
        cudaEventRecord(g_evf, 0);
        cudaStreamWaitEvent(g_side, g_evf, 0);
        pinv_scale_kernel<<<NHEADS, 256, 0, g_side>>>(A2, PS);
        pinv_tr_kernel<<<dim3(16, NHEADS), 256, 0, g_side>>>(A2, PS, Z0);
        float* zi = Z0;
        float* zo = Z1;
        for (int it = 0; it < 6; it++) {
            nk256_kernel<<<dim3(4, 4, NHEADS), 256, 0, g_side>>>(A2, zi, W1, 1.f, 0.f);
            nk256_kernel<<<dim3(4, 4, NHEADS), 256, 0, g_side>>>(W1, W1, W2, -1.f, 7.f);
            nk256_kernel<<<dim3(4, 4, NHEADS), 256, 0, g_side>>>(W1, W2, W3, -1.f, 15.f);
            nk256_kernel<<<dim3(4, 4, NHEADS), 256, 0, g_side>>>(zi, W3, zo, -0.25f, 3.25f);
            float* t = zi; zi = zo; zo = t;
        }
        cudaEventRecord(g_evj, g_side);

        // S3 = QL @ K^T -> softmax -> A3V = P3 @ V (split-K MMA, 33 k32-chunks/slice)
        slogits_kernel<<<dim3(NP / 128, MLAND / 128, NHEADS), 256, SLOG_SMEM>>>(
            QLH, QLL, AH + QKOFF, AL + QKOFF, S,
            (size_t)MLAND * DH, (size_t)NP * DH, (size_t)MLAND * NP, NP);
        p3_kernel<<<dim3(MLAND, NHEADS), 256>>>(S, PH, PL);
        pgemm_kernel<<<dim3(MLAND / 128, 8, NHEADS), 256, PG_SMEM>>>(
            PH, PL, VH, VL, PVP, NP, (size_t)MLAND * NP, (size_t)NP * DH, 33, 0);
        pvred_kernel<<<64, 256>>>(PVP, A3V);

        // S1 = Q @ KL^T -> softmax
        slogits_kernel<<<dim3(MLAND / 128, NP / 128, NHEADS), 256, SLOG_SMEM>>>(
            AH, AL, KLH, KLL, S,
            (size_t)NP * DH, (size_t)MLAND * DH, (size_t)NP * MLAND, MLAND);
        p1_kernel<<<NP * NHEADS / 8, 256>>>(S, PH, PL);

        // join pinv; Bm; O = P1 @ Bm (8 k32-chunks); += conv
        cudaStreamWaitEvent(0, g_evj, 0);
        bmat_kernel<<<dim3(MLAND / 4, NHEADS), 256>>>(zi, A3V, BmH, BmL);
        pgemm_kernel<<<dim3(NP / 128, 1, NHEADS), 256, PG_SMEM>>>(
            PH, PL, BmH, BmL, O, MLAND, (size_t)NP * MLAND, (size_t)MLAND * DH, 8, 1);
        conv_tile_kernel<<<dim3(NP / 128, NHEADS), 256>>>(QKV, convw, O);

        // out projection (accumulate into Hbuf)
        wconv_kernel<<<dim3(DMODEL / 32, DMODEL / 32), 256>>>(outw, WH, WL, DMODEL, DMODEL);
        aconv_kernel<<<8320, 128>>>(O + (size_t)PADF * DMODEL, AH, AL, NHTOK, DMODEL);
        tc_gemm_kernel<<<dim3(DMODEL / 128, 65), 256, TCG_SMEM>>>(
            AH, AL, WH, WL, Hbuf, outb, NHTOK, DMODEL, DMODEL, FLAG_ACC, 0, 1.f);
    };

    attn(H, ln1_g, ln1_b, qkv1_w, out1_w, out1_b, conv1_w);

    ppeg_tile_kernel<<<dim3(144, NHEADS), 256, PPEG_SMEM>>>(
        H, H2, pg7_w, pg7_b, pg5_w, pg5_b, pg3_w, pg3_b);
    copy_row0_kernel<<<1, DMODEL>>>(H, H2);

    attn(H2, ln2_g, ln2_b, qkv2_w, out2_w, out2_b, conv2_w);

    final_kernel<<<1, DMODEL>>>(H2, norm_g, norm_b, fc2_w, fc2_b, (float*)d_out, out_size);
}

// round 14
// speedup vs baseline: 1.1767x; 1.0292x over previous
#include <cuda_runtime.h>
#include <cuda_bf16.h>
#include <math.h>
#include <stdint.h>

// ---------------------------------------------------------------------------
// Problem constants
// ---------------------------------------------------------------------------
#define NTOK   8192
#define INDIM  1024
#define DMODEL 512
#define NHEADS 8
#define DH     64
#define MLAND  256
#define LWIN   33
#define NP     8448          // padded attention length
#define NHTOK  8282          // tokens incl cls
#define PADF   166
#define HSQ    91
#define NFEAT  8281
#define NWRAP  89
#define EPSLN  1e-5f

#define FLAG_RELU  1
#define FLAG_ACC   2
#define FLAG_SPLIT 4

// ---------------------------------------------------------------------------
// Scratch (device globals)
// ---------------------------------------------------------------------------
__device__ float g_H  [NHTOK * DMODEL];
__device__ float g_H2 [NHTOK * DMODEL];
__device__ float g_QL [NHEADS * MLAND * DH];
__device__ float g_KL [NHEADS * MLAND * DH];
__device__ float g_A2 [NHEADS * MLAND * MLAND];
__device__ float g_Z0 [NHEADS * MLAND * MLAND];
__device__ float g_Z1 [NHEADS * MLAND * MLAND];
__device__ float g_W1 [NHEADS * MLAND * MLAND];
__device__ float g_W2 [NHEADS * MLAND * MLAND];
__device__ float g_W3 [NHEADS * MLAND * MLAND];
__device__ float g_PS [NHEADS];
__device__ float g_A3V[NHEADS * MLAND * DH];
__device__ float g_O  [NP * DMODEL];
__device__ float g_S  [NHEADS * NP * MLAND];     // logits scratch (S3 then S1)
__device__ float g_PVP[8 * NHEADS * MLAND * DH]; // split-K partials
// bf16 hi/lo staging
__device__ __nv_bfloat16 g_AH[NP * INDIM];       // LN output / out-proj staging
__device__ __nv_bfloat16 g_AL[NP * INDIM];
__device__ __nv_bfloat16 g_QKH[2 * NHEADS * NP * DH];  // Q then K, per-head hi
__device__ __nv_bfloat16 g_QKL[2 * NHEADS * NP * DH];  // Q then K, per-head lo
__device__ __nv_bfloat16 g_WH[3 * DMODEL * DMODEL];
__device__ __nv_bfloat16 g_WL[3 * DMODEL * DMODEL];
__device__ __nv_bfloat16 g_QLH[NHEADS * MLAND * DH];
__device__ __nv_bfloat16 g_QLL[NHEADS * MLAND * DH];
__device__ __nv_bfloat16 g_KLH[NHEADS * MLAND * DH];
__device__ __nv_bfloat16 g_KLL[NHEADS * MLAND * DH];
__device__ __nv_bfloat16 g_VH [NHEADS * NP * DH];
__device__ __nv_bfloat16 g_VL [NHEADS * NP * DH];
__device__ __nv_bfloat16 g_PH [NHEADS * NP * MLAND];
__device__ __nv_bfloat16 g_PL [NHEADS * NP * MLAND];
__device__ __nv_bfloat16 g_BmH[NHEADS * MLAND * DH];
__device__ __nv_bfloat16 g_BmL[NHEADS * MLAND * DH];

#define QKOFF (NHEADS * NP * DH)

// ---------------------------------------------------------------------------
// warp-mma helpers (sm_80+ PTX)
// ---------------------------------------------------------------------------
__device__ __forceinline__ uint32_t smem_u32(const void* p)
{
    uint32_t a;
    asm("{ .reg .u64 t; cvta.to.shared.u64 t, %1; cvt.u32.u64 %0, t; }" : "=r"(a) : "l"(p));
    return a;
}
__device__ __forceinline__ void ldsm_x4(uint32_t* r, uint32_t addr)
{
    asm volatile("ldmatrix.sync.aligned.m8n8.x4.shared.b16 {%0,%1,%2,%3}, [%4];"
                 : "=r"(r[0]), "=r"(r[1]), "=r"(r[2]), "=r"(r[3]) : "r"(addr));
}
__device__ __forceinline__ void ldsm_x2(uint32_t* r, uint32_t addr)
{
    asm volatile("ldmatrix.sync.aligned.m8n8.x2.shared.b16 {%0,%1}, [%2];"
                 : "=r"(r[0]), "=r"(r[1]) : "r"(addr));
}
__device__ __forceinline__ void ldsm_x2_trans(uint32_t* r, uint32_t addr)
{
    asm volatile("ldmatrix.sync.aligned.m8n8.x2.trans.shared.b16 {%0,%1}, [%2];"
                 : "=r"(r[0]), "=r"(r[1]) : "r"(addr));
}
__device__ __forceinline__ void mma_bf16(float* d, const uint32_t* a, const uint32_t* b)
{
    asm volatile("mma.sync.aligned.m16n8k16.row.col.f32.bf16.bf16.f32 "
                 "{%0,%1,%2,%3}, {%4,%5,%6,%7}, {%8,%9}, {%0,%1,%2,%3};"
                 : "+f"(d[0]), "+f"(d[1]), "+f"(d[2]), "+f"(d[3])
                 : "r"(a[0]), "r"(a[1]), "r"(a[2]), "r"(a[3]), "r"(b[0]), "r"(b[1]));
}
__device__ __forceinline__ void cp_async16(uint32_t smem_addr, const void* gptr)
{
    asm volatile("cp.async.ca.shared.global [%0], [%1], 16;"
                 :: "r"(smem_addr), "l"(gptr));
}
__device__ __forceinline__ void cp_commit()
{
    asm volatile("cp.async.commit_group;" ::: "memory");
}
__device__ __forceinline__ void cp_wait1()
{
    asm volatile("cp.async.wait_group 1;" ::: "memory");
}

// ---------------------------------------------------------------------------
// Weight convert+transpose: W [K][N] f32 -> Whi/Wlo [N][K] bf16
// ---------------------------------------------------------------------------
__global__ void wconv_kernel(const float* __restrict__ W,
                             __nv_bfloat16* __restrict__ Whi, __nv_bfloat16* __restrict__ Wlo,
                             int K, int N)
{
    __shared__ float tl[32][33];
    int kb = blockIdx.y * 32, nb = blockIdx.x * 32;
    int t = threadIdx.x;
    for (int i = t; i < 1024; i += 256) {
        int r = i >> 5, c = i & 31;
        tl[r][c] = W[(size_t)(kb + r) * N + nb + c];
    }
    __syncthreads();
    for (int i = t; i < 1024; i += 256) {
        int n = i >> 5, k = i & 31;
        float v = tl[k][n];
        __nv_bfloat16 h = __float2bfloat16(v);
        float lo = v - __bfloat162float(h);
        size_t o = (size_t)(nb + n) * K + kb + k;
        Whi[o] = h;
        Wlo[o] = __float2bfloat16(lo);
    }
}

// ---------------------------------------------------------------------------
// Activation convert (f32 -> hi/lo bf16, zero pad rows)
// ---------------------------------------------------------------------------
__global__ void aconv_kernel(const float* __restrict__ A,
                             __nv_bfloat16* __restrict__ Ahi, __nv_bfloat16* __restrict__ Alo,
                             int Min, int Kn)
{
    int r = blockIdx.x;
    size_t base = (size_t)r * Kn;
    if (r >= Min) {
        __nv_bfloat162 z = __float2bfloat162_rn(0.f);
        for (int c = threadIdx.x * 2; c < Kn; c += 256) {
            *reinterpret_cast<__nv_bfloat162*>(Ahi + base + c) = z;
            *reinterpret_cast<__nv_bfloat162*>(Alo + base + c) = z;
        }
        return;
    }
    for (int c = threadIdx.x * 2; c < Kn; c += 256) {
        float2 v = *reinterpret_cast<const float2*>(A + base + c);
        __nv_bfloat16 h0 = __float2bfloat16(v.x);
        __nv_bfloat16 h1 = __float2bfloat16(v.y);
        float l0 = v.x - __bfloat162float(h0);
        float l1 = v.y - __bfloat162float(h1);
        __nv_bfloat162 hp; hp.x = h0; hp.y = h1;
        __nv_bfloat162 lp; lp.x = __float2bfloat16(l0); lp.y = __float2bfloat16(l1);
        *reinterpret_cast<__nv_bfloat162*>(Ahi + base + c) = hp;
        *reinterpret_cast<__nv_bfloat162*>(Alo + base + c) = lp;
    }
}

// ---------------------------------------------------------------------------
// Fused LayerNorm + bf16 hi/lo conversion: H -> AH/AL (padded rows = 0)
// ---------------------------------------------------------------------------
__global__ void lnconv_kernel(const float* __restrict__ Hin,
                              __nv_bfloat16* __restrict__ Ahi, __nv_bfloat16* __restrict__ Alo,
                              const float* __restrict__ g, const float* __restrict__ b)
{
    int row = blockIdx.x;
    int tid = threadIdx.x;
    size_t base = (size_t)row * DMODEL;
    if (row < PADF) {
        __nv_bfloat16 z = __float2bfloat16(0.f);
        Ahi[base + tid] = z; Ahi[base + tid + 256] = z;
        Alo[base + tid] = z; Alo[base + tid + 256] = z;
        return;
    }
    const float* x = Hin + (size_t)(row - PADF) * DMODEL;
    float v0 = x[tid], v1 = x[tid + 256];
    __shared__ float s1[256], s2[256];
    s1[tid] = v0 + v1;
    s2[tid] = v0 * v0 + v1 * v1;
    __syncthreads();
    for (int o = 128; o > 0; o >>= 1) {
        if (tid < o) { s1[tid] += s1[tid + o]; s2[tid] += s2[tid + o]; }
        __syncthreads();
    }
    float mean = s1[0] * (1.f / DMODEL);
    float var  = s2[0] * (1.f / DMODEL) - mean * mean;
    float rs = rsqrtf(var + EPSLN);
    float y0 = (v0 - mean) * rs * g[tid] + b[tid];
    float y1 = (v1 - mean) * rs * g[tid + 256] + b[tid + 256];
    __nv_bfloat16 h0 = __float2bfloat16(y0);
    __nv_bfloat16 h1 = __float2bfloat16(y1);
    Ahi[base + tid]       = h0;
    Ahi[base + tid + 256] = h1;
    Alo[base + tid]       = __float2bfloat16(y0 - __bfloat162float(h0));
    Alo[base + tid + 256] = __float2bfloat16(y1 - __bfloat162float(h1));
}

// ---------------------------------------------------------------------------
// warp-MMA GEMM with cp.async double-buffered K-chunks of 32.
// C[M][N] = op(A @ B^T); 128x128 CTA tile, 8 warps (4x2).
// FLAG_SPLIT: write per-head bf16 hi/lo (QK into QKH/QKL, V into VH/VL);
//   col -> part=col>>9, h=(col>>6)&7, d=col&63.
// ---------------------------------------------------------------------------
#define TCP_STR  40                         // bf16 row stride (80 B, 16B-aligned)
#define TCP_BUF  (4 * 128 * TCP_STR)        // elements per buffer (20480)
#define TCG_SMEM (2 * TCP_BUF * 2)          // 81920 bytes

__global__ void __launch_bounds__(256)
tc_gemm_kernel(const __nv_bfloat16* __restrict__ Ahi, const __nv_bfloat16* __restrict__ Alo,
               const __nv_bfloat16* __restrict__ Bhi, const __nv_bfloat16* __restrict__ Blo,
               float* __restrict__ C, const float* __restrict__ bias,
               __nv_bfloat16* __restrict__ QKH, __nv_bfloat16* __restrict__ QKL,
               __nv_bfloat16* __restrict__ VH, __nv_bfloat16* __restrict__ VL,
               int Mn, int Nn, int Kn, int flags, int scale_cols, float scale)
{
    extern __shared__ __nv_bfloat16 smb[];
    const int t = threadIdx.x, lane = t & 31, wid = t >> 5;
    const int m0 = blockIdx.y * 128, n0 = blockIdx.x * 128;
    const int wm = (wid & 3) * 32;
    const int wn = (wid >> 2) * 64;

    const uint32_t smem_base = smem_u32(smb);

    const int a_row = (lane & 7) + ((lane >> 3) & 1) * 8;
    const int a_col = (lane >> 4) * 8;
    const int b_row = lane & 7;
    const int b_col = ((lane >> 3) & 1) * 8;

    const int nchunks = Kn >> 5;

    const int r1 = t >> 2,        kg1 = (t & 3) << 3;
    const int r2 = (t >> 2) + 64, kg2 = kg1;

    auto issue = [&](int ci, int buf) {
        int k0 = ci << 5;
        uint32_t bb = smem_base + (uint32_t)buf * TCP_BUF * 2;
        const __nv_bfloat16* gsrc[4] = {
            Ahi + (size_t)m0 * Kn, Alo + (size_t)m0 * Kn,
            Bhi + (size_t)n0 * Kn, Blo + (size_t)n0 * Kn };
#pragma unroll
        for (int arr = 0; arr < 4; arr++) {
            uint32_t sb = bb + (uint32_t)arr * 128 * TCP_STR * 2;
            cp_async16(sb + (uint32_t)(r1 * TCP_STR + kg1) * 2,
                       gsrc[arr] + (size_t)r1 * Kn + k0 + kg1);
            cp_async16(sb + (uint32_t)(r2 * TCP_STR + kg2) * 2,
                       gsrc[arr] + (size_t)r2 * Kn + k0 + kg2);
        }
    };

    float acc[2][8][4];
#pragma unroll
    for (int i = 0; i < 2; i++)
#pragma unroll
        for (int j = 0; j < 8; j++)
#pragma unroll
            for (int k = 0; k < 4; k++) acc[i][j][k] = 0.f;

    issue(0, 0); cp_commit();
    if (nchunks > 1) issue(1, 1);
    cp_commit();

    for (int ci = 0; ci < nchunks; ci++) {
        cp_wait1();
        __syncthreads();
        const int buf = ci & 1;
        uint32_t bb = smem_base + (uint32_t)buf * TCP_BUF * 2;
        uint32_t sAh_u = bb;
        uint32_t sAl_u = bb + 128 * TCP_STR * 2;
        uint32_t sBh_u = bb + 2 * 128 * TCP_STR * 2;
        uint32_t sBl_u = bb + 3 * 128 * TCP_STR * 2;
#pragma unroll
        for (int ks = 0; ks < 2; ks++) {
            const int kl = ks * 16;
            uint32_t ah[2][4], al[2][4];
#pragma unroll
            for (int mt = 0; mt < 2; mt++) {
                uint32_t off = (uint32_t)((wm + mt * 16 + a_row) * TCP_STR + kl + a_col) * 2;
                ldsm_x4(ah[mt], sAh_u + off);
                ldsm_x4(al[mt], sAl_u + off);
            }
#pragma unroll
            for (int ng = 0; ng < 2; ng++) {
                uint32_t bh[4][2], bl[4][2];
#pragma unroll
                for (int nt = 0; nt < 4; nt++) {
                    uint32_t off = (uint32_t)((wn + ng * 32 + nt * 8 + b_row) * TCP_STR + kl + b_col) * 2;
                    ldsm_x2(bh[nt], sBh_u + off);
                    ldsm_x2(bl[nt], sBl_u + off);
                }
#pragma unroll
                for (int mt = 0; mt < 2; mt++)
#pragma unroll
                    for (int nt = 0; nt < 4; nt++) {
                        float* d = acc[mt][ng * 4 + nt];
                        mma_bf16(d, ah[mt], bh[nt]);
                        mma_bf16(d, ah[mt], bl[nt]);
                        mma_bf16(d, al[mt], bh[nt]);
                    }
            }
        }
        __syncthreads();
        if (ci + 2 < nchunks) issue(ci + 2, buf);
        cp_commit();
    }

    const bool relu  = (flags & FLAG_RELU) != 0;
    const bool accu  = (flags & FLAG_ACC) != 0;
    const bool split = (flags & FLAG_SPLIT) != 0;
#pragma unroll
    for (int mt = 0; mt < 2; mt++) {
        int rbase = m0 + wm + mt * 16 + (lane >> 2);
#pragma unroll
        for (int nt = 0; nt < 8; nt++) {
            int c0 = n0 + wn + nt * 8 + (lane & 3) * 2;
#pragma unroll
            for (int half = 0; half < 2; half++) {
                int row = rbase + half * 8;
                if (row >= Mn) continue;
                float v0 = acc[mt][nt][half * 2 + 0];
                float v1 = acc[mt][nt][half * 2 + 1];
                if (c0 < scale_cols)     v0 *= scale;
                if (c0 + 1 < scale_cols) v1 *= scale;
                if (split) {
                    // per-head hi/lo output (c0 even -> both cols same head)
                    int part = c0 >> 9;
                    int h = (c0 >> 6) & 7;
                    int d = c0 & 63;
                    size_t o = (size_t)h * NP * DH + (size_t)row * DH + d;
                    __nv_bfloat16 h0 = __float2bfloat16(v0);
                    __nv_bfloat16 h1 = __float2bfloat16(v1);
                    __nv_bfloat162 hp; hp.x = h0; hp.y = h1;
                    __nv_bfloat162 lp;
                    lp.x = __float2bfloat16(v0 - __bfloat162float(h0));
                    lp.y = __float2bfloat16(v1 - __bfloat162float(h1));
                    if (part < 2) {
                        *reinterpret_cast<__nv_bfloat162*>(QKH + (size_t)part * QKOFF + o) = hp;
                        *reinterpret_cast<__nv_bfloat162*>(QKL + (size_t)part * QKOFF + o) = lp;
                    } else {
                        *reinterpret_cast<__nv_bfloat162*>(VH + o) = hp;
                        *reinterpret_cast<__nv_bfloat162*>(VL + o) = lp;
                    }
                    continue;
                }
                if (bias) { v0 += bias[c0]; v1 += bias[c0 + 1]; }
                if (relu) { v0 = fmaxf(v0, 0.f); v1 = fmaxf(v1, 0.f); }
                size_t o = (size_t)row * Nn + c0;
                if (accu) { C[o] += v0; C[o + 1] += v1; }
                else      { C[o] = v0;  C[o + 1] = v1; }
            }
        }
    }
}

// ---------------------------------------------------------------------------
// Batched logits MMA (K=64, one chunk): C[b][m][n] = A[b] @ B[b]^T
// ---------------------------------------------------------------------------
#define TCB_STR  72
#define SLOG_SMEM (4 * 128 * TCB_STR * 2)   // 73728 bytes

__global__ void __launch_bounds__(256)
slogits_kernel(const __nv_bfloat16* __restrict__ Ahi, const __nv_bfloat16* __restrict__ Alo,
               const __nv_bfloat16* __restrict__ Bhi, const __nv_bfloat16* __restrict__ Blo,
               float* __restrict__ C,
               size_t strideA, size_t strideB, size_t strideC, int ldc)
{
    extern __shared__ __nv_bfloat16 smb[];
    __nv_bfloat16* sAh = smb;
    __nv_bfloat16* sAl = smb + 128 * TCB_STR;
    __nv_bfloat16* sBh = smb + 2 * 128 * TCB_STR;
    __nv_bfloat16* sBl = smb + 3 * 128 * TCB_STR;

    const int t = threadIdx.x, lane = t & 31, wid = t >> 5;
    const int m0 = blockIdx.y * 128, n0 = blockIdx.x * 128;
    const int b = blockIdx.z;
    const __nv_bfloat16* Ah = Ahi + (size_t)b * strideA;
    const __nv_bfloat16* Al = Alo + (size_t)b * strideA;
    const __nv_bfloat16* Bh = Bhi + (size_t)b * strideB;
    const __nv_bfloat16* Bl = Blo + (size_t)b * strideB;
    float* Cb = C + (size_t)b * strideC;

    const int wm = (wid & 3) * 32;
    const int wn = (wid >> 2) * 64;

    const uint32_t sAh_u = smem_u32(sAh), sAl_u = smem_u32(sAl);
    const uint32_t sBh_u = smem_u32(sBh), sBl_u = smem_u32(sBl);

    const int a_row = (lane & 7) + ((lane >> 3) & 1) * 8;
    const int a_col = (lane >> 4) * 8;
    const int b_row = lane & 7;
    const int b_col = ((lane >> 3) & 1) * 8;

    float acc[2][8][4];
#pragma unroll
    for (int i = 0; i < 2; i++)
#pragma unroll
        for (int j = 0; j < 8; j++)
#pragma unroll
            for (int k = 0; k < 4; k++) acc[i][j][k] = 0.f;

    for (int i = t; i < 1024; i += 256) {
        int r = i >> 3, kg = (i & 7) << 3;
        int off = r * TCB_STR + kg;
        size_t ga = (size_t)(m0 + r) * DH + kg;
        size_t gb = (size_t)(n0 + r) * DH + kg;
        *reinterpret_cast<uint4*>(sAh + off) = *reinterpret_cast<const uint4*>(Ah + ga);
        *reinterpret_cast<uint4*>(sAl + off) = *reinterpret_cast<const uint4*>(Al + ga);
        *reinterpret_cast<uint4*>(sBh + off) = *reinterpret_cast<const uint4*>(Bh + gb);
        *reinterpret_cast<uint4*>(sBl + off) = *reinterpret_cast<const uint4*>(Bl + gb);
    }
    __syncthreads();
#pragma unroll
    for (int ks = 0; ks < 4; ks++) {
        const int kl = ks * 16;
        uint32_t ah[2][4], al[2][4];
#pragma unroll
        for (int mt = 0; mt < 2; mt++) {
            uint32_t off = (uint32_t)((wm + mt * 16 + a_row) * TCB_STR + kl + a_col) * 2;
            ldsm_x4(ah[mt], sAh_u + off);
            ldsm_x4(al[mt], sAl_u + off);
        }
#pragma unroll
        for (int ng = 0; ng < 2; ng++) {
            uint32_t bh[4][2], bl[4][2];
#pragma unroll
            for (int nt = 0; nt < 4; nt++) {
                uint32_t off = (uint32_t)((wn + ng * 32 + nt * 8 + b_row) * TCB_STR + kl + b_col) * 2;
                ldsm_x2(bh[nt], sBh_u + off);
                ldsm_x2(bl[nt], sBl_u + off);
            }
#pragma unroll
            for (int mt = 0; mt < 2; mt++)
#pragma unroll
                for (int nt = 0; nt < 4; nt++) {
                    float* d = acc[mt][nt + ng * 4];
                    mma_bf16(d, ah[mt], bh[nt]);
                    mma_bf16(d, ah[mt], bl[nt]);
                    mma_bf16(d, al[mt], bh[nt]);
                }
        }
    }

#pragma unroll
    for (int mt = 0; mt < 2; mt++) {
        int rbase = m0 + wm + mt * 16 + (lane >> 2);
#pragma unroll
        for (int nt = 0; nt < 8; nt++) {
            int c0 = n0 + wn + nt * 8 + (lane & 3) * 2;
#pragma unroll
            for (int half = 0; half < 2; half++) {
                int row = rbase + half * 8;
                size_t o = (size_t)row * ldc + c0;
                Cb[o]     = acc[mt][nt][half * 2 + 0];
                Cb[o + 1] = acc[mt][nt][half * 2 + 1];
            }
        }
    }
}

// ---------------------------------------------------------------------------
// pgemm with cp.async double-buffered K-chunks of 32 (unchanged from R12)
// ---------------------------------------------------------------------------
#define PGP_PSTR 40
#define PGP_BSTR 72
#define PGP_PL   (128 * PGP_PSTR)
#define PGP_BH   (2 * 128 * PGP_PSTR)
#define PGP_BL   (PGP_BH + 32 * PGP_BSTR)
#define PGP_BUF  (PGP_BL + 32 * PGP_BSTR)
#define PG_SMEM  (2 * PGP_BUF * 2)

__global__ void __launch_bounds__(256)
pgemm_kernel(const __nv_bfloat16* __restrict__ Phi, const __nv_bfloat16* __restrict__ Plo,
             const __nv_bfloat16* __restrict__ Bhi, const __nv_bfloat16* __restrict__ Blo,
             float* __restrict__ Cout,
             int Pld, size_t pHeadStride, size_t bHeadStride,
             int chunksPerSlice, int mode)
{
    extern __shared__ __nv_bfloat16 smb[];
    const int t = threadIdx.x, lane = t & 31, wid = t >> 5;
    const int m0 = blockIdx.x * 128;
    const int kslice = blockIdx.y;
    const int head = blockIdx.z;

    const int c0 = kslice * chunksPerSlice;
    const int nch = chunksPerSlice;

    const __nv_bfloat16* Ph = Phi + (size_t)head * pHeadStride;
    const __nv_bfloat16* Pl = Plo + (size_t)head * pHeadStride;
    const __nv_bfloat16* Bh = Bhi + (size_t)head * bHeadStride;
    const __nv_bfloat16* Bl = Blo + (size_t)head * bHeadStride;

    const int wm = (wid & 3) * 32;
    const int wn = (wid >> 2) * 32;

    const uint32_t smem_base = smem_u32(smb);

    const int a_row = (lane & 7) + ((lane >> 3) & 1) * 8;
    const int a_col = (lane >> 4) * 8;
    const int bt_k = lane & 15;

    const int pr = t >> 2, pkg = (t & 3) << 3;
    const int br = t >> 3, bcg = (t & 7) << 3;

    auto issue = [&](int ci, int buf) {
        int k0 = ci << 5;
        uint32_t bb = smem_base + (uint32_t)buf * PGP_BUF * 2;
        cp_async16(bb + (uint32_t)(pr * PGP_PSTR + pkg) * 2,
                   Ph + (size_t)(m0 + pr) * Pld + k0 + pkg);
        cp_async16(bb + (uint32_t)((pr + 64) * PGP_PSTR + pkg) * 2,
                   Ph + (size_t)(m0 + pr + 64) * Pld + k0 + pkg);
        uint32_t pl = bb + PGP_PL * 2;
        cp_async16(pl + (uint32_t)(pr * PGP_PSTR + pkg) * 2,
                   Pl + (size_t)(m0 + pr) * Pld + k0 + pkg);
        cp_async16(pl + (uint32_t)((pr + 64) * PGP_PSTR + pkg) * 2,
                   Pl + (size_t)(m0 + pr + 64) * Pld + k0 + pkg);
        uint32_t bhh = bb + PGP_BH * 2;
        uint32_t bll = bb + PGP_BL * 2;
        cp_async16(bhh + (uint32_t)(br * PGP_BSTR + bcg) * 2,
                   Bh + (size_t)(k0 + br) * 64 + bcg);
        cp_async16(bll + (uint32_t)(br * PGP_BSTR + bcg) * 2,
                   Bl + (size_t)(k0 + br) * 64 + bcg);
    };

    float acc[2][4][4];
#pragma unroll
    for (int i = 0; i < 2; i++)
#pragma unroll
        for (int j = 0; j < 4; j++)
#pragma unroll
            for (int k = 0; k < 4; k++) acc[i][j][k] = 0.f;

    issue(c0, 0); cp_commit();
    if (nch > 1) issue(c0 + 1, 1);
    cp_commit();

    for (int ci = 0; ci < nch; ci++) {
        cp_wait1();
        __syncthreads();
        const int buf = ci & 1;
        uint32_t bb = smem_base + (uint32_t)buf * PGP_BUF * 2;
        uint32_t sPh_u = bb;
        uint32_t sPl_u = bb + PGP_PL * 2;
        uint32_t sBh_u = bb + PGP_BH * 2;
        uint32_t sBl_u = bb + PGP_BL * 2;
#pragma unroll
        for (int ks = 0; ks < 2; ks++) {
            const int kl = ks * 16;
            uint32_t ph[2][4], pl2[2][4];
#pragma unroll
            for (int mt = 0; mt < 2; mt++) {
                uint32_t off = (uint32_t)((wm + mt * 16 + a_row) * PGP_PSTR + kl + a_col) * 2;
                ldsm_x4(ph[mt], sPh_u + off);
                ldsm_x4(pl2[mt], sPl_u + off);
            }
            uint32_t bh[4][2], bl[4][2];
#pragma unroll
            for (int nt = 0; nt < 4; nt++) {
                uint32_t off = (uint32_t)((kl + bt_k) * PGP_BSTR + wn + nt * 8) * 2;
                ldsm_x2_trans(bh[nt], sBh_u + off);
                ldsm_x2_trans(bl[nt], sBl_u + off);
            }
#pragma unroll
            for (int mt = 0; mt < 2; mt++)
#pragma unroll
                for (int nt = 0; nt < 4; nt++) {
                    float* d = acc[mt][nt];
                    mma_bf16(d, ph[mt], bh[nt]);
                    mma_bf16(d, ph[mt], bl[nt]);
                    mma_bf16(d, pl2[mt], bh[nt]);
                }
        }
        __syncthreads();
        if (ci + 2 < nch) issue(c0 + ci + 2, buf);
        cp_commit();
    }

#pragma unroll
    for (int mt = 0; mt < 2; mt++) {
        int rbase = m0 + wm + mt * 16 + (lane >> 2);
#pragma unroll
        for (int nt = 0; nt < 4; nt++) {
            int c0c = wn + nt * 8 + (lane & 3) * 2;
#pragma unroll
            for (int half = 0; half < 2; half++) {
                int row = rbase + half * 8;
                float v0 = acc[mt][nt][half * 2 + 0];
                float v1 = acc[mt][nt][half * 2 + 1];
                if (mode == 0) {
                    size_t o = (((size_t)kslice * NHEADS + head) * MLAND + row) * 64 + c0c;
                    Cout[o] = v0; Cout[o + 1] = v1;
                } else {
                    size_t o = (size_t)row * DMODEL + head * 64 + c0c;
                    Cout[o] = v0; Cout[o + 1] = v1;
                }
            }
        }
    }
}

// ---------------------------------------------------------------------------
// split-K reduction: A3V = sum over 8 slices
// ---------------------------------------------------------------------------
__global__ void pvred_kernel(const float* __restrict__ PVP, float* __restrict__ A3V)
{
    int h = blockIdx.x & 7, seg = blockIdx.x >> 3;
    int idx = seg * 2048 + threadIdx.x * 8;
    for (int j = 0; j < 8; j++) {
        int li = idx + j;
        float s = 0.f;
#pragma unroll
        for (int sl = 0; sl < 8; sl++)
            s += PVP[(((size_t)sl * NHEADS + h) * MLAND * 64) + li];
        A3V[(size_t)h * MLAND * 64 + li] = s;
    }
}

// ---------------------------------------------------------------------------
// p3 softmax: S3 [h][m][NP] -> normalized P hi/lo (block per row)
// ---------------------------------------------------------------------------
__global__ void p3_kernel(const float* __restrict__ S,
                          __nv_bfloat16* __restrict__ PH, __nv_bfloat16* __restrict__ PL)
{
    int m = blockIdx.x, h = blockIdx.y;
    int t = threadIdx.x;
    const float* row = S + ((size_t)h * MLAND + m) * NP;
    float vals[33];
    float mx = -1e30f;
#pragma unroll
    for (int i = 0; i < 33; i++) {
        vals[i] = row[i * 256 + t];
        mx = fmaxf(mx, vals[i]);
    }
    __shared__ float red[256];
    red[t] = mx; __syncthreads();
    for (int o = 128; o > 0; o >>= 1) {
        if (t < o) red[t] = fmaxf(red[t], red[t + o]);
        __syncthreads();
    }
    mx = red[0]; __syncthreads();
    float sum = 0.f;
#pragma unroll
    for (int i = 0; i < 33; i++) {
        vals[i] = __expf(vals[i] - mx);
        sum += vals[i];
    }
    red[t] = sum; __syncthreads();
    for (int o = 128; o > 0; o >>= 1) {
        if (t < o) red[t] += red[t + o];
        __syncthreads();
    }
    float inv = 1.0f / red[0];
    __nv_bfloat16* ph = PH + ((size_t)h * MLAND + m) * NP;
    __nv_bfloat16* pl = PL + ((size_t)h * MLAND + m) * NP;
#pragma unroll
    for (int i = 0; i < 33; i++) {
        float p = vals[i] * inv;
        __nv_bfloat16 hi = __float2bfloat16(p);
        ph[i * 256 + t] = hi;
        pl[i * 256 + t] = __float2bfloat16(p - __bfloat162float(hi));
    }
}

// ---------------------------------------------------------------------------
// p1 softmax: S1 [h][n][256] -> normalized P hi/lo (warp per row)
// ---------------------------------------------------------------------------
__global__ void p1_kernel(const float* __restrict__ S,
                          __nv_bfloat16* __restrict__ PH, __nv_bfloat16* __restrict__ PL)
{
    int row = blockIdx.x * 8 + (threadIdx.x >> 5);
    int lane = threadIdx.x & 31;
    const float* r = S + (size_t)row * MLAND;
    float a[8];
#pragma unroll
    for (int k = 0; k < 8; k++) a[k] = r[lane + k * 32];
    float m = a[0];
#pragma unroll
    for (int k = 1; k < 8; k++) m = fmaxf(m, a[k]);
    for (int o = 16; o > 0; o >>= 1) m = fmaxf(m, __shfl_xor_sync(0xffffffffu, m, o));
    float s = 0.f;
#pragma unroll
    for (int k = 0; k < 8; k++) { a[k] = __expf(a[k] - m); s += a[k]; }
    for (int o = 16; o > 0; o >>= 1) s += __shfl_xor_sync(0xffffffffu, s, o);
    float inv = 1.0f / s;
    __nv_bfloat16* ph = PH + (size_t)row * MLAND;
    __nv_bfloat16* pl = PL + (size_t)row * MLAND;
#pragma unroll
    for (int k = 0; k < 8; k++) {
        float p = a[k] * inv;
        __nv_bfloat16 hi = __float2bfloat16(p);
        ph[lane + k * 32] = hi;
        pl[lane + k * 32] = __float2bfloat16(p - __bfloat162float(hi));
    }
}

// ---------------------------------------------------------------------------
// Assemble h rows: cls + wrap
// ---------------------------------------------------------------------------
__global__ void assemble_kernel(const float* __restrict__ cls, float* __restrict__ H)
{
    int j = blockIdx.x;
    int c = threadIdx.x;
    if (j == 0) H[c] = cls[c];
    else        H[(size_t)(NTOK + j) * DMODEL + c] = H[(size_t)j * DMODEL + c];
}

// ---------------------------------------------------------------------------
// Landmarks from per-head Q/K hi/lo: means of 33-groups
// ---------------------------------------------------------------------------
__global__ void landmarks_kernel(const __nv_bfloat16* __restrict__ QKH,
                                 const __nv_bfloat16* __restrict__ QKL,
                                 float* __restrict__ QL, float* __restrict__ KL,
                                 __nv_bfloat16* __restrict__ QLH, __nv_bfloat16* __restrict__ QLL,
                                 __nv_bfloat16* __restrict__ KLH, __nv_bfloat16* __restrict__ KLL)
{
    int hm = blockIdx.x;
    int h = hm >> 8, m = hm & 255;
    int tid = threadIdx.x;
    int d = tid & 63;
    int part = (tid < 64) ? 0 : 1;   // 0 = q, 1 = k
    size_t base = (size_t)part * QKOFF + (size_t)h * NP * DH + (size_t)(m * LWIN) * DH + d;
    float s = 0.f;
#pragma unroll
    for (int j = 0; j < LWIN; j++) {
        size_t idx = base + (size_t)j * DH;
        s += __bfloat162float(QKH[idx]) + __bfloat162float(QKL[idx]);
    }
    s *= (1.0f / LWIN);
    __nv_bfloat16 hi = __float2bfloat16(s);
    __nv_bfloat16 lo = __float2bfloat16(s - __bfloat162float(hi));
    size_t o = (size_t)(h * MLAND + m) * DH + d;
    if (part == 0) {
        QL[o] = s; QLH[o] = hi; QLL[o] = lo;
    } else {
        KL[o] = s; KLH[o] = hi; KLL[o] = lo;
    }
}

// ---------------------------------------------------------------------------
// a2 = softmax(q_l @ k_l^T)
// ---------------------------------------------------------------------------
__global__ void a2_kernel(const float* __restrict__ QL, const float* __restrict__ KL,
                          float* __restrict__ A2)
{
    int m = blockIdx.x, h = blockIdx.y;
    int tid = threadIdx.x;
    __shared__ float q[64];
    __shared__ float red[256];
    if (tid < 64) q[tid] = QL[(size_t)(h * MLAND + m) * DH + tid];
    __syncthreads();
    const float* kr = KL + (size_t)(h * MLAND + tid) * DH;
    float s = 0.f;
#pragma unroll
    for (int i = 0; i < 16; i++) {
        float4 kv = reinterpret_cast<const float4*>(kr)[i];
        float4 qv = reinterpret_cast<const float4*>(q)[i];
        s += kv.x * qv.x + kv.y * qv.y + kv.z * qv.z + kv.w * qv.w;
    }
    red[tid] = s; __syncthreads();
    for (int o = 128; o > 0; o >>= 1) {
        if (tid < o) red[tid] = fmaxf(red[tid], red[tid + o]);
        __syncthreads();
    }
    float mx = red[0]; __syncthreads();
    float e = __expf(s - mx);
    red[tid] = e; __syncthreads();
    for (int o = 128; o > 0; o >>= 1) {
        if (tid < o) red[tid] += red[tid + o];
        __syncthreads();
    }
    float sm = red[0];
    A2[(size_t)(h * MLAND + m) * MLAND + tid] = e / sm;
}

// ---------------------------------------------------------------------------
// pinv chain
// ---------------------------------------------------------------------------
__global__ void pinv_scale_kernel(const float* __restrict__ A2, float* __restrict__ PS)
{
    int h = blockIdx.x;
    int t = threadIdx.x;
    int w = t >> 5, lane = t & 31;
    const float* Ah = A2 + (size_t)h * 65536;
    __shared__ float rs[256];
    __shared__ float cs2[256];
    for (int r = w; r < 256; r += 8) {
        float s = 0.f;
        for (int j = lane; j < 256; j += 32) s += fabsf(Ah[r * 256 + j]);
        for (int o = 16; o > 0; o >>= 1) s += __shfl_xor_sync(0xffffffffu, s, o);
        if (lane == 0) rs[r] = s;
    }
    float cs = 0.f;
    for (int i = 0; i < 256; i++) cs += fabsf(Ah[i * 256 + t]);
    cs2[t] = cs;
    __syncthreads();
    for (int o = 128; o > 0; o >>= 1) {
        if (t < o) { rs[t] = fmaxf(rs[t], rs[t + o]); cs2[t] = fmaxf(cs2[t], cs2[t + o]); }
        __syncthreads();
    }
    if (t == 0) PS[h] = 1.0f / (rs[0] * cs2[0]);
}

__global__ void pinv_tr_kernel(const float* __restrict__ A2, const float* __restrict__ PS,
                               float* __restrict__ Z0)
{
    __shared__ float tl[64][65];
    int h = blockIdx.y;
    int seg = blockIdx.x;
    int bi = (seg >> 2) * 64, bj = (seg & 3) * 64;
    int t = threadIdx.x;
    float inv = PS[h];
    const float* Ah = A2 + (size_t)h * 65536;
    float* Zh = Z0 + (size_t)h * 65536;
    for (int lin = t; lin < 4096; lin += 256) {
        int r = lin >> 6, c = lin & 63;
        tl[r][c] = Ah[(size_t)(bi + r) * 256 + bj + c];
    }
    __syncthreads();
    for (int lin = t; lin < 4096; lin += 256) {
        int r = lin >> 6, c = lin & 63;
        Zh[(size_t)(bj + r) * 256 + bi + c] = tl[c][r] * inv;
    }
}

__global__ void nk256_kernel(const float* __restrict__ A, const float* __restrict__ B,
                             float* __restrict__ C, float alpha, float gamma)
{
    const float* Ah = A + (size_t)blockIdx.z * 65536;
    const float* Bh = B + (size_t)blockIdx.z * 65536;
    float* Ch = C + (size_t)blockIdx.z * 65536;
    __shared__ float As[16][64];
    __shared__ float Bs[16][64];
    const int bm = blockIdx.y * 64;
    const int bn = blockIdx.x * 64;
    const int tid = threadIdx.x;
    const int tx = tid & 15, ty = tid >> 4;
    const int row0 = ty * 4, col0 = tx * 4;
    float acc[4][4];
#pragma unroll
    for (int i = 0; i < 4; i++)
#pragma unroll
        for (int j = 0; j < 4; j++) acc[i][j] = 0.f;

    for (int k0 = 0; k0 < 256; k0 += 16) {
        {
            int ar = tid >> 2;
            int ac = (tid & 3) << 2;
            float4 v = *reinterpret_cast<const float4*>(Ah + (size_t)(bm + ar) * 256 + k0 + ac);
            As[ac + 0][ar] = v.x; As[ac + 1][ar] = v.y;
            As[ac + 2][ar] = v.z; As[ac + 3][ar] = v.w;
        }
        {
            int br = tid >> 4;
            int bc = (tid & 15) << 2;
            float4 v = *reinterpret_cast<const float4*>(Bh + (size_t)(k0 + br) * 256 + bn + bc);
            *reinterpret_cast<float4*>(&Bs[br][bc]) = v;
        }
        __syncthreads();
#pragma unroll
        for (int k = 0; k < 16; k++) {
            float a[4], b[4];
            *reinterpret_cast<float4*>(a) = *reinterpret_cast<const float4*>(&As[k][row0]);
            *reinterpret_cast<float4*>(b) = *reinterpret_cast<const float4*>(&Bs[k][col0]);
#pragma unroll
            for (int i = 0; i < 4; i++)
#pragma unroll
                for (int j = 0; j < 4; j++) acc[i][j] += a[i] * b[j];
        }
        __syncthreads();
    }
#pragma unroll
    for (int i = 0; i < 4; i++)
#pragma unroll
        for (int j = 0; j < 4; j++) {
            size_t o = (size_t)(bm + row0 + i) * 256 + bn + col0 + j;
            Ch[o] = alpha * acc[i][j] + gamma * Ah[o];
        }
}

// ---------------------------------------------------------------------------
// Bm = pinv(a2) @ a3v  -> bf16 hi/lo
// ---------------------------------------------------------------------------
__global__ void bmat_kernel(const float* __restrict__ Z, const float* __restrict__ A3V,
                            __nv_bfloat16* __restrict__ BmH, __nv_bfloat16* __restrict__ BmL)
{
    int h = blockIdx.y;
    int m0 = blockIdx.x * 4;
    __shared__ float zs[4][256];
    int tid = threadIdx.x;
    int r = tid >> 6, d = tid & 63;
    for (int lin = tid; lin < 1024; lin += 256) {
        int rr = lin >> 8, k = lin & 255;
        zs[rr][k] = Z[(size_t)h * 65536 + (size_t)(m0 + rr) * 256 + k];
    }
    __syncthreads();
    float acc = 0.f;
    for (int k = 0; k < 256; k++)
        acc += zs[r][k] * A3V[(size_t)(h * MLAND + k) * DH + d];
    size_t o = (size_t)(h * MLAND + m0 + r) * DH + d;
    __nv_bfloat16 hi = __float2bfloat16(acc);
    BmH[o] = hi;
    BmL[o] = __float2bfloat16(acc - __bfloat162float(hi));
}

// ---------------------------------------------------------------------------
// Depthwise seq-conv (k=33) on v (from VH/VL), tiled in smem; adds into O
// ---------------------------------------------------------------------------
__global__ void conv_tile_kernel(const __nv_bfloat16* __restrict__ VH,
                                 const __nv_bfloat16* __restrict__ VL,
                                 const float* __restrict__ W, float* __restrict__ O)
{
    __shared__ float vs[160 * 64];
    __shared__ float ws[33];
    int h = blockIdx.y;
    int n0 = blockIdx.x * 128;
    int t = threadIdx.x;
    if (t < 33) ws[t] = W[h * LWIN + t];
    for (int lin = t; lin < 160 * 64; lin += 256) {
        int r = lin >> 6, c = lin & 63;
        int n = n0 + r - 16;
        float v = 0.f;
        if (n >= 0 && n < NP) {
            size_t o = (size_t)h * NP * DH + (size_t)n * DH + c;
            v = __bfloat162float(VH[o]) + __bfloat162float(VL[o]);
        }
        vs[lin] = v;
    }
    __syncthreads();
    int c = t & 63, rg = t >> 6;
    for (int q = 0; q < 32; q++) {
        int r = rg * 32 + q;
        float acc = 0.f;
#pragma unroll
        for (int k = 0; k < LWIN; k++) acc += ws[k] * vs[(r + k) * 64 + c];
        O[(size_t)(n0 + r) * DMODEL + h * DH + c] += acc;
    }
}

// ---------------------------------------------------------------------------
// PPEG tiled
// ---------------------------------------------------------------------------
#define PPEG_TILE (14 * 14 * 64)
#define PPEG_W7   PPEG_TILE
#define PPEG_W5   (PPEG_W7 + 64 * 49)
#define PPEG_W3   (PPEG_W5 + 64 * 25)
#define PPEG_TOT  (PPEG_W3 + 64 * 9)

__global__ void ppeg_tile_kernel(const float* __restrict__ Hin, float* __restrict__ Hout,
                                 const float* __restrict__ w7, const float* __restrict__ b7,
                                 const float* __restrict__ w5, const float* __restrict__ b5,
                                 const float* __restrict__ w3, const float* __restrict__ b3)
{
    extern __shared__ float sm[];
    float* tile = sm;
    float* ws7 = sm + PPEG_W7;
    float* ws5 = sm + PPEG_W5;
    float* ws3 = sm + PPEG_W3;

    int ti = blockIdx.x;
    int ty0 = (ti / 12) * 8, tx0 = (ti % 12) * 8;
    int cg = blockIdx.y * 64;
    int t = threadIdx.x;

    for (int lin = t; lin < PPEG_TILE; lin += 256) {
        int p = lin >> 6, c = lin & 63;
        int gy = ty0 + p / 14 - 3;
        int gx = tx0 + p % 14 - 3;
        float v = 0.f;
        if ((unsigned)gy < (unsigned)HSQ && (unsigned)gx < (unsigned)HSQ)
            v = Hin[(size_t)(1 + gy * HSQ + gx) * DMODEL + cg + c];
        tile[lin] = v;
    }
    for (int lin = t; lin < 64 * 49; lin += 256) ws7[lin] = w7[(size_t)cg * 49 + lin];
    for (int lin = t; lin < 64 * 25; lin += 256) ws5[lin] = w5[(size_t)cg * 25 + lin];
    for (int lin = t; lin < 64 * 9;  lin += 256) ws3[lin] = w3[(size_t)cg * 9 + lin];
    __syncthreads();

    int c = t & 63, pg = t >> 6;
    float bsum = b7[cg + c] + b5[cg + c] + b3[cg + c];
    for (int q = 0; q < 16; q++) {
        int p = pg * 16 + q;
        int oy = p >> 3, ox = p & 7;
        int gy = ty0 + oy, gx = tx0 + ox;
        if (gy >= HSQ || gx >= HSQ) continue;
        float acc = tile[((oy + 3) * 14 + ox + 3) * 64 + c] + bsum;
#pragma unroll
        for (int a = 0; a < 7; a++)
#pragma unroll
            for (int bq = 0; bq < 7; bq++)
                acc += ws7[c * 49 + a * 7 + bq] * tile[((oy + a) * 14 + ox + bq) * 64 + c];
#pragma unroll
        for (int a = 0; a < 5; a++)
#pragma unroll
            for (int bq = 0; bq < 5; bq++)
                acc += ws5[c * 25 + a * 5 + bq] * tile[((oy + a + 1) * 14 + ox + bq + 1) * 64 + c];
#pragma unroll
        for (int a = 0; a < 3; a++)
#pragma unroll
            for (int bq = 0; bq < 3; bq++)
                acc += ws3[c * 9 + a * 3 + bq] * tile[((oy + a + 2) * 14 + ox + bq + 2) * 64 + c];
        Hout[(size_t)(1 + gy * HSQ + gx) * DMODEL + cg + c] = acc;
    }
}

__global__ void copy_row0_kernel(const float* __restrict__ Hin, float* __restrict__ Hout)
{
    Hout[threadIdx.x] = Hin[threadIdx.x];
}

// ---------------------------------------------------------------------------
// Final head
// ---------------------------------------------------------------------------
__global__ void final_kernel(const float* __restrict__ H, const float* __restrict__ g,
                             const float* __restrict__ b, const float* __restrict__ w,
                             const float* __restrict__ bias2, float* __restrict__ out,
                             int out_size)
{
    int c = threadIdx.x;
    __shared__ float s1[512], s2[512];
    float x = H[c];
    s1[c] = x; s2[c] = x * x;
    __syncthreads();
    for (int o = 256; o > 0; o >>= 1) {
        if (c < o) { s1[c] += s1[c + o]; s2[c] += s2[c + o]; }
        __syncthreads();
    }
    float mean = s1[0] * (1.f / DMODEL);
    float var  = s2[0] * (1.f / DMODEL) - mean * mean;
    float e = (x - mean) * rsqrtf(var + EPSLN) * g[c] + b[c];
    __syncthreads();
    s1[c] = e * w[c * 2 + 0];
    s2[c] = e * w[c * 2 + 1];
    __syncthreads();
    for (int o = 256; o > 0; o >>= 1) {
        if (c < o) { s1[c] += s1[c + o]; s2[c] += s2[c + o]; }
        __syncthreads();
    }
    float l0 = s1[0] + bias2[0];
    float l1 = s2[0] + bias2[1];
    if (c == 0) {
        float m = fmaxf(l0, l1);
        float e0 = expf(l0 - m), e1 = expf(l1 - m);
        float ss = e0 + e1;
        if (out_size > 0) out[0] = l0;
        if (out_size > 1) out[1] = l1;
        if (out_size > 2) out[2] = e0 / ss;
        if (out_size > 3) out[3] = e1 / ss;
        if (out_size > 4) out[4] = (l1 > l0) ? 1.0f : 0.0f;
    }
    if (5 + c < out_size) out[5 + c] = e;
}

// ---------------------------------------------------------------------------
// Host orchestration
// ---------------------------------------------------------------------------
static float* symaddr(const void* sym)
{
    void* p = nullptr;
    cudaGetSymbolAddress(&p, sym);
    return (float*)p;
}
static __nv_bfloat16* symaddr_bf(const void* sym)
{
    void* p = nullptr;
    cudaGetSymbolAddress(&p, sym);
    return (__nv_bfloat16*)p;
}

static cudaStream_t g_side = nullptr;
static cudaEvent_t  g_evf  = nullptr;
static cudaEvent_t  g_evj  = nullptr;

extern "C" void kernel_launch(void* const* d_in, const int* in_sizes, int n_in,
                              void* d_out, int out_size)
{
    if (!g_side) {
        cudaStreamCreateWithFlags(&g_side, cudaStreamNonBlocking);
        cudaEventCreateWithFlags(&g_evf, cudaEventDisableTiming);
        cudaEventCreateWithFlags(&g_evj, cudaEventDisableTiming);
    }

    const float* x       = (const float*)d_in[0];
    const float* fc1_w   = (const float*)d_in[1];
    const float* fc1_b   = (const float*)d_in[2];
    const float* cls     = (const float*)d_in[3];
    const float* ln1_g   = (const float*)d_in[4];
    const float* ln1_b   = (const float*)d_in[5];
    const float* qkv1_w  = (const float*)d_in[6];
    const float* out1_w  = (const float*)d_in[7];
    const float* out1_b  = (const float*)d_in[8];
    const float* conv1_w = (const float*)d_in[9];
    const float* ln2_g   = (const float*)d_in[10];
    const float* ln2_b   = (const float*)d_in[11];
    const float* qkv2_w  = (const float*)d_in[12];
    const float* out2_w  = (const float*)d_in[13];
    const float* out2_b  = (const float*)d_in[14];
    const float* conv2_w = (const float*)d_in[15];
    const float* pg7_w   = (const float*)d_in[16];
    const float* pg7_b   = (const float*)d_in[17];
    const float* pg5_w   = (const float*)d_in[18];
    const float* pg5_b   = (const float*)d_in[19];
    const float* pg3_w   = (const float*)d_in[20];
    const float* pg3_b   = (const float*)d_in[21];
    const float* norm_g  = (const float*)d_in[22];
    const float* norm_b  = (const float*)d_in[23];
    const float* fc2_w   = (const float*)d_in[24];
    const float* fc2_b   = (const float*)d_in[25];

    float* H   = symaddr(g_H);
    float* H2  = symaddr(g_H2);
    float* QL  = symaddr(g_QL);
    float* KL  = symaddr(g_KL);
    float* A2  = symaddr(g_A2);
    float* Z0  = symaddr(g_Z0);
    float* Z1  = symaddr(g_Z1);
    float* W1  = symaddr(g_W1);
    float* W2  = symaddr(g_W2);
    float* W3  = symaddr(g_W3);
    float* PS  = symaddr(g_PS);
    float* A3V = symaddr(g_A3V);
    float* O   = symaddr(g_O);
    float* S   = symaddr(g_S);
    float* PVP = symaddr(g_PVP);
    __nv_bfloat16* AH  = symaddr_bf(g_AH);
    __nv_bfloat16* AL  = symaddr_bf(g_AL);
    __nv_bfloat16* QKH = symaddr_bf(g_QKH);
    __nv_bfloat16* QKL = symaddr_bf(g_QKL);
    __nv_bfloat16* WH  = symaddr_bf(g_WH);
    __nv_bfloat16* WL  = symaddr_bf(g_WL);
    __nv_bfloat16* QLH = symaddr_bf(g_QLH);
    __nv_bfloat16* QLL = symaddr_bf(g_QLL);
    __nv_bfloat16* KLH = symaddr_bf(g_KLH);
    __nv_bfloat16* KLL = symaddr_bf(g_KLL);
    __nv_bfloat16* VH  = symaddr_bf(g_VH);
    __nv_bfloat16* VL  = symaddr_bf(g_VL);
    __nv_bfloat16* PH  = symaddr_bf(g_PH);
    __nv_bfloat16* PL  = symaddr_bf(g_PL);
    __nv_bfloat16* BmH = symaddr_bf(g_BmH);
    __nv_bfloat16* BmL = symaddr_bf(g_BmL);

    const int PPEG_SMEM = PPEG_TOT * 4;
    cudaFuncSetAttribute(ppeg_tile_kernel, cudaFuncAttributeMaxDynamicSharedMemorySize, PPEG_SMEM);
    cudaFuncSetAttribute(tc_gemm_kernel,  cudaFuncAttributeMaxDynamicSharedMemorySize, TCG_SMEM);
    cudaFuncSetAttribute(slogits_kernel,  cudaFuncAttributeMaxDynamicSharedMemorySize, SLOG_SMEM);
    cudaFuncSetAttribute(pgemm_kernel,    cudaFuncAttributeMaxDynamicSharedMemorySize, PG_SMEM);

    // ---- fc1 + relu via tensor cores ----
    wconv_kernel<<<dim3(DMODEL / 32, INDIM / 32), 256>>>(fc1_w, WH, WL, INDIM, DMODEL);
    aconv_kernel<<<NTOK, 128>>>(x, AH, AL, NTOK, INDIM);
    tc_gemm_kernel<<<dim3(DMODEL / 128, NTOK / 128), 256, TCG_SMEM>>>(
        AH, AL, WH, WL, H + DMODEL, fc1_b, nullptr, nullptr, nullptr, nullptr,
        NTOK, DMODEL, INDIM, FLAG_RELU, 0, 1.f);
    assemble_kernel<<<NWRAP + 1, DMODEL>>>(cls, H);

    auto attn = [&](float* Hbuf, const float* lng, const float* lnb, const float* qkvw,
                    const float* outw, const float* outb, const float* convw) {
        // fused LN + hi/lo conversion straight into AH/AL
        lnconv_kernel<<<NP, 256>>>(Hbuf, AH, AL, lng, lnb);
        wconv_kernel<<<dim3(3 * DMODEL / 32, DMODEL / 32), 256>>>(qkvw, WH, WL, DMODEL, 3 * DMODEL);
        // qkv GEMM: split epilogue writes per-head Q/K/V hi/lo directly
        tc_gemm_kernel<<<dim3(3 * DMODEL / 128, NP / 128), 256, TCG_SMEM>>>(
            AH, AL, WH, WL, nullptr, nullptr, QKH, QKL, VH, VL,
            NP, 3 * DMODEL, DMODEL, FLAG_SPLIT, DMODEL, 0.125f);
        landmarks_kernel<<<NHEADS * MLAND, 128>>>(QKH, QKL, QL, KL, QLH, QLL, KLH, KLL);
        a2_kernel<<<dim3(MLAND, NHEADS), 256>>>(QL, KL, A2);

        // fork: pinv chain on side stream
        cudaEventRecord(g_evf, 0);
        cudaStreamWaitEvent(g_side, g_evf, 0);
        pinv_scale_kernel<<<NHEADS, 256, 0, g_side>>>(A2, PS);
        pinv_tr_kernel<<<dim3(16, NHEADS), 256, 0, g_side>>>(A2, PS, Z0);
        float* zi = Z0;
        float* zo = Z1;
        for (int it = 0; it < 6; it++) {
            nk256_kernel<<<dim3(4, 4, NHEADS), 256, 0, g_side>>>(A2, zi, W1, 1.f, 0.f);
            nk256_kernel<<<dim3(4, 4, NHEADS), 256, 0, g_side>>>(W1, W1, W2, -1.f, 7.f);
            nk256_kernel<<<dim3(4, 4, NHEADS), 256, 0, g_side>>>(W1, W2, W3, -1.f, 15.f);
            nk256_kernel<<<dim3(4, 4, NHEADS), 256, 0, g_side>>>(zi, W3, zo, -0.25f, 3.25f);
            float* t = zi; zi = zo; zo = t;
        }
        cudaEventRecord(g_evj, g_side);

        // S3 = QL @ K^T -> softmax -> A3V = P3 @ V (split-K MMA, 33 k32-chunks/slice)
        slogits_kernel<<<dim3(NP / 128, MLAND / 128, NHEADS), 256, SLOG_SMEM>>>(
            QLH, QLL, QKH + QKOFF, QKL + QKOFF, S,
            (size_t)MLAND * DH, (size_t)NP * DH, (size_t)MLAND * NP, NP);
        p3_kernel<<<dim3(MLAND, NHEADS), 256>>>(S, PH, PL);
        pgemm_kernel<<<dim3(MLAND / 128, 8, NHEADS), 256, PG_SMEM>>>(
            PH, PL, VH, VL, PVP, NP, (size_t)MLAND * NP, (size_t)NP * DH, 33, 0);
        pvred_kernel<<<64, 256>>>(PVP, A3V);

        // S1 = Q @ KL^T -> softmax
        slogits_kernel<<<dim3(MLAND / 128, NP / 128, NHEADS), 256, SLOG_SMEM>>>(
            QKH, QKL, KLH, KLL, S,
            (size_t)NP * DH, (size_t)MLAND * DH, (size_t)NP * MLAND, MLAND);
        p1_kernel<<<NP * NHEADS / 8, 256>>>(S, PH, PL);

        // join pinv; Bm; O = P1 @ Bm (8 k32-chunks); += conv
        cudaStreamWaitEvent(0, g_evj, 0);
        bmat_kernel<<<dim3(MLAND / 4, NHEADS), 256>>>(zi, A3V, BmH, BmL);
        pgemm_kernel<<<dim3(NP / 128, 1, NHEADS), 256, PG_SMEM>>>(
            PH, PL, BmH, BmL, O, MLAND, (size_t)NP * MLAND, (size_t)MLAND * DH, 8, 1);
        conv_tile_kernel<<<dim3(NP / 128, NHEADS), 256>>>(VH, VL, convw, O);

        // out projection (accumulate into Hbuf)
        wconv_kernel<<<dim3(DMODEL / 32, DMODEL / 32), 256>>>(outw, WH, WL, DMODEL, DMODEL);
        aconv_kernel<<<8320, 128>>>(O + (size_t)PADF * DMODEL, AH, AL, NHTOK, DMODEL);
        tc_gemm_kernel<<<dim3(DMODEL / 128, 65), 256, TCG_SMEM>>>(
            AH, AL, WH, WL, Hbuf, outb, nullptr, nullptr, nullptr, nullptr,
            NHTOK, DMODEL, DMODEL, FLAG_ACC, 0, 1.f);
    };

    attn(H, ln1_g, ln1_b, qkv1_w, out1_w, out1_b, conv1_w);

    ppeg_tile_kernel<<<dim3(144, NHEADS), 256, PPEG_SMEM>>>(
        H, H2, pg7_w, pg7_b, pg5_w, pg5_b, pg3_w, pg3_b);
    copy_row0_kernel<<<1, DMODEL>>>(H, H2);

    attn(H2, ln2_g, ln2_b, qkv2_w, out2_w, out2_b, conv2_w);

    final_kernel<<<1, DMODEL>>>(H2, norm_g, norm_b, fc2_w, fc2_b, (float*)d_out, out_size);
}

// round 16
// speedup vs baseline: 1.2014x; 1.0210x over previous
#include <cuda_runtime.h>
#include <cuda_bf16.h>
#include <math.h>
#include <stdint.h>

// ---------------------------------------------------------------------------
// Problem constants
// ---------------------------------------------------------------------------
#define NTOK   8192
#define INDIM  1024
#define DMODEL 512
#define NHEADS 8
#define DH     64
#define MLAND  256
#define LWIN   33
#define NP     8448          // padded attention length
#define NHTOK  8282          // tokens incl cls
#define PADF   166
#define HSQ    91
#define NFEAT  8281
#define NWRAP  89
#define EPSLN  1e-5f

#define FLAG_RELU  1
#define FLAG_ACC   2
#define FLAG_SPLIT 4

// ---------------------------------------------------------------------------
// Scratch (device globals)
// ---------------------------------------------------------------------------
__device__ float g_H  [NHTOK * DMODEL];
__device__ float g_H2 [NHTOK * DMODEL];
__device__ float g_QL [NHEADS * MLAND * DH];
__device__ float g_KL [NHEADS * MLAND * DH];
__device__ float g_A2 [NHEADS * MLAND * MLAND];
__device__ float g_Z0 [NHEADS * MLAND * MLAND];
__device__ float g_Z1 [NHEADS * MLAND * MLAND];
__device__ float g_W1 [NHEADS * MLAND * MLAND];
__device__ float g_W2 [NHEADS * MLAND * MLAND];
__device__ float g_W3 [NHEADS * MLAND * MLAND];
__device__ float g_PS [NHEADS];
__device__ float g_A3V[NHEADS * MLAND * DH];
__device__ float g_O  [NP * DMODEL];
__device__ float g_S  [NHEADS * NP * MLAND];     // logits scratch (S3 then S1)
__device__ float g_PVP[8 * NHEADS * MLAND * DH]; // split-K partials
// bf16 hi/lo staging
__device__ __nv_bfloat16 g_AH[NP * INDIM];       // LN output / out-proj staging
__device__ __nv_bfloat16 g_AL[NP * INDIM];
__device__ __nv_bfloat16 g_QKH[2 * NHEADS * NP * DH];  // Q then K, per-head hi
__device__ __nv_bfloat16 g_QKL[2 * NHEADS * NP * DH];  // Q then K, per-head lo
__device__ __nv_bfloat16 g_WH[3 * DMODEL * DMODEL];
__device__ __nv_bfloat16 g_WL[3 * DMODEL * DMODEL];
__device__ __nv_bfloat16 g_QLH[NHEADS * MLAND * DH];
__device__ __nv_bfloat16 g_QLL[NHEADS * MLAND * DH];
__device__ __nv_bfloat16 g_KLH[NHEADS * MLAND * DH];
__device__ __nv_bfloat16 g_KLL[NHEADS * MLAND * DH];
__device__ __nv_bfloat16 g_VH [NHEADS * NP * DH];
__device__ __nv_bfloat16 g_VL [NHEADS * NP * DH];
__device__ __nv_bfloat16 g_PH [NHEADS * NP * MLAND];
__device__ __nv_bfloat16 g_PL [NHEADS * NP * MLAND];
__device__ __nv_bfloat16 g_BmH[NHEADS * MLAND * DH];
__device__ __nv_bfloat16 g_BmL[NHEADS * MLAND * DH];

#define QKOFF (NHEADS * NP * DH)

// ---------------------------------------------------------------------------
// warp-mma helpers (sm_80+ PTX)
// ---------------------------------------------------------------------------
__device__ __forceinline__ uint32_t smem_u32(const void* p)
{
    uint32_t a;
    asm("{ .reg .u64 t; cvta.to.shared.u64 t, %1; cvt.u32.u64 %0, t; }" : "=r"(a) : "l"(p));
    return a;
}
__device__ __forceinline__ void ldsm_x4(uint32_t* r, uint32_t addr)
{
    asm volatile("ldmatrix.sync.aligned.m8n8.x4.shared.b16 {%0,%1,%2,%3}, [%4];"
                 : "=r"(r[0]), "=r"(r[1]), "=r"(r[2]), "=r"(r[3]) : "r"(addr));
}
__device__ __forceinline__ void ldsm_x2(uint32_t* r, uint32_t addr)
{
    asm volatile("ldmatrix.sync.aligned.m8n8.x2.shared.b16 {%0,%1}, [%2];"
                 : "=r"(r[0]), "=r"(r[1]) : "r"(addr));
}
__device__ __forceinline__ void ldsm_x2_trans(uint32_t* r, uint32_t addr)
{
    asm volatile("ldmatrix.sync.aligned.m8n8.x2.trans.shared.b16 {%0,%1}, [%2];"
                 : "=r"(r[0]), "=r"(r[1]) : "r"(addr));
}
__device__ __forceinline__ void mma_bf16(float* d, const uint32_t* a, const uint32_t* b)
{
    asm volatile("mma.sync.aligned.m16n8k16.row.col.f32.bf16.bf16.f32 "
                 "{%0,%1,%2,%3}, {%4,%5,%6,%7}, {%8,%9}, {%0,%1,%2,%3};"
                 : "+f"(d[0]), "+f"(d[1]), "+f"(d[2]), "+f"(d[3])
                 : "r"(a[0]), "r"(a[1]), "r"(a[2]), "r"(a[3]), "r"(b[0]), "r"(b[1]));
}
__device__ __forceinline__ void cp_async16(uint32_t smem_addr, const void* gptr)
{
    asm volatile("cp.async.ca.shared.global [%0], [%1], 16;"
                 :: "r"(smem_addr), "l"(gptr));
}
__device__ __forceinline__ void cp_commit()
{
    asm volatile("cp.async.commit_group;" ::: "memory");
}
__device__ __forceinline__ void cp_wait1()
{
    asm volatile("cp.async.wait_group 1;" ::: "memory");
}

// ---------------------------------------------------------------------------
// Weight convert+transpose: W [K][N] f32 -> Whi/Wlo [N][K] bf16
// ---------------------------------------------------------------------------
__global__ void wconv_kernel(const float* __restrict__ W,
                             __nv_bfloat16* __restrict__ Whi, __nv_bfloat16* __restrict__ Wlo,
                             int K, int N)
{
    __shared__ float tl[32][33];
    int kb = blockIdx.y * 32, nb = blockIdx.x * 32;
    int t = threadIdx.x;
    for (int i = t; i < 1024; i += 256) {
        int r = i >> 5, c = i & 31;
        tl[r][c] = W[(size_t)(kb + r) * N + nb + c];
    }
    __syncthreads();
    for (int i = t; i < 1024; i += 256) {
        int n = i >> 5, k = i & 31;
        float v = tl[k][n];
        __nv_bfloat16 h = __float2bfloat16(v);
        float lo = v - __bfloat162float(h);
        size_t o = (size_t)(nb + n) * K + kb + k;
        Whi[o] = h;
        Wlo[o] = __float2bfloat16(lo);
    }
}

// ---------------------------------------------------------------------------
// Activation convert (f32 -> hi/lo bf16, zero pad rows)
// ---------------------------------------------------------------------------
__global__ void aconv_kernel(const float* __restrict__ A,
                             __nv_bfloat16* __restrict__ Ahi, __nv_bfloat16* __restrict__ Alo,
                             int Min, int Kn)
{
    int r = blockIdx.x;
    size_t base = (size_t)r * Kn;
    if (r >= Min) {
        __nv_bfloat162 z = __float2bfloat162_rn(0.f);
        for (int c = threadIdx.x * 2; c < Kn; c += 256) {
            *reinterpret_cast<__nv_bfloat162*>(Ahi + base + c) = z;
            *reinterpret_cast<__nv_bfloat162*>(Alo + base + c) = z;
        }
        return;
    }
    for (int c = threadIdx.x * 2; c < Kn; c += 256) {
        float2 v = *reinterpret_cast<const float2*>(A + base + c);
        __nv_bfloat16 h0 = __float2bfloat16(v.x);
        __nv_bfloat16 h1 = __float2bfloat16(v.y);
        float l0 = v.x - __bfloat162float(h0);
        float l1 = v.y - __bfloat162float(h1);
        __nv_bfloat162 hp; hp.x = h0; hp.y = h1;
        __nv_bfloat162 lp; lp.x = __float2bfloat16(l0); lp.y = __float2bfloat16(l1);
        *reinterpret_cast<__nv_bfloat162*>(Ahi + base + c) = hp;
        *reinterpret_cast<__nv_bfloat162*>(Alo + base + c) = lp;
    }
}

// ---------------------------------------------------------------------------
// Fused LayerNorm + bf16 hi/lo conversion: H -> AH/AL (padded rows = 0)
// ---------------------------------------------------------------------------
__global__ void lnconv_kernel(const float* __restrict__ Hin,
                              __nv_bfloat16* __restrict__ Ahi, __nv_bfloat16* __restrict__ Alo,
                              const float* __restrict__ g, const float* __restrict__ b)
{
    int row = blockIdx.x;
    int tid = threadIdx.x;
    size_t base = (size_t)row * DMODEL;
    if (row < PADF) {
        __nv_bfloat16 z = __float2bfloat16(0.f);
        Ahi[base + tid] = z; Ahi[base + tid + 256] = z;
        Alo[base + tid] = z; Alo[base + tid + 256] = z;
        return;
    }
    const float* x = Hin + (size_t)(row - PADF) * DMODEL;
    float v0 = x[tid], v1 = x[tid + 256];
    __shared__ float s1[256], s2[256];
    s1[tid] = v0 + v1;
    s2[tid] = v0 * v0 + v1 * v1;
    __syncthreads();
    for (int o = 128; o > 0; o >>= 1) {
        if (tid < o) { s1[tid] += s1[tid + o]; s2[tid] += s2[tid + o]; }
        __syncthreads();
    }
    float mean = s1[0] * (1.f / DMODEL);
    float var  = s2[0] * (1.f / DMODEL) - mean * mean;
    float rs = rsqrtf(var + EPSLN);
    float y0 = (v0 - mean) * rs * g[tid] + b[tid];
    float y1 = (v1 - mean) * rs * g[tid + 256] + b[tid + 256];
    __nv_bfloat16 h0 = __float2bfloat16(y0);
    __nv_bfloat16 h1 = __float2bfloat16(y1);
    Ahi[base + tid]       = h0;
    Ahi[base + tid + 256] = h1;
    Alo[base + tid]       = __float2bfloat16(y0 - __bfloat162float(h0));
    Alo[base + tid + 256] = __float2bfloat16(y1 - __bfloat162float(h1));
}

// ---------------------------------------------------------------------------
// warp-MMA GEMM with cp.async double-buffered K-chunks of 32.
// C[M][N] = op(A @ B^T); 128x128 CTA tile, 8 warps (4x2).
// FLAG_SPLIT: write per-head bf16 hi/lo (QK into QKH/QKL, V into VH/VL)
// ---------------------------------------------------------------------------
#define TCP_STR  40                         // bf16 row stride (80 B, 16B-aligned)
#define TCP_BUF  (4 * 128 * TCP_STR)        // elements per buffer (20480)
#define TCG_SMEM (2 * TCP_BUF * 2)          // 81920 bytes

__global__ void __launch_bounds__(256)
tc_gemm_kernel(const __nv_bfloat16* __restrict__ Ahi, const __nv_bfloat16* __restrict__ Alo,
               const __nv_bfloat16* __restrict__ Bhi, const __nv_bfloat16* __restrict__ Blo,
               float* __restrict__ C, const float* __restrict__ bias,
               __nv_bfloat16* __restrict__ QKH, __nv_bfloat16* __restrict__ QKL,
               __nv_bfloat16* __restrict__ VH, __nv_bfloat16* __restrict__ VL,
               int Mn, int Nn, int Kn, int flags, int scale_cols, float scale)
{
    extern __shared__ __nv_bfloat16 smb[];
    const int t = threadIdx.x, lane = t & 31, wid = t >> 5;
    const int m0 = blockIdx.y * 128, n0 = blockIdx.x * 128;
    const int wm = (wid & 3) * 32;
    const int wn = (wid >> 2) * 64;

    const uint32_t smem_base = smem_u32(smb);

    const int a_row = (lane & 7) + ((lane >> 3) & 1) * 8;
    const int a_col = (lane >> 4) * 8;
    const int b_row = lane & 7;
    const int b_col = ((lane >> 3) & 1) * 8;

    const int nchunks = Kn >> 5;

    const int r1 = t >> 2,        kg1 = (t & 3) << 3;
    const int r2 = (t >> 2) + 64, kg2 = kg1;

    auto issue = [&](int ci, int buf) {
        int k0 = ci << 5;
        uint32_t bb = smem_base + (uint32_t)buf * TCP_BUF * 2;
        const __nv_bfloat16* gsrc[4] = {
            Ahi + (size_t)m0 * Kn, Alo + (size_t)m0 * Kn,
            Bhi + (size_t)n0 * Kn, Blo + (size_t)n0 * Kn };
#pragma unroll
        for (int arr = 0; arr < 4; arr++) {
            uint32_t sb = bb + (uint32_t)arr * 128 * TCP_STR * 2;
            cp_async16(sb + (uint32_t)(r1 * TCP_STR + kg1) * 2,
                       gsrc[arr] + (size_t)r1 * Kn + k0 + kg1);
            cp_async16(sb + (uint32_t)(r2 * TCP_STR + kg2) * 2,
                       gsrc[arr] + (size_t)r2 * Kn + k0 + kg2);
        }
    };

    float acc[2][8][4];
#pragma unroll
    for (int i = 0; i < 2; i++)
#pragma unroll
        for (int j = 0; j < 8; j++)
#pragma unroll
            for (int k = 0; k < 4; k++) acc[i][j][k] = 0.f;

    issue(0, 0); cp_commit();
    if (nchunks > 1) issue(1, 1);
    cp_commit();

    for (int ci = 0; ci < nchunks; ci++) {
        cp_wait1();
        __syncthreads();
        const int buf = ci & 1;
        uint32_t bb = smem_base + (uint32_t)buf * TCP_BUF * 2;
        uint32_t sAh_u = bb;
        uint32_t sAl_u = bb + 128 * TCP_STR * 2;
        uint32_t sBh_u = bb + 2 * 128 * TCP_STR * 2;
        uint32_t sBl_u = bb + 3 * 128 * TCP_STR * 2;
#pragma unroll
        for (int ks = 0; ks < 2; ks++) {
            const int kl = ks * 16;
            uint32_t ah[2][4], al[2][4];
#pragma unroll
            for (int mt = 0; mt < 2; mt++) {
                uint32_t off = (uint32_t)((wm + mt * 16 + a_row) * TCP_STR + kl + a_col) * 2;
                ldsm_x4(ah[mt], sAh_u + off);
                ldsm_x4(al[mt], sAl_u + off);
            }
#pragma unroll
            for (int ng = 0; ng < 2; ng++) {
                uint32_t bh[4][2], bl[4][2];
#pragma unroll
                for (int nt = 0; nt < 4; nt++) {
                    uint32_t off = (uint32_t)((wn + ng * 32 + nt * 8 + b_row) * TCP_STR + kl + b_col) * 2;
                    ldsm_x2(bh[nt], sBh_u + off);
                    ldsm_x2(bl[nt], sBl_u + off);
                }
#pragma unroll
                for (int mt = 0; mt < 2; mt++)
#pragma unroll
                    for (int nt = 0; nt < 4; nt++) {
                        float* d = acc[mt][ng * 4 + nt];
                        mma_bf16(d, ah[mt], bh[nt]);
                        mma_bf16(d, ah[mt], bl[nt]);
                        mma_bf16(d, al[mt], bh[nt]);
                    }
            }
        }
        __syncthreads();
        if (ci + 2 < nchunks) issue(ci + 2, buf);
        cp_commit();
    }

    const bool relu  = (flags & FLAG_RELU) != 0;
    const bool accu  = (flags & FLAG_ACC) != 0;
    const bool split = (flags & FLAG_SPLIT) != 0;
#pragma unroll
    for (int mt = 0; mt < 2; mt++) {
        int rbase = m0 + wm + mt * 16 + (lane >> 2);
#pragma unroll
        for (int nt = 0; nt < 8; nt++) {
            int c0 = n0 + wn + nt * 8 + (lane & 3) * 2;
#pragma unroll
            for (int half = 0; half < 2; half++) {
                int row = rbase + half * 8;
                if (row >= Mn) continue;
                float v0 = acc[mt][nt][half * 2 + 0];
                float v1 = acc[mt][nt][half * 2 + 1];
                if (c0 < scale_cols)     v0 *= scale;
                if (c0 + 1 < scale_cols) v1 *= scale;
                if (split) {
                    int part = c0 >> 9;
                    int h = (c0 >> 6) & 7;
                    int d = c0 & 63;
                    size_t o = (size_t)h * NP * DH + (size_t)row * DH + d;
                    __nv_bfloat16 h0 = __float2bfloat16(v0);
                    __nv_bfloat16 h1 = __float2bfloat16(v1);
                    __nv_bfloat162 hp; hp.x = h0; hp.y = h1;
                    __nv_bfloat162 lp;
                    lp.x = __float2bfloat16(v0 - __bfloat162float(h0));
                    lp.y = __float2bfloat16(v1 - __bfloat162float(h1));
                    if (part < 2) {
                        *reinterpret_cast<__nv_bfloat162*>(QKH + (size_t)part * QKOFF + o) = hp;
                        *reinterpret_cast<__nv_bfloat162*>(QKL + (size_t)part * QKOFF + o) = lp;
                    } else {
                        *reinterpret_cast<__nv_bfloat162*>(VH + o) = hp;
                        *reinterpret_cast<__nv_bfloat162*>(VL + o) = lp;
                    }
                    continue;
                }
                if (bias) { v0 += bias[c0]; v1 += bias[c0 + 1]; }
                if (relu) { v0 = fmaxf(v0, 0.f); v1 = fmaxf(v1, 0.f); }
                size_t o = (size_t)row * Nn + c0;
                if (accu) { C[o] += v0; C[o + 1] += v1; }
                else      { C[o] = v0;  C[o + 1] = v1; }
            }
        }
    }
}

// ---------------------------------------------------------------------------
// Batched logits MMA (K=64, one chunk): C[b][m][n] = A[b] @ B[b]^T
// ---------------------------------------------------------------------------
#define TCB_STR  72
#define SLOG_SMEM (4 * 128 * TCB_STR * 2)   // 73728 bytes

__global__ void __launch_bounds__(256)
slogits_kernel(const __nv_bfloat16* __restrict__ Ahi, const __nv_bfloat16* __restrict__ Alo,
               const __nv_bfloat16* __restrict__ Bhi, const __nv_bfloat16* __restrict__ Blo,
               float* __restrict__ C,
               size_t strideA, size_t strideB, size_t strideC, int ldc)
{
    extern __shared__ __nv_bfloat16 smb[];
    __nv_bfloat16* sAh = smb;
    __nv_bfloat16* sAl = smb + 128 * TCB_STR;
    __nv_bfloat16* sBh = smb + 2 * 128 * TCB_STR;
    __nv_bfloat16* sBl = smb + 3 * 128 * TCB_STR;

    const int t = threadIdx.x, lane = t & 31, wid = t >> 5;
    const int m0 = blockIdx.y * 128, n0 = blockIdx.x * 128;
    const int b = blockIdx.z;
    const __nv_bfloat16* Ah = Ahi + (size_t)b * strideA;
    const __nv_bfloat16* Al = Alo + (size_t)b * strideA;
    const __nv_bfloat16* Bh = Bhi + (size_t)b * strideB;
    const __nv_bfloat16* Bl = Blo + (size_t)b * strideB;
    float* Cb = C + (size_t)b * strideC;

    const int wm = (wid & 3) * 32;
    const int wn = (wid >> 2) * 64;

    const uint32_t sAh_u = smem_u32(sAh), sAl_u = smem_u32(sAl);
    const uint32_t sBh_u = smem_u32(sBh), sBl_u = smem_u32(sBl);

    const int a_row = (lane & 7) + ((lane >> 3) & 1) * 8;
    const int a_col = (lane >> 4) * 8;
    const int b_row = lane & 7;
    const int b_col = ((lane >> 3) & 1) * 8;

    float acc[2][8][4];
#pragma unroll
    for (int i = 0; i < 2; i++)
#pragma unroll
        for (int j = 0; j < 8; j++)
#pragma unroll
            for (int k = 0; k < 4; k++) acc[i][j][k] = 0.f;

    for (int i = t; i < 1024; i += 256) {
        int r = i >> 3, kg = (i & 7) << 3;
        int off = r * TCB_STR + kg;
        size_t ga = (size_t)(m0 + r) * DH + kg;
        size_t gb = (size_t)(n0 + r) * DH + kg;
        *reinterpret_cast<uint4*>(sAh + off) = *reinterpret_cast<const uint4*>(Ah + ga);
        *reinterpret_cast<uint4*>(sAl + off) = *reinterpret_cast<const uint4*>(Al + ga);
        *reinterpret_cast<uint4*>(sBh + off) = *reinterpret_cast<const uint4*>(Bh + gb);
        *reinterpret_cast<uint4*>(sBl + off) = *reinterpret_cast<const uint4*>(Bl + gb);
    }
    __syncthreads();
#pragma unroll
    for (int ks = 0; ks < 4; ks++) {
        const int kl = ks * 16;
        uint32_t ah[2][4], al[2][4];
#pragma unroll
        for (int mt = 0; mt < 2; mt++) {
            uint32_t off = (uint32_t)((wm + mt * 16 + a_row) * TCB_STR + kl + a_col) * 2;
            ldsm_x4(ah[mt], sAh_u + off);
            ldsm_x4(al[mt], sAl_u + off);
        }
#pragma unroll
        for (int ng = 0; ng < 2; ng++) {
            uint32_t bh[4][2], bl[4][2];
#pragma unroll
            for (int nt = 0; nt < 4; nt++) {
                uint32_t off = (uint32_t)((wn + ng * 32 + nt * 8 + b_row) * TCB_STR + kl + b_col) * 2;
                ldsm_x2(bh[nt], sBh_u + off);
                ldsm_x2(bl[nt], sBl_u + off);
            }
#pragma unroll
            for (int mt = 0; mt < 2; mt++)
#pragma unroll
                for (int nt = 0; nt < 4; nt++) {
                    float* d = acc[mt][nt + ng * 4];
                    mma_bf16(d, ah[mt], bh[nt]);
                    mma_bf16(d, ah[mt], bl[nt]);
                    mma_bf16(d, al[mt], bh[nt]);
                }
        }
    }

#pragma unroll
    for (int mt = 0; mt < 2; mt++) {
        int rbase = m0 + wm + mt * 16 + (lane >> 2);
#pragma unroll
        for (int nt = 0; nt < 8; nt++) {
            int c0 = n0 + wn + nt * 8 + (lane & 3) * 2;
#pragma unroll
            for (int half = 0; half < 2; half++) {
                int row = rbase + half * 8;
                size_t o = (size_t)row * ldc + c0;
                Cb[o]     = acc[mt][nt][half * 2 + 0];
                Cb[o + 1] = acc[mt][nt][half * 2 + 1];
            }
        }
    }
}

// ---------------------------------------------------------------------------
// pgemm with cp.async double-buffered K-chunks of 32
// ---------------------------------------------------------------------------
#define PGP_PSTR 40
#define PGP_BSTR 72
#define PGP_PL   (128 * PGP_PSTR)
#define PGP_BH   (2 * 128 * PGP_PSTR)
#define PGP_BL   (PGP_BH + 32 * PGP_BSTR)
#define PGP_BUF  (PGP_BL + 32 * PGP_BSTR)
#define PG_SMEM  (2 * PGP_BUF * 2)

__global__ void __launch_bounds__(256)
pgemm_kernel(const __nv_bfloat16* __restrict__ Phi, const __nv_bfloat16* __restrict__ Plo,
             const __nv_bfloat16* __restrict__ Bhi, const __nv_bfloat16* __restrict__ Blo,
             float* __restrict__ Cout,
             int Pld, size_t pHeadStride, size_t bHeadStride,
             int chunksPerSlice, int mode)
{
    extern __shared__ __nv_bfloat16 smb[];
    const int t = threadIdx.x, lane = t & 31, wid = t >> 5;
    const int m0 = blockIdx.x * 128;
    const int kslice = blockIdx.y;
    const int head = blockIdx.z;

    const int c0 = kslice * chunksPerSlice;
    const int nch = chunksPerSlice;

    const __nv_bfloat16* Ph = Phi + (size_t)head * pHeadStride;
    const __nv_bfloat16* Pl = Plo + (size_t)head * pHeadStride;
    const __nv_bfloat16* Bh = Bhi + (size_t)head * bHeadStride;
    const __nv_bfloat16* Bl = Blo + (size_t)head * bHeadStride;

    const int wm = (wid & 3) * 32;
    const int wn = (wid >> 2) * 32;

    const uint32_t smem_base = smem_u32(smb);

    const int a_row = (lane & 7) + ((lane >> 3) & 1) * 8;
    const int a_col = (lane >> 4) * 8;
    const int bt_k = lane & 15;

    const int pr = t >> 2, pkg = (t & 3) << 3;
    const int br = t >> 3, bcg = (t & 7) << 3;

    auto issue = [&](int ci, int buf) {
        int k0 = ci << 5;
        uint32_t bb = smem_base + (uint32_t)buf * PGP_BUF * 2;
        cp_async16(bb + (uint32_t)(pr * PGP_PSTR + pkg) * 2,
                   Ph + (size_t)(m0 + pr) * Pld + k0 + pkg);
        cp_async16(bb + (uint32_t)((pr + 64) * PGP_PSTR + pkg) * 2,
                   Ph + (size_t)(m0 + pr + 64) * Pld + k0 + pkg);
        uint32_t pl = bb + PGP_PL * 2;
        cp_async16(pl + (uint32_t)(pr * PGP_PSTR + pkg) * 2,
                   Pl + (size_t)(m0 + pr) * Pld + k0 + pkg);
        cp_async16(pl + (uint32_t)((pr + 64) * PGP_PSTR + pkg) * 2,
                   Pl + (size_t)(m0 + pr + 64) * Pld + k0 + pkg);
        uint32_t bhh = bb + PGP_BH * 2;
        uint32_t bll = bb + PGP_BL * 2;
        cp_async16(bhh + (uint32_t)(br * PGP_BSTR + bcg) * 2,
                   Bh + (size_t)(k0 + br) * 64 + bcg);
        cp_async16(bll + (uint32_t)(br * PGP_BSTR + bcg) * 2,
                   Bl + (size_t)(k0 + br) * 64 + bcg);
    };

    float acc[2][4][4];
#pragma unroll
    for (int i = 0; i < 2; i++)
#pragma unroll
        for (int j = 0; j < 4; j++)
#pragma unroll
            for (int k = 0; k < 4; k++) acc[i][j][k] = 0.f;

    issue(c0, 0); cp_commit();
    if (nch > 1) issue(c0 + 1, 1);
    cp_commit();

    for (int ci = 0; ci < nch; ci++) {
        cp_wait1();
        __syncthreads();
        const int buf = ci & 1;
        uint32_t bb = smem_base + (uint32_t)buf * PGP_BUF * 2;
        uint32_t sPh_u = bb;
        uint32_t sPl_u = bb + PGP_PL * 2;
        uint32_t sBh_u = bb + PGP_BH * 2;
        uint32_t sBl_u = bb + PGP_BL * 2;
#pragma unroll
        for (int ks = 0; ks < 2; ks++) {
            const int kl = ks * 16;
            uint32_t ph[2][4], pl2[2][4];
#pragma unroll
            for (int mt = 0; mt < 2; mt++) {
                uint32_t off = (uint32_t)((wm + mt * 16 + a_row) * PGP_PSTR + kl + a_col) * 2;
                ldsm_x4(ph[mt], sPh_u + off);
                ldsm_x4(pl2[mt], sPl_u + off);
            }
            uint32_t bh[4][2], bl[4][2];
#pragma unroll
            for (int nt = 0; nt < 4; nt++) {
                uint32_t off = (uint32_t)((kl + bt_k) * PGP_BSTR + wn + nt * 8) * 2;
                ldsm_x2_trans(bh[nt], sBh_u + off);
                ldsm_x2_trans(bl[nt], sBl_u + off);
            }
#pragma unroll
            for (int mt = 0; mt < 2; mt++)
#pragma unroll
                for (int nt = 0; nt < 4; nt++) {
                    float* d = acc[mt][nt];
                    mma_bf16(d, ph[mt], bh[nt]);
                    mma_bf16(d, ph[mt], bl[nt]);
                    mma_bf16(d, pl2[mt], bh[nt]);
                }
        }
        __syncthreads();
        if (ci + 2 < nch) issue(c0 + ci + 2, buf);
        cp_commit();
    }

#pragma unroll
    for (int mt = 0; mt < 2; mt++) {
        int rbase = m0 + wm + mt * 16 + (lane >> 2);
#pragma unroll
        for (int nt = 0; nt < 4; nt++) {
            int c0c = wn + nt * 8 + (lane & 3) * 2;
#pragma unroll
            for (int half = 0; half < 2; half++) {
                int row = rbase + half * 8;
                float v0 = acc[mt][nt][half * 2 + 0];
                float v1 = acc[mt][nt][half * 2 + 1];
                if (mode == 0) {
                    size_t o = (((size_t)kslice * NHEADS + head) * MLAND + row) * 64 + c0c;
                    Cout[o] = v0; Cout[o + 1] = v1;
                } else {
                    size_t o = (size_t)row * DMODEL + head * 64 + c0c;
                    Cout[o] = v0; Cout[o + 1] = v1;
                }
            }
        }
    }
}

// ---------------------------------------------------------------------------
// split-K reduction: A3V = sum over 8 slices
// ---------------------------------------------------------------------------
__global__ void pvred_kernel(const float* __restrict__ PVP, float* __restrict__ A3V)
{
    int h = blockIdx.x & 7, seg = blockIdx.x >> 3;
    int idx = seg * 2048 + threadIdx.x * 8;
    for (int j = 0; j < 8; j++) {
        int li = idx + j;
        float s = 0.f;
#pragma unroll
        for (int sl = 0; sl < 8; sl++)
            s += PVP[(((size_t)sl * NHEADS + h) * MLAND * 64) + li];
        A3V[(size_t)h * MLAND * 64 + li] = s;
    }
}

// ---------------------------------------------------------------------------
// p3 softmax: S3 [h][m][NP] -> normalized P hi/lo (block per row)
// ---------------------------------------------------------------------------
__global__ void p3_kernel(const float* __restrict__ S,
                          __nv_bfloat16* __restrict__ PH, __nv_bfloat16* __restrict__ PL)
{
    int m = blockIdx.x, h = blockIdx.y;
    int t = threadIdx.x;
    const float* row = S + ((size_t)h * MLAND + m) * NP;
    float vals[33];
    float mx = -1e30f;
#pragma unroll
    for (int i = 0; i < 33; i++) {
        vals[i] = row[i * 256 + t];
        mx = fmaxf(mx, vals[i]);
    }
    __shared__ float red[256];
    red[t] = mx; __syncthreads();
    for (int o = 128; o > 0; o >>= 1) {
        if (t < o) red[t] = fmaxf(red[t], red[t + o]);
        __syncthreads();
    }
    mx = red[0]; __syncthreads();
    float sum = 0.f;
#pragma unroll
    for (int i = 0; i < 33; i++) {
        vals[i] = __expf(vals[i] - mx);
        sum += vals[i];
    }
    red[t] = sum; __syncthreads();
    for (int o = 128; o > 0; o >>= 1) {
        if (t < o) red[t] += red[t + o];
        __syncthreads();
    }
    float inv = 1.0f / red[0];
    __nv_bfloat16* ph = PH + ((size_t)h * MLAND + m) * NP;
    __nv_bfloat16* pl = PL + ((size_t)h * MLAND + m) * NP;
#pragma unroll
    for (int i = 0; i < 33; i++) {
        float p = vals[i] * inv;
        __nv_bfloat16 hi = __float2bfloat16(p);
        ph[i * 256 + t] = hi;
        pl[i * 256 + t] = __float2bfloat16(p - __bfloat162float(hi));
    }
}

// ---------------------------------------------------------------------------
// p1 softmax: S1 [h][n][256] -> normalized P hi/lo (warp per row)
// ---------------------------------------------------------------------------
__global__ void p1_kernel(const float* __restrict__ S,
                          __nv_bfloat16* __restrict__ PH, __nv_bfloat16* __restrict__ PL)
{
    int row = blockIdx.x * 8 + (threadIdx.x >> 5);
    int lane = threadIdx.x & 31;
    const float* r = S + (size_t)row * MLAND;
    float a[8];
#pragma unroll
    for (int k = 0; k < 8; k++) a[k] = r[lane + k * 32];
    float m = a[0];
#pragma unroll
    for (int k = 1; k < 8; k++) m = fmaxf(m, a[k]);
    for (int o = 16; o > 0; o >>= 1) m = fmaxf(m, __shfl_xor_sync(0xffffffffu, m, o));
    float s = 0.f;
#pragma unroll
    for (int k = 0; k < 8; k++) { a[k] = __expf(a[k] - m); s += a[k]; }
    for (int o = 16; o > 0; o >>= 1) s += __shfl_xor_sync(0xffffffffu, s, o);
    float inv = 1.0f / s;
    __nv_bfloat16* ph = PH + (size_t)row * MLAND;
    __nv_bfloat16* pl = PL + (size_t)row * MLAND;
#pragma unroll
    for (int k = 0; k < 8; k++) {
        float p = a[k] * inv;
        __nv_bfloat16 hi = __float2bfloat16(p);
        ph[lane + k * 32] = hi;
        pl[lane + k * 32] = __float2bfloat16(p - __bfloat162float(hi));
    }
}

// ---------------------------------------------------------------------------
// Assemble h rows: cls + wrap
// ---------------------------------------------------------------------------
__global__ void assemble_kernel(const float* __restrict__ cls, float* __restrict__ H)
{
    int j = blockIdx.x;
    int c = threadIdx.x;
    if (j == 0) H[c] = cls[c];
    else        H[(size_t)(NTOK + j) * DMODEL + c] = H[(size_t)j * DMODEL + c];
}

// ---------------------------------------------------------------------------
// Landmarks from per-head Q/K hi/lo: means of 33-groups
// ---------------------------------------------------------------------------
__global__ void landmarks_kernel(const __nv_bfloat16* __restrict__ QKH,
                                 const __nv_bfloat16* __restrict__ QKL,
                                 float* __restrict__ QL, float* __restrict__ KL,
                                 __nv_bfloat16* __restrict__ QLH, __nv_bfloat16* __restrict__ QLL,
                                 __nv_bfloat16* __restrict__ KLH, __nv_bfloat16* __restrict__ KLL)
{
    int hm = blockIdx.x;
    int h = hm >> 8, m = hm & 255;
    int tid = threadIdx.x;
    int d = tid & 63;
    int part = (tid < 64) ? 0 : 1;   // 0 = q, 1 = k
    size_t base = (size_t)part * QKOFF + (size_t)h * NP * DH + (size_t)(m * LWIN) * DH + d;
    float s = 0.f;
#pragma unroll
    for (int j = 0; j < LWIN; j++) {
        size_t idx = base + (size_t)j * DH;
        s += __bfloat162float(QKH[idx]) + __bfloat162float(QKL[idx]);
    }
    s *= (1.0f / LWIN);
    __nv_bfloat16 hi = __float2bfloat16(s);
    __nv_bfloat16 lo = __float2bfloat16(s - __bfloat162float(hi));
    size_t o = (size_t)(h * MLAND + m) * DH + d;
    if (part == 0) {
        QL[o] = s; QLH[o] = hi; QLL[o] = lo;
    } else {
        KL[o] = s; KLH[o] = hi; KLL[o] = lo;
    }
}

// ---------------------------------------------------------------------------
// a2 = softmax(q_l @ k_l^T)
// ---------------------------------------------------------------------------
__global__ void a2_kernel(const float* __restrict__ QL, const float* __restrict__ KL,
                          float* __restrict__ A2)
{
    int m = blockIdx.x, h = blockIdx.y;
    int tid = threadIdx.x;
    __shared__ float q[64];
    __shared__ float red[256];
    if (tid < 64) q[tid] = QL[(size_t)(h * MLAND + m) * DH + tid];
    __syncthreads();
    const float* kr = KL + (size_t)(h * MLAND + tid) * DH;
    float s = 0.f;
#pragma unroll
    for (int i = 0; i < 16; i++) {
        float4 kv = reinterpret_cast<const float4*>(kr)[i];
        float4 qv = reinterpret_cast<const float4*>(q)[i];
        s += kv.x * qv.x + kv.y * qv.y + kv.z * qv.z + kv.w * qv.w;
    }
    red[tid] = s; __syncthreads();
    for (int o = 128; o > 0; o >>= 1) {
        if (tid < o) red[tid] = fmaxf(red[tid], red[tid + o]);
        __syncthreads();
    }
    float mx = red[0]; __syncthreads();
    float e = __expf(s - mx);
    red[tid] = e; __syncthreads();
    for (int o = 128; o > 0; o >>= 1) {
        if (tid < o) red[tid] += red[tid + o];
        __syncthreads();
    }
    float sm = red[0];
    A2[(size_t)(h * MLAND + m) * MLAND + tid] = e / sm;
}

// ---------------------------------------------------------------------------
// pinv chain
// ---------------------------------------------------------------------------
__global__ void pinv_scale_kernel(const float* __restrict__ A2, float* __restrict__ PS)
{
    int h = blockIdx.x;
    int t = threadIdx.x;
    int w = t >> 5, lane = t & 31;
    const float* Ah = A2 + (size_t)h * 65536;
    __shared__ float rs[256];
    __shared__ float cs2[256];
    for (int r = w; r < 256; r += 8) {
        float s = 0.f;
        for (int j = lane; j < 256; j += 32) s += fabsf(Ah[r * 256 + j]);
        for (int o = 16; o > 0; o >>= 1) s += __shfl_xor_sync(0xffffffffu, s, o);
        if (lane == 0) rs[r] = s;
    }
    float cs = 0.f;
    for (int i = 0; i < 256; i++) cs += fabsf(Ah[i * 256 + t]);
    cs2[t] = cs;
    __syncthreads();
    for (int o = 128; o > 0; o >>= 1) {
        if (t < o) { rs[t] = fmaxf(rs[t], rs[t + o]); cs2[t] = fmaxf(cs2[t], cs2[t + o]); }
        __syncthreads();
    }
    if (t == 0) PS[h] = 1.0f / (rs[0] * cs2[0]);
}

__global__ void pinv_tr_kernel(const float* __restrict__ A2, const float* __restrict__ PS,
                               float* __restrict__ Z0)
{
    __shared__ float tl[64][65];
    int h = blockIdx.y;
    int seg = blockIdx.x;
    int bi = (seg >> 2) * 64, bj = (seg & 3) * 64;
    int t = threadIdx.x;
    float inv = PS[h];
    const float* Ah = A2 + (size_t)h * 65536;
    float* Zh = Z0 + (size_t)h * 65536;
    for (int lin = t; lin < 4096; lin += 256) {
        int r = lin >> 6, c = lin & 63;
        tl[r][c] = Ah[(size_t)(bi + r) * 256 + bj + c];
    }
    __syncthreads();
    for (int lin = t; lin < 4096; lin += 256) {
        int r = lin >> 6, c = lin & 63;
        Zh[(size_t)(bj + r) * 256 + bi + c] = tl[c][r] * inv;
    }
}

__global__ void nk256_kernel(const float* __restrict__ A, const float* __restrict__ B,
                             float* __restrict__ C, float alpha, float gamma)
{
    const float* Ah = A + (size_t)blockIdx.z * 65536;
    const float* Bh = B + (size_t)blockIdx.z * 65536;
    float* Ch = C + (size_t)blockIdx.z * 65536;
    __shared__ float As[16][64];
    __shared__ float Bs[16][64];
    const int bm = blockIdx.y * 64;
    const int bn = blockIdx.x * 64;
    const int tid = threadIdx.x;
    const int tx = tid & 15, ty = tid >> 4;
    const int row0 = ty * 4, col0 = tx * 4;
    float acc[4][4];
#pragma unroll
    for (int i = 0; i < 4; i++)
#pragma unroll
        for (int j = 0; j < 4; j++) acc[i][j] = 0.f;

    for (int k0 = 0; k0 < 256; k0 += 16) {
        {
            int ar = tid >> 2;
            int ac = (tid & 3) << 2;
            float4 v = *reinterpret_cast<const float4*>(Ah + (size_t)(bm + ar) * 256 + k0 + ac);
            As[ac + 0][ar] = v.x; As[ac + 1][ar] = v.y;
            As[ac + 2][ar] = v.z; As[ac + 3][ar] = v.w;
        }
        {
            int br = tid >> 4;
            int bc = (tid & 15) << 2;
            float4 v = *reinterpret_cast<const float4*>(Bh + (size_t)(k0 + br) * 256 + bn + bc);
            *reinterpret_cast<float4*>(&Bs[br][bc]) = v;
        }
        __syncthreads();
#pragma unroll
        for (int k = 0; k < 16; k++) {
            float a[4], b[4];
            *reinterpret_cast<float4*>(a) = *reinterpret_cast<const float4*>(&As[k][row0]);
            *reinterpret_cast<float4*>(b) = *reinterpret_cast<const float4*>(&Bs[k][col0]);
#pragma unroll
            for (int i = 0; i < 4; i++)
#pragma unroll
                for (int j = 0; j < 4; j++) acc[i][j] += a[i] * b[j];
        }
        __syncthreads();
    }
#pragma unroll
    for (int i = 0; i < 4; i++)
#pragma unroll
        for (int j = 0; j < 4; j++) {
            size_t o = (size_t)(bm + row0 + i) * 256 + bn + col0 + j;
            Ch[o] = alpha * acc[i][j] + gamma * Ah[o];
        }
}

// ---------------------------------------------------------------------------
// Bm = pinv(a2) @ a3v  -> bf16 hi/lo
// ---------------------------------------------------------------------------
__global__ void bmat_kernel(const float* __restrict__ Z, const float* __restrict__ A3V,
                            __nv_bfloat16* __restrict__ BmH, __nv_bfloat16* __restrict__ BmL)
{
    int h = blockIdx.y;
    int m0 = blockIdx.x * 4;
    __shared__ float zs[4][256];
    int tid = threadIdx.x;
    int r = tid >> 6, d = tid & 63;
    for (int lin = tid; lin < 1024; lin += 256) {
        int rr = lin >> 8, k = lin & 255;
        zs[rr][k] = Z[(size_t)h * 65536 + (size_t)(m0 + rr) * 256 + k];
    }
    __syncthreads();
    float acc = 0.f;
    for (int k = 0; k < 256; k++)
        acc += zs[r][k] * A3V[(size_t)(h * MLAND + k) * DH + d];
    size_t o = (size_t)(h * MLAND + m0 + r) * DH + d;
    __nv_bfloat16 hi = __float2bfloat16(acc);
    BmH[o] = hi;
    BmL[o] = __float2bfloat16(acc - __bfloat162float(hi));
}

// ---------------------------------------------------------------------------
// Fused conv + out-proj A staging: AHout = (O + dwconv(V)) as bf16 hi/lo at
// row (n - PADF). Rows n < PADF skipped; AH rows >= NHTOK left stale (masked
// by out-proj epilogue).
// ---------------------------------------------------------------------------
__global__ void convout_kernel(const __nv_bfloat16* __restrict__ VH,
                               const __nv_bfloat16* __restrict__ VL,
                               const float* __restrict__ O, const float* __restrict__ W,
                               __nv_bfloat16* __restrict__ Ahi, __nv_bfloat16* __restrict__ Alo)
{
    __shared__ float vs[160 * 64];
    __shared__ float ws[33];
    int h = blockIdx.y;
    int n0 = blockIdx.x * 128;
    int t = threadIdx.x;
    if (t < 33) ws[t] = W[h * LWIN + t];
    for (int lin = t; lin < 160 * 64; lin += 256) {
        int r = lin >> 6, c = lin & 63;
        int n = n0 + r - 16;
        float v = 0.f;
        if (n >= 0 && n < NP) {
            size_t o = (size_t)h * NP * DH + (size_t)n * DH + c;
            v = __bfloat162float(VH[o]) + __bfloat162float(VL[o]);
        }
        vs[lin] = v;
    }
    __syncthreads();
    int c = t & 63, rg = t >> 6;
    for (int q = 0; q < 32; q++) {
        int r = rg * 32 + q;
        int n = n0 + r;
        if (n < PADF) continue;
        float acc = 0.f;
#pragma unroll
        for (int k = 0; k < LWIN; k++) acc += ws[k] * vs[(r + k) * 64 + c];
        float v = O[(size_t)n * DMODEL + h * DH + c] + acc;
        size_t o = (size_t)(n - PADF) * DMODEL + h * DH + c;
        __nv_bfloat16 hi = __float2bfloat16(v);
        Ahi[o] = hi;
        Alo[o] = __float2bfloat16(v - __bfloat162float(hi));
    }
}

// ---------------------------------------------------------------------------
// PPEG tiled
// ---------------------------------------------------------------------------
#define PPEG_TILE (14 * 14 * 64)
#define PPEG_W7   PPEG_TILE
#define PPEG_W5   (PPEG_W7 + 64 * 49)
#define PPEG_W3   (PPEG_W5 + 64 * 25)
#define PPEG_TOT  (PPEG_W3 + 64 * 9)

__global__ void ppeg_tile_kernel(const float* __restrict__ Hin, float* __restrict__ Hout,
                                 const float* __restrict__ w7, const float* __restrict__ b7,
                                 const float* __restrict__ w5, const float* __restrict__ b5,
                                 const float* __restrict__ w3, const float* __restrict__ b3)
{
    extern __shared__ float sm[];
    float* tile = sm;
    float* ws7 = sm + PPEG_W7;
    float* ws5 = sm + PPEG_W5;
    float* ws3 = sm + PPEG_W3;

    int ti = blockIdx.x;
    int ty0 = (ti / 12) * 8, tx0 = (ti % 12) * 8;
    int cg = blockIdx.y * 64;
    int t = threadIdx.x;

    for (int lin = t; lin < PPEG_TILE; lin += 256) {
        int p = lin >> 6, c = lin & 63;
        int gy = ty0 + p / 14 - 3;
        int gx = tx0 + p % 14 - 3;
        float v = 0.f;
        if ((unsigned)gy < (unsigned)HSQ && (unsigned)gx < (unsigned)HSQ)
            v = Hin[(size_t)(1 + gy * HSQ + gx) * DMODEL + cg + c];
        tile[lin] = v;
    }
    for (int lin = t; lin < 64 * 49; lin += 256) ws7[lin] = w7[(size_t)cg * 49 + lin];
    for (int lin = t; lin < 64 * 25; lin += 256) ws5[lin] = w5[(size_t)cg * 25 + lin];
    for (int lin = t; lin < 64 * 9;  lin += 256) ws3[lin] = w3[(size_t)cg * 9 + lin];
    __syncthreads();

    int c = t & 63, pg = t >> 6;
    float bsum = b7[cg + c] + b5[cg + c] + b3[cg + c];
    for (int q = 0; q < 16; q++) {
        int p = pg * 16 + q;
        int oy = p >> 3, ox = p & 7;
        int gy = ty0 + oy, gx = tx0 + ox;
        if (gy >= HSQ || gx >= HSQ) continue;
        float acc = tile[((oy + 3) * 14 + ox + 3) * 64 + c] + bsum;
#pragma unroll
        for (int a = 0; a < 7; a++)
#pragma unroll
            for (int bq = 0; bq < 7; bq++)
                acc += ws7[c * 49 + a * 7 + bq] * tile[((oy + a) * 14 + ox + bq) * 64 + c];
#pragma unroll
        for (int a = 0; a < 5; a++)
#pragma unroll
            for (int bq = 0; bq < 5; bq++)
                acc += ws5[c * 25 + a * 5 + bq] * tile[((oy + a + 1) * 14 + ox + bq + 1) * 64 + c];
#pragma unroll
        for (int a = 0; a < 3; a++)
#pragma unroll
            for (int bq = 0; bq < 3; bq++)
                acc += ws3[c * 9 + a * 3 + bq] * tile[((oy + a + 2) * 14 + ox + bq + 2) * 64 + c];
        Hout[(size_t)(1 + gy * HSQ + gx) * DMODEL + cg + c] = acc;
    }
}

__global__ void copy_row0_kernel(const float* __restrict__ Hin, float* __restrict__ Hout)
{
    Hout[threadIdx.x] = Hin[threadIdx.x];
}

// ---------------------------------------------------------------------------
// Final head
// ---------------------------------------------------------------------------
__global__ void final_kernel(const float* __restrict__ H, const float* __restrict__ g,
                             const float* __restrict__ b, const float* __restrict__ w,
                             const float* __restrict__ bias2, float* __restrict__ out,
                             int out_size)
{
    int c = threadIdx.x;
    __shared__ float s1[512], s2[512];
    float x = H[c];
    s1[c] = x; s2[c] = x * x;
    __syncthreads();
    for (int o = 256; o > 0; o >>= 1) {
        if (c < o) { s1[c] += s1[c + o]; s2[c] += s2[c + o]; }
        __syncthreads();
    }
    float mean = s1[0] * (1.f / DMODEL);
    float var  = s2[0] * (1.f / DMODEL) - mean * mean;
    float e = (x - mean) * rsqrtf(var + EPSLN) * g[c] + b[c];
    __syncthreads();
    s1[c] = e * w[c * 2 + 0];
    s2[c] = e * w[c * 2 + 1];
    __syncthreads();
    for (int o = 256; o > 0; o >>= 1) {
        if (c < o) { s1[c] += s1[c + o]; s2[c] += s2[c + o]; }
        __syncthreads();
    }
    float l0 = s1[0] + bias2[0];
    float l1 = s2[0] + bias2[1];
    if (c == 0) {
        float m = fmaxf(l0, l1);
        float e0 = expf(l0 - m), e1 = expf(l1 - m);
        float ss = e0 + e1;
        if (out_size > 0) out[0] = l0;
        if (out_size > 1) out[1] = l1;
        if (out_size > 2) out[2] = e0 / ss;
        if (out_size > 3) out[3] = e1 / ss;
        if (out_size > 4) out[4] = (l1 > l0) ? 1.0f : 0.0f;
    }
    if (5 + c < out_size) out[5 + c] = e;
}

// ---------------------------------------------------------------------------
// Host orchestration
// ---------------------------------------------------------------------------
static float* symaddr(const void* sym)
{
    void* p = nullptr;
    cudaGetSymbolAddress(&p, sym);
    return (float*)p;
}
static __nv_bfloat16* symaddr_bf(const void* sym)
{
    void* p = nullptr;
    cudaGetSymbolAddress(&p, sym);
    return (__nv_bfloat16*)p;
}

static cudaStream_t g_side = nullptr;
static cudaEvent_t  g_evf  = nullptr;
static cudaEvent_t  g_evj  = nullptr;

extern "C" void kernel_launch(void* const* d_in, const int* in_sizes, int n_in,
                              void* d_out, int out_size)
{
    if (!g_side) {
        cudaStreamCreateWithFlags(&g_side, cudaStreamNonBlocking);
        cudaEventCreateWithFlags(&g_evf, cudaEventDisableTiming);
        cudaEventCreateWithFlags(&g_evj, cudaEventDisableTiming);
    }

    const float* x       = (const float*)d_in[0];
    const float* fc1_w   = (const float*)d_in[1];
    const float* fc1_b   = (const float*)d_in[2];
    const float* cls     = (const float*)d_in[3];
    const float* ln1_g   = (const float*)d_in[4];
    const float* ln1_b   = (const float*)d_in[5];
    const float* qkv1_w  = (const float*)d_in[6];
    const float* out1_w  = (const float*)d_in[7];
    const float* out1_b  = (const float*)d_in[8];
    const float* conv1_w = (const float*)d_in[9];
    const float* ln2_g   = (const float*)d_in[10];
    const float* ln2_b   = (const float*)d_in[11];
    const float* qkv2_w  = (const float*)d_in[12];
    const float* out2_w  = (const float*)d_in[13];
    const float* out2_b  = (const float*)d_in[14];
    const float* conv2_w = (const float*)d_in[15];
    const float* pg7_w   = (const float*)d_in[16];
    const float* pg7_b   = (const float*)d_in[17];
    const float* pg5_w   = (const float*)d_in[18];
    const float* pg5_b   = (const float*)d_in[19];
    const float* pg3_w   = (const float*)d_in[20];
    const float* pg3_b   = (const float*)d_in[21];
    const float* norm_g  = (const float*)d_in[22];
    const float* norm_b  = (const float*)d_in[23];
    const float* fc2_w   = (const float*)d_in[24];
    const float* fc2_b   = (const float*)d_in[25];

    float* H   = symaddr(g_H);
    float* H2  = symaddr(g_H2);
    float* QL  = symaddr(g_QL);
    float* KL  = symaddr(g_KL);
    float* A2  = symaddr(g_A2);
    float* Z0  = symaddr(g_Z0);
    float* Z1  = symaddr(g_Z1);
    float* W1  = symaddr(g_W1);
    float* W2  = symaddr(g_W2);
    float* W3  = symaddr(g_W3);
    float* PS  = symaddr(g_PS);
    float* A3V = symaddr(g_A3V);
    float* O   = symaddr(g_O);
    float* S   = symaddr(g_S);
    float* PVP = symaddr(g_PVP);
    __nv_bfloat16* AH  = symaddr_bf(g_AH);
    __nv_bfloat16* AL  = symaddr_bf(g_AL);
    __nv_bfloat16* QKH = symaddr_bf(g_QKH);
    __nv_bfloat16* QKL = symaddr_bf(g_QKL);
    __nv_bfloat16* WH  = symaddr_bf(g_WH);
    __nv_bfloat16* WL  = symaddr_bf(g_WL);
    __nv_bfloat16* QLH = symaddr_bf(g_QLH);
    __nv_bfloat16* QLL = symaddr_bf(g_QLL);
    __nv_bfloat16* KLH = symaddr_bf(g_KLH);
    __nv_bfloat16* KLL = symaddr_bf(g_KLL);
    __nv_bfloat16* VH  = symaddr_bf(g_VH);
    __nv_bfloat16* VL  = symaddr_bf(g_VL);
    __nv_bfloat16* PH  = symaddr_bf(g_PH);
    __nv_bfloat16* PL  = symaddr_bf(g_PL);
    __nv_bfloat16* BmH = symaddr_bf(g_BmH);
    __nv_bfloat16* BmL = symaddr_bf(g_BmL);

    const int PPEG_SMEM = PPEG_TOT * 4;
    cudaFuncSetAttribute(ppeg_tile_kernel, cudaFuncAttributeMaxDynamicSharedMemorySize, PPEG_SMEM);
    cudaFuncSetAttribute(tc_gemm_kernel,  cudaFuncAttributeMaxDynamicSharedMemorySize, TCG_SMEM);
    cudaFuncSetAttribute(slogits_kernel,  cudaFuncAttributeMaxDynamicSharedMemorySize, SLOG_SMEM);
    cudaFuncSetAttribute(pgemm_kernel,    cudaFuncAttributeMaxDynamicSharedMemorySize, PG_SMEM);

    // ---- fc1 + relu via tensor cores ----
    wconv_kernel<<<dim3(DMODEL / 32, INDIM / 32), 256>>>(fc1_w, WH, WL, INDIM, DMODEL);
    aconv_kernel<<<NTOK, 128>>>(x, AH, AL, NTOK, INDIM);
    tc_gemm_kernel<<<dim3(DMODEL / 128, NTOK / 128), 256, TCG_SMEM>>>(
        AH, AL, WH, WL, H + DMODEL, fc1_b, nullptr, nullptr, nullptr, nullptr,
        NTOK, DMODEL, INDIM, FLAG_RELU, 0, 1.f);
    assemble_kernel<<<NWRAP + 1, DMODEL>>>(cls, H);

    auto attn = [&](float* Hbuf, const float* lng, const float* lnb, const float* qkvw,
                    const float* outw, const float* outb, const float* convw) {
        // fused LN + hi/lo conversion straight into AH/AL
        lnconv_kernel<<<NP, 256>>>(Hbuf, AH, AL, lng, lnb);
        wconv_kernel<<<dim3(3 * DMODEL / 32, DMODEL / 32), 256>>>(qkvw, WH, WL, DMODEL, 3 * DMODEL);
        // qkv GEMM: split epilogue writes per-head Q/K/V hi/lo directly
        tc_gemm_kernel<<<dim3(3 * DMODEL / 128, NP / 128), 256, TCG_SMEM>>>(
            AH, AL, WH, WL, nullptr, nullptr, QKH, QKL, VH, VL,
            NP, 3 * DMODEL, DMODEL, FLAG_SPLIT, DMODEL, 0.125f);
        landmarks_kernel<<<NHEADS * MLAND, 128>>>(QKH, QKL, QL, KL, QLH, QLL, KLH, KLL);
        a2_kernel<<<dim3(MLAND, NHEADS), 256>>>(QL, KL, A2);

        // fork: pinv chain on side stream
        cudaEventRecord(g_evf, 0);
        cudaStreamWaitEvent(g_side, g_evf, 0);
        pinv_scale_kernel<<<NHEADS, 256, 0, g_side>>>(A2, PS);
        pinv_tr_kernel<<<dim3(16, NHEADS), 256, 0, g_side>>>(A2, PS, Z0);
        float* zi = Z0;
        float* zo = Z1;
        for (int it = 0; it < 6; it++) {
            nk256_kernel<<<dim3(4, 4, NHEADS), 256, 0, g_side>>>(A2, zi, W1, 1.f, 0.f);
            nk256_kernel<<<dim3(4, 4, NHEADS), 256, 0, g_side>>>(W1, W1, W2, -1.f, 7.f);
            nk256_kernel<<<dim3(4, 4, NHEADS), 256, 0, g_side>>>(W1, W2, W3, -1.f, 15.f);
            nk256_kernel<<<dim3(4, 4, NHEADS), 256, 0, g_side>>>(zi, W3, zo, -0.25f, 3.25f);
            float* t = zi; zi = zo; zo = t;
        }
        cudaEventRecord(g_evj, g_side);

        // S3 = QL @ K^T -> softmax -> A3V = P3 @ V (split-K MMA, 33 k32-chunks/slice)
        slogits_kernel<<<dim3(NP / 128, MLAND / 128, NHEADS), 256, SLOG_SMEM>>>(
            QLH, QLL, QKH + QKOFF, QKL + QKOFF, S,
            (size_t)MLAND * DH, (size_t)NP * DH, (size_t)MLAND * NP, NP);
        p3_kernel<<<dim3(MLAND, NHEADS), 256>>>(S, PH, PL);
        pgemm_kernel<<<dim3(MLAND / 128, 8, NHEADS), 256, PG_SMEM>>>(
            PH, PL, VH, VL, PVP, NP, (size_t)MLAND * NP, (size_t)NP * DH, 33, 0);
        pvred_kernel<<<64, 256>>>(PVP, A3V);

        // S1 = Q @ KL^T -> softmax
        slogits_kernel<<<dim3(MLAND / 128, NP / 128, NHEADS), 256, SLOG_SMEM>>>(
            QKH, QKL, KLH, KLL, S,
            (size_t)NP * DH, (size_t)MLAND * DH, (size_t)NP * MLAND, MLAND);
        p1_kernel<<<NP * NHEADS / 8, 256>>>(S, PH, PL);

        // join pinv; Bm; O = P1 @ Bm (8 k32-chunks); conv+staging fused
        cudaStreamWaitEvent(0, g_evj, 0);
        bmat_kernel<<<dim3(MLAND / 4, NHEADS), 256>>>(zi, A3V, BmH, BmL);
        pgemm_kernel<<<dim3(NP / 128, 1, NHEADS), 256, PG_SMEM>>>(
            PH, PL, BmH, BmL, O, MLAND, (size_t)NP * MLAND, (size_t)MLAND * DH, 8, 1);
        convout_kernel<<<dim3(NP / 128, NHEADS), 256>>>(VH, VL, O, convw, AH, AL);

        // out projection (accumulate into Hbuf) straight from AH/AL
        wconv_kernel<<<dim3(DMODEL / 32, DMODEL / 32), 256>>>(outw, WH, WL, DMODEL, DMODEL);
        tc_gemm_kernel<<<dim3(DMODEL / 128, 65), 256, TCG_SMEM>>>(
            AH, AL, WH, WL, Hbuf, outb, nullptr, nullptr, nullptr, nullptr,
            NHTOK, DMODEL, DMODEL, FLAG_ACC, 0, 1.f);
    };

    attn(H, ln1_g, ln1_b, qkv1_w, out1_w, out1_b, conv1_w);

    ppeg_tile_kernel<<<dim3(144, NHEADS), 256, PPEG_SMEM>>>(
        H, H2, pg7_w, pg7_b, pg5_w, pg5_b, pg3_w, pg3_b);
    copy_row0_kernel<<<1, DMODEL>>>(H, H2);

    attn(H2, ln2_g, ln2_b, qkv2_w, out2_w, out2_b, conv2_w);

    final_kernel<<<1, DMODEL>>>(H2, norm_g, norm_b, fc2_w, fc2_b, (float*)d_out, out_size);
}

// round 17
// speedup vs baseline: 1.2107x; 1.0078x over previous
#include <cuda_runtime.h>
#include <cuda_bf16.h>
#include <math.h>
#include <stdint.h>

// ---------------------------------------------------------------------------
// Problem constants
// ---------------------------------------------------------------------------
#define NTOK   8192
#define INDIM  1024
#define DMODEL 512
#define NHEADS 8
#define DH     64
#define MLAND  256
#define LWIN   33
#define NP     8448          // padded attention length
#define NHTOK  8282          // tokens incl cls
#define PADF   166
#define HSQ    91
#define NFEAT  8281
#define NWRAP  89
#define EPSLN  1e-5f

#define FLAG_RELU  1
#define FLAG_ACC   2
#define FLAG_SPLIT 4

// ---------------------------------------------------------------------------
// Scratch (device globals)
// ---------------------------------------------------------------------------
__device__ float g_H  [NHTOK * DMODEL];
__device__ float g_H2 [NHTOK * DMODEL];
__device__ float g_QL [NHEADS * MLAND * DH];
__device__ float g_KL [NHEADS * MLAND * DH];
__device__ float g_A2 [NHEADS * MLAND * MLAND];
__device__ float g_Z0 [NHEADS * MLAND * MLAND];
__device__ float g_Z1 [NHEADS * MLAND * MLAND];
__device__ float g_W1 [NHEADS * MLAND * MLAND];
__device__ float g_W2 [NHEADS * MLAND * MLAND];
__device__ float g_W3 [NHEADS * MLAND * MLAND];
__device__ float g_PS [NHEADS];
__device__ float g_A3V[NHEADS * MLAND * DH];
__device__ float g_O  [NP * DMODEL];
__device__ float g_S  [NHEADS * MLAND * NP];     // S3 logits scratch
__device__ float g_PVP[8 * NHEADS * MLAND * DH]; // split-K partials
// bf16 hi/lo staging
__device__ __nv_bfloat16 g_AH[NP * INDIM];       // LN output / out-proj staging
__device__ __nv_bfloat16 g_AL[NP * INDIM];
__device__ __nv_bfloat16 g_QKH[2 * NHEADS * NP * DH];  // Q then K, per-head hi
__device__ __nv_bfloat16 g_QKL[2 * NHEADS * NP * DH];  // Q then K, per-head lo
__device__ __nv_bfloat16 g_WH[3 * DMODEL * DMODEL];
__device__ __nv_bfloat16 g_WL[3 * DMODEL * DMODEL];
__device__ __nv_bfloat16 g_QLH[NHEADS * MLAND * DH];
__device__ __nv_bfloat16 g_QLL[NHEADS * MLAND * DH];
__device__ __nv_bfloat16 g_KLH[NHEADS * MLAND * DH];
__device__ __nv_bfloat16 g_KLL[NHEADS * MLAND * DH];
__device__ __nv_bfloat16 g_VH [NHEADS * NP * DH];
__device__ __nv_bfloat16 g_VL [NHEADS * NP * DH];
__device__ __nv_bfloat16 g_PH [NHEADS * NP * MLAND];
__device__ __nv_bfloat16 g_PL [NHEADS * NP * MLAND];
__device__ __nv_bfloat16 g_BmH[NHEADS * MLAND * DH];
__device__ __nv_bfloat16 g_BmL[NHEADS * MLAND * DH];

#define QKOFF (NHEADS * NP * DH)

// ---------------------------------------------------------------------------
// warp-mma helpers (sm_80+ PTX)
// ---------------------------------------------------------------------------
__device__ __forceinline__ uint32_t smem_u32(const void* p)
{
    uint32_t a;
    asm("{ .reg .u64 t; cvta.to.shared.u64 t, %1; cvt.u32.u64 %0, t; }" : "=r"(a) : "l"(p));
    return a;
}
__device__ __forceinline__ void ldsm_x4(uint32_t* r, uint32_t addr)
{
    asm volatile("ldmatrix.sync.aligned.m8n8.x4.shared.b16 {%0,%1,%2,%3}, [%4];"
                 : "=r"(r[0]), "=r"(r[1]), "=r"(r[2]), "=r"(r[3]) : "r"(addr));
}
__device__ __forceinline__ void ldsm_x2(uint32_t* r, uint32_t addr)
{
    asm volatile("ldmatrix.sync.aligned.m8n8.x2.shared.b16 {%0,%1}, [%2];"
                 : "=r"(r[0]), "=r"(r[1]) : "r"(addr));
}
__device__ __forceinline__ void ldsm_x2_trans(uint32_t* r, uint32_t addr)
{
    asm volatile("ldmatrix.sync.aligned.m8n8.x2.trans.shared.b16 {%0,%1}, [%2];"
                 : "=r"(r[0]), "=r"(r[1]) : "r"(addr));
}
__device__ __forceinline__ void mma_bf16(float* d, const uint32_t* a, const uint32_t* b)
{
    asm volatile("mma.sync.aligned.m16n8k16.row.col.f32.bf16.bf16.f32 "
                 "{%0,%1,%2,%3}, {%4,%5,%6,%7}, {%8,%9}, {%0,%1,%2,%3};"
                 : "+f"(d[0]), "+f"(d[1]), "+f"(d[2]), "+f"(d[3])
                 : "r"(a[0]), "r"(a[1]), "r"(a[2]), "r"(a[3]), "r"(b[0]), "r"(b[1]));
}
__device__ __forceinline__ void cp_async16(uint32_t smem_addr, const void* gptr)
{
    asm volatile("cp.async.ca.shared.global [%0], [%1], 16;"
                 :: "r"(smem_addr), "l"(gptr));
}
__device__ __forceinline__ void cp_commit()
{
    asm volatile("cp.async.commit_group;" ::: "memory");
}
__device__ __forceinline__ void cp_wait1()
{
    asm volatile("cp.async.wait_group 1;" ::: "memory");
}

// ---------------------------------------------------------------------------
// Weight convert+transpose: W [K][N] f32 -> Whi/Wlo [N][K] bf16
// ---------------------------------------------------------------------------
__global__ void wconv_kernel(const float* __restrict__ W,
                             __nv_bfloat16* __restrict__ Whi, __nv_bfloat16* __restrict__ Wlo,
                             int K, int N)
{
    __shared__ float tl[32][33];
    int kb = blockIdx.y * 32, nb = blockIdx.x * 32;
    int t = threadIdx.x;
    for (int i = t; i < 1024; i += 256) {
        int r = i >> 5, c = i & 31;
        tl[r][c] = W[(size_t)(kb + r) * N + nb + c];
    }
    __syncthreads();
    for (int i = t; i < 1024; i += 256) {
        int n = i >> 5, k = i & 31;
        float v = tl[k][n];
        __nv_bfloat16 h = __float2bfloat16(v);
        float lo = v - __bfloat162float(h);
        size_t o = (size_t)(nb + n) * K + kb + k;
        Whi[o] = h;
        Wlo[o] = __float2bfloat16(lo);
    }
}

// ---------------------------------------------------------------------------
// Activation convert (f32 -> hi/lo bf16, zero pad rows)
// ---------------------------------------------------------------------------
__global__ void aconv_kernel(const float* __restrict__ A,
                             __nv_bfloat16* __restrict__ Ahi, __nv_bfloat16* __restrict__ Alo,
                             int Min, int Kn)
{
    int r = blockIdx.x;
    size_t base = (size_t)r * Kn;
    if (r >= Min) {
        __nv_bfloat162 z = __float2bfloat162_rn(0.f);
        for (int c = threadIdx.x * 2; c < Kn; c += 256) {
            *reinterpret_cast<__nv_bfloat162*>(Ahi + base + c) = z;
            *reinterpret_cast<__nv_bfloat162*>(Alo + base + c) = z;
        }
        return;
    }
    for (int c = threadIdx.x * 2; c < Kn; c += 256) {
        float2 v = *reinterpret_cast<const float2*>(A + base + c);
        __nv_bfloat16 h0 = __float2bfloat16(v.x);
        __nv_bfloat16 h1 = __float2bfloat16(v.y);
        float l0 = v.x - __bfloat162float(h0);
        float l1 = v.y - __bfloat162float(h1);
        __nv_bfloat162 hp; hp.x = h0; hp.y = h1;
        __nv_bfloat162 lp; lp.x = __float2bfloat16(l0); lp.y = __float2bfloat16(l1);
        *reinterpret_cast<__nv_bfloat162*>(Ahi + base + c) = hp;
        *reinterpret_cast<__nv_bfloat162*>(Alo + base + c) = lp;
    }
}

// ---------------------------------------------------------------------------
// Fused LayerNorm + bf16 hi/lo conversion: H -> AH/AL (padded rows = 0)
// ---------------------------------------------------------------------------
__global__ void lnconv_kernel(const float* __restrict__ Hin,
                              __nv_bfloat16* __restrict__ Ahi, __nv_bfloat16* __restrict__ Alo,
                              const float* __restrict__ g, const float* __restrict__ b)
{
    int row = blockIdx.x;
    int tid = threadIdx.x;
    size_t base = (size_t)row * DMODEL;
    if (row < PADF) {
        __nv_bfloat16 z = __float2bfloat16(0.f);
        Ahi[base + tid] = z; Ahi[base + tid + 256] = z;
        Alo[base + tid] = z; Alo[base + tid + 256] = z;
        return;
    }
    const float* x = Hin + (size_t)(row - PADF) * DMODEL;
    float v0 = x[tid], v1 = x[tid + 256];
    __shared__ float s1[256], s2[256];
    s1[tid] = v0 + v1;
    s2[tid] = v0 * v0 + v1 * v1;
    __syncthreads();
    for (int o = 128; o > 0; o >>= 1) {
        if (tid < o) { s1[tid] += s1[tid + o]; s2[tid] += s2[tid + o]; }
        __syncthreads();
    }
    float mean = s1[0] * (1.f / DMODEL);
    float var  = s2[0] * (1.f / DMODEL) - mean * mean;
    float rs = rsqrtf(var + EPSLN);
    float y0 = (v0 - mean) * rs * g[tid] + b[tid];
    float y1 = (v1 - mean) * rs * g[tid + 256] + b[tid + 256];
    __nv_bfloat16 h0 = __float2bfloat16(y0);
    __nv_bfloat16 h1 = __float2bfloat16(y1);
    Ahi[base + tid]       = h0;
    Ahi[base + tid + 256] = h1;
    Alo[base + tid]       = __float2bfloat16(y0 - __bfloat162float(h0));
    Alo[base + tid + 256] = __float2bfloat16(y1 - __bfloat162float(h1));
}

// ---------------------------------------------------------------------------
// warp-MMA GEMM with cp.async double-buffered K-chunks of 32.
// C[M][N] = op(A @ B^T); 128x128 CTA tile, 8 warps (4x2).
// FLAG_SPLIT: write per-head bf16 hi/lo (QK into QKH/QKL, V into VH/VL)
// ---------------------------------------------------------------------------
#define TCP_STR  40                         // bf16 row stride (80 B, 16B-aligned)
#define TCP_BUF  (4 * 128 * TCP_STR)        // elements per buffer (20480)
#define TCG_SMEM (2 * TCP_BUF * 2)          // 81920 bytes

__global__ void __launch_bounds__(256)
tc_gemm_kernel(const __nv_bfloat16* __restrict__ Ahi, const __nv_bfloat16* __restrict__ Alo,
               const __nv_bfloat16* __restrict__ Bhi, const __nv_bfloat16* __restrict__ Blo,
               float* __restrict__ C, const float* __restrict__ bias,
               __nv_bfloat16* __restrict__ QKH, __nv_bfloat16* __restrict__ QKL,
               __nv_bfloat16* __restrict__ VH, __nv_bfloat16* __restrict__ VL,
               int Mn, int Nn, int Kn, int flags, int scale_cols, float scale)
{
    extern __shared__ __nv_bfloat16 smb[];
    const int t = threadIdx.x, lane = t & 31, wid = t >> 5;
    const int m0 = blockIdx.y * 128, n0 = blockIdx.x * 128;
    const int wm = (wid & 3) * 32;
    const int wn = (wid >> 2) * 64;

    const uint32_t smem_base = smem_u32(smb);

    const int a_row = (lane & 7) + ((lane >> 3) & 1) * 8;
    const int a_col = (lane >> 4) * 8;
    const int b_row = lane & 7;
    const int b_col = ((lane >> 3) & 1) * 8;

    const int nchunks = Kn >> 5;

    const int r1 = t >> 2,        kg1 = (t & 3) << 3;
    const int r2 = (t >> 2) + 64, kg2 = kg1;

    auto issue = [&](int ci, int buf) {
        int k0 = ci << 5;
        uint32_t bb = smem_base + (uint32_t)buf * TCP_BUF * 2;
        const __nv_bfloat16* gsrc[4] = {
            Ahi + (size_t)m0 * Kn, Alo + (size_t)m0 * Kn,
            Bhi + (size_t)n0 * Kn, Blo + (size_t)n0 * Kn };
#pragma unroll
        for (int arr = 0; arr < 4; arr++) {
            uint32_t sb = bb + (uint32_t)arr * 128 * TCP_STR * 2;
            cp_async16(sb + (uint32_t)(r1 * TCP_STR + kg1) * 2,
                       gsrc[arr] + (size_t)r1 * Kn + k0 + kg1);
            cp_async16(sb + (uint32_t)(r2 * TCP_STR + kg2) * 2,
                       gsrc[arr] + (size_t)r2 * Kn + k0 + kg2);
        }
    };

    float acc[2][8][4];
#pragma unroll
    for (int i = 0; i < 2; i++)
#pragma unroll
        for (int j = 0; j < 8; j++)
#pragma unroll
            for (int k = 0; k < 4; k++) acc[i][j][k] = 0.f;

    issue(0, 0); cp_commit();
    if (nchunks > 1) issue(1, 1);
    cp_commit();

    for (int ci = 0; ci < nchunks; ci++) {
        cp_wait1();
        __syncthreads();
        const int buf = ci & 1;
        uint32_t bb = smem_base + (uint32_t)buf * TCP_BUF * 2;
        uint32_t sAh_u = bb;
        uint32_t sAl_u = bb + 128 * TCP_STR * 2;
        uint32_t sBh_u = bb + 2 * 128 * TCP_STR * 2;
        uint32_t sBl_u = bb + 3 * 128 * TCP_STR * 2;
#pragma unroll
        for (int ks = 0; ks < 2; ks++) {
            const int kl = ks * 16;
            uint32_t ah[2][4], al[2][4];
#pragma unroll
            for (int mt = 0; mt < 2; mt++) {
                uint32_t off = (uint32_t)((wm + mt * 16 + a_row) * TCP_STR + kl + a_col) * 2;
                ldsm_x4(ah[mt], sAh_u + off);
                ldsm_x4(al[mt], sAl_u + off);
            }
#pragma unroll
            for (int ng = 0; ng < 2; ng++) {
                uint32_t bh[4][2], bl[4][2];
#pragma unroll
                for (int nt = 0; nt < 4; nt++) {
                    uint32_t off = (uint32_t)((wn + ng * 32 + nt * 8 + b_row) * TCP_STR + kl + b_col) * 2;
                    ldsm_x2(bh[nt], sBh_u + off);
                    ldsm_x2(bl[nt], sBl_u + off);
                }
#pragma unroll
                for (int mt = 0; mt < 2; mt++)
#pragma unroll
                    for (int nt = 0; nt < 4; nt++) {
                        float* d = acc[mt][ng * 4 + nt];
                        mma_bf16(d, ah[mt], bh[nt]);
                        mma_bf16(d, ah[mt], bl[nt]);
                        mma_bf16(d, al[mt], bh[nt]);
                    }
            }
        }
        __syncthreads();
        if (ci + 2 < nchunks) issue(ci + 2, buf);
        cp_commit();
    }

    const bool relu  = (flags & FLAG_RELU) != 0;
    const bool accu  = (flags & FLAG_ACC) != 0;
    const bool split = (flags & FLAG_SPLIT) != 0;
#pragma unroll
    for (int mt = 0; mt < 2; mt++) {
        int rbase = m0 + wm + mt * 16 + (lane >> 2);
#pragma unroll
        for (int nt = 0; nt < 8; nt++) {
            int c0 = n0 + wn + nt * 8 + (lane & 3) * 2;
#pragma unroll
            for (int half = 0; half < 2; half++) {
                int row = rbase + half * 8;
                if (row >= Mn) continue;
                float v0 = acc[mt][nt][half * 2 + 0];
                float v1 = acc[mt][nt][half * 2 + 1];
                if (c0 < scale_cols)     v0 *= scale;
                if (c0 + 1 < scale_cols) v1 *= scale;
                if (split) {
                    int part = c0 >> 9;
                    int h = (c0 >> 6) & 7;
                    int d = c0 & 63;
                    size_t o = (size_t)h * NP * DH + (size_t)row * DH + d;
                    __nv_bfloat16 h0 = __float2bfloat16(v0);
                    __nv_bfloat16 h1 = __float2bfloat16(v1);
                    __nv_bfloat162 hp; hp.x = h0; hp.y = h1;
                    __nv_bfloat162 lp;
                    lp.x = __float2bfloat16(v0 - __bfloat162float(h0));
                    lp.y = __float2bfloat16(v1 - __bfloat162float(h1));
                    if (part < 2) {
                        *reinterpret_cast<__nv_bfloat162*>(QKH + (size_t)part * QKOFF + o) = hp;
                        *reinterpret_cast<__nv_bfloat162*>(QKL + (size_t)part * QKOFF + o) = lp;
                    } else {
                        *reinterpret_cast<__nv_bfloat162*>(VH + o) = hp;
                        *reinterpret_cast<__nv_bfloat162*>(VL + o) = lp;
                    }
                    continue;
                }
                if (bias) { v0 += bias[c0]; v1 += bias[c0 + 1]; }
                if (relu) { v0 = fmaxf(v0, 0.f); v1 = fmaxf(v1, 0.f); }
                size_t o = (size_t)row * Nn + c0;
                if (accu) { C[o] += v0; C[o + 1] += v1; }
                else      { C[o] = v0;  C[o + 1] = v1; }
            }
        }
    }
}

// ---------------------------------------------------------------------------
// Batched logits MMA (K=64, one chunk): C[b][m][n] = A[b] @ B[b]^T
// (used for S3 only)
// ---------------------------------------------------------------------------
#define TCB_STR  72
#define SLOG_SMEM (4 * 128 * TCB_STR * 2)   // 73728 bytes

__global__ void __launch_bounds__(256)
slogits_kernel(const __nv_bfloat16* __restrict__ Ahi, const __nv_bfloat16* __restrict__ Alo,
               const __nv_bfloat16* __restrict__ Bhi, const __nv_bfloat16* __restrict__ Blo,
               float* __restrict__ C,
               size_t strideA, size_t strideB, size_t strideC, int ldc)
{
    extern __shared__ __nv_bfloat16 smb[];
    __nv_bfloat16* sAh = smb;
    __nv_bfloat16* sAl = smb + 128 * TCB_STR;
    __nv_bfloat16* sBh = smb + 2 * 128 * TCB_STR;
    __nv_bfloat16* sBl = smb + 3 * 128 * TCB_STR;

    const int t = threadIdx.x, lane = t & 31, wid = t >> 5;
    const int m0 = blockIdx.y * 128, n0 = blockIdx.x * 128;
    const int b = blockIdx.z;
    const __nv_bfloat16* Ah = Ahi + (size_t)b * strideA;
    const __nv_bfloat16* Al = Alo + (size_t)b * strideA;
    const __nv_bfloat16* Bh = Bhi + (size_t)b * strideB;
    const __nv_bfloat16* Bl = Blo + (size_t)b * strideB;
    float* Cb = C + (size_t)b * strideC;

    const int wm = (wid & 3) * 32;
    const int wn = (wid >> 2) * 64;

    const uint32_t sAh_u = smem_u32(sAh), sAl_u = smem_u32(sAl);
    const uint32_t sBh_u = smem_u32(sBh), sBl_u = smem_u32(sBl);

    const int a_row = (lane & 7) + ((lane >> 3) & 1) * 8;
    const int a_col = (lane >> 4) * 8;
    const int b_row = lane & 7;
    const int b_col = ((lane >> 3) & 1) * 8;

    float acc[2][8][4];
#pragma unroll
    for (int i = 0; i < 2; i++)
#pragma unroll
        for (int j = 0; j < 8; j++)
#pragma unroll
            for (int k = 0; k < 4; k++) acc[i][j][k] = 0.f;

    for (int i = t; i < 1024; i += 256) {
        int r = i >> 3, kg = (i & 7) << 3;
        int off = r * TCB_STR + kg;
        size_t ga = (size_t)(m0 + r) * DH + kg;
        size_t gb = (size_t)(n0 + r) * DH + kg;
        *reinterpret_cast<uint4*>(sAh + off) = *reinterpret_cast<const uint4*>(Ah + ga);
        *reinterpret_cast<uint4*>(sAl + off) = *reinterpret_cast<const uint4*>(Al + ga);
        *reinterpret_cast<uint4*>(sBh + off) = *reinterpret_cast<const uint4*>(Bh + gb);
        *reinterpret_cast<uint4*>(sBl + off) = *reinterpret_cast<const uint4*>(Bl + gb);
    }
    __syncthreads();
#pragma unroll
    for (int ks = 0; ks < 4; ks++) {
        const int kl = ks * 16;
        uint32_t ah[2][4], al[2][4];
#pragma unroll
        for (int mt = 0; mt < 2; mt++) {
            uint32_t off = (uint32_t)((wm + mt * 16 + a_row) * TCB_STR + kl + a_col) * 2;
            ldsm_x4(ah[mt], sAh_u + off);
            ldsm_x4(al[mt], sAl_u + off);
        }
#pragma unroll
        for (int ng = 0; ng < 2; ng++) {
            uint32_t bh[4][2], bl[4][2];
#pragma unroll
            for (int nt = 0; nt < 4; nt++) {
                uint32_t off = (uint32_t)((wn + ng * 32 + nt * 8 + b_row) * TCB_STR + kl + b_col) * 2;
                ldsm_x2(bh[nt], sBh_u + off);
                ldsm_x2(bl[nt], sBl_u + off);
            }
#pragma unroll
            for (int mt = 0; mt < 2; mt++)
#pragma unroll
                for (int nt = 0; nt < 4; nt++) {
                    float* d = acc[mt][nt + ng * 4];
                    mma_bf16(d, ah[mt], bh[nt]);
                    mma_bf16(d, ah[mt], bl[nt]);
                    mma_bf16(d, al[mt], bh[nt]);
                }
        }
    }

#pragma unroll
    for (int mt = 0; mt < 2; mt++) {
        int rbase = m0 + wm + mt * 16 + (lane >> 2);
#pragma unroll
        for (int nt = 0; nt < 8; nt++) {
            int c0 = n0 + wn + nt * 8 + (lane & 3) * 2;
#pragma unroll
            for (int half = 0; half < 2; half++) {
                int row = rbase + half * 8;
                size_t o = (size_t)row * ldc + c0;
                Cb[o]     = acc[mt][nt][half * 2 + 0];
                Cb[o + 1] = acc[mt][nt][half * 2 + 1];
            }
        }
    }
}

// ---------------------------------------------------------------------------
// Fused S1 logits + softmax: per CTA, 64 q-rows x full 256 landmark cols.
// Q hi/lo [h][NP][64] vs KL hi/lo [h][256][64]; softmax over 256; write P hi/lo.
// smem: operands (A 2x64x72 + B 2x256x72 bf16 = 92160 B), then reused as
// Ss f32 [64][264] (67584 B) after MMA.
// ---------------------------------------------------------------------------
#define S1F_ASTR 72
#define S1F_A   0
#define S1F_AL  (64 * S1F_ASTR)
#define S1F_B   (2 * 64 * S1F_ASTR)
#define S1F_BL  (2 * 64 * S1F_ASTR + 256 * S1F_ASTR)
#define S1F_SMEM ((2 * 64 * S1F_ASTR + 2 * 256 * S1F_ASTR) * 2)  // 92160 bytes

__global__ void __launch_bounds__(256)
s1fused_kernel(const __nv_bfloat16* __restrict__ Qh, const __nv_bfloat16* __restrict__ Ql,
               const __nv_bfloat16* __restrict__ KLh, const __nv_bfloat16* __restrict__ KLl,
               __nv_bfloat16* __restrict__ PH, __nv_bfloat16* __restrict__ PL)
{
    extern __shared__ __nv_bfloat16 smb[];
    __nv_bfloat16* sAh = smb + S1F_A;
    __nv_bfloat16* sAl = smb + S1F_AL;
    __nv_bfloat16* sBh = smb + S1F_B;
    __nv_bfloat16* sBl = smb + S1F_BL;

    const int t = threadIdx.x, lane = t & 31, wid = t >> 5;
    const int m0 = blockIdx.x * 64;
    const int head = blockIdx.y;

    const __nv_bfloat16* Ah = Qh + (size_t)head * NP * DH;
    const __nv_bfloat16* Al = Ql + (size_t)head * NP * DH;
    const __nv_bfloat16* Bh = KLh + (size_t)head * MLAND * DH;
    const __nv_bfloat16* Bl = KLl + (size_t)head * MLAND * DH;

    // warp layout: 2m x 4n -> warp tile 32 rows x 64 cols
    const int wm = (wid & 1) * 32;
    const int wn = (wid >> 1) * 64;

    const uint32_t sAh_u = smem_u32(sAh), sAl_u = smem_u32(sAl);
    const uint32_t sBh_u = smem_u32(sBh), sBl_u = smem_u32(sBl);

    const int a_row = (lane & 7) + ((lane >> 3) & 1) * 8;
    const int a_col = (lane >> 4) * 8;
    const int b_row = lane & 7;
    const int b_col = ((lane >> 3) & 1) * 8;

    // load A: 64 rows x 64 k (512 x 16B per array; 2 per thread)
    for (int i = t; i < 512; i += 256) {
        int r = i >> 3, kg = (i & 7) << 3;
        int off = r * S1F_ASTR + kg;
        size_t ga = (size_t)(m0 + r) * DH + kg;
        *reinterpret_cast<uint4*>(sAh + off) = *reinterpret_cast<const uint4*>(Ah + ga);
        *reinterpret_cast<uint4*>(sAl + off) = *reinterpret_cast<const uint4*>(Al + ga);
    }
    // load B: 256 rows x 64 k (2048 x 16B per array; 8 per thread)
    for (int i = t; i < 2048; i += 256) {
        int r = i >> 3, kg = (i & 7) << 3;
        int off = r * S1F_ASTR + kg;
        size_t gb = (size_t)r * DH + kg;
        *reinterpret_cast<uint4*>(sBh + off) = *reinterpret_cast<const uint4*>(Bh + gb);
        *reinterpret_cast<uint4*>(sBl + off) = *reinterpret_cast<const uint4*>(Bl + gb);
    }
    __syncthreads();

    float acc[2][8][4];
#pragma unroll
    for (int i = 0; i < 2; i++)
#pragma unroll
        for (int j = 0; j < 8; j++)
#pragma unroll
            for (int k = 0; k < 4; k++) acc[i][j][k] = 0.f;

#pragma unroll
    for (int ks = 0; ks < 4; ks++) {
        const int kl = ks * 16;
        uint32_t ah[2][4], al[2][4];
#pragma unroll
        for (int mt = 0; mt < 2; mt++) {
            uint32_t off = (uint32_t)((wm + mt * 16 + a_row) * S1F_ASTR + kl + a_col) * 2;
            ldsm_x4(ah[mt], sAh_u + off);
            ldsm_x4(al[mt], sAl_u + off);
        }
#pragma unroll
        for (int ng = 0; ng < 2; ng++) {
            uint32_t bh[4][2], bl[4][2];
#pragma unroll
            for (int nt = 0; nt < 4; nt++) {
                uint32_t off = (uint32_t)((wn + ng * 32 + nt * 8 + b_row) * S1F_ASTR + kl + b_col) * 2;
                ldsm_x2(bh[nt], sBh_u + off);
                ldsm_x2(bl[nt], sBl_u + off);
            }
#pragma unroll
            for (int mt = 0; mt < 2; mt++)
#pragma unroll
                for (int nt = 0; nt < 4; nt++) {
                    float* d = acc[mt][nt + ng * 4];
                    mma_bf16(d, ah[mt], bh[nt]);
                    mma_bf16(d, ah[mt], bl[nt]);
                    mma_bf16(d, al[mt], bh[nt]);
                }
        }
    }
    __syncthreads();   // all ldsm reads complete; safe to overwrite operands

    // dump fragments to Ss [64][264] f32 (aliases operand smem)
    float* Ss = reinterpret_cast<float*>(smb);
#pragma unroll
    for (int mt = 0; mt < 2; mt++) {
        int rl = wm + mt * 16 + (lane >> 2);
#pragma unroll
        for (int nt = 0; nt < 8; nt++) {
            int cc = wn + ((nt & 3) * 8) + ((nt >> 2) * 32) + (lane & 3) * 2;
            // NOTE: col mapping must match acc index: acc[mt][nt+ng*4] has col wn+ng*32+nt*8
            // handled below by recomputing from (j = nt index in 0..7): ng = j>>2, ntl = j&3
            (void)cc;
        }
    }
#pragma unroll
    for (int mt = 0; mt < 2; mt++) {
        int rl = wm + mt * 16 + (lane >> 2);
#pragma unroll
        for (int j = 0; j < 8; j++) {
            int ng = j >> 2, ntl = j & 3;
            int col = wn + ng * 32 + ntl * 8 + (lane & 3) * 2;
#pragma unroll
            for (int half = 0; half < 2; half++) {
                int row = rl + half * 8;
                Ss[row * 264 + col]     = acc[mt][j][half * 2 + 0];
                Ss[row * 264 + col + 1] = acc[mt][j][half * 2 + 1];
            }
        }
    }
    __syncthreads();

    // softmax: warp w handles rows w*8 .. w*8+7 (each row = 256 cols)
    __nv_bfloat16* ph = PH + ((size_t)head * NP + m0) * MLAND;
    __nv_bfloat16* pl = PL + ((size_t)head * NP + m0) * MLAND;
    for (int rr = 0; rr < 8; rr++) {
        int row = wid * 8 + rr;
        float a[8];
#pragma unroll
        for (int k = 0; k < 8; k++) a[k] = Ss[row * 264 + lane + k * 32];
        float m = a[0];
#pragma unroll
        for (int k = 1; k < 8; k++) m = fmaxf(m, a[k]);
        for (int o = 16; o > 0; o >>= 1) m = fmaxf(m, __shfl_xor_sync(0xffffffffu, m, o));
        float s = 0.f;
#pragma unroll
        for (int k = 0; k < 8; k++) { a[k] = __expf(a[k] - m); s += a[k]; }
        for (int o = 16; o > 0; o >>= 1) s += __shfl_xor_sync(0xffffffffu, s, o);
        float inv = 1.0f / s;
#pragma unroll
        for (int k = 0; k < 8; k++) {
            float p = a[k] * inv;
            __nv_bfloat16 hi = __float2bfloat16(p);
            ph[(size_t)row * MLAND + lane + k * 32] = hi;
            pl[(size_t)row * MLAND + lane + k * 32] = __float2bfloat16(p - __bfloat162float(hi));
        }
    }
}

// ---------------------------------------------------------------------------
// pgemm with cp.async double-buffered K-chunks of 32
// ---------------------------------------------------------------------------
#define PGP_PSTR 40
#define PGP_BSTR 72
#define PGP_PL   (128 * PGP_PSTR)
#define PGP_BH   (2 * 128 * PGP_PSTR)
#define PGP_BL   (PGP_BH + 32 * PGP_BSTR)
#define PGP_BUF  (PGP_BL + 32 * PGP_BSTR)
#define PG_SMEM  (2 * PGP_BUF * 2)

__global__ void __launch_bounds__(256)
pgemm_kernel(const __nv_bfloat16* __restrict__ Phi, const __nv_bfloat16* __restrict__ Plo,
             const __nv_bfloat16* __restrict__ Bhi, const __nv_bfloat16* __restrict__ Blo,
             float* __restrict__ Cout,
             int Pld, size_t pHeadStride, size_t bHeadStride,
             int chunksPerSlice, int mode)
{
    extern __shared__ __nv_bfloat16 smb[];
    const int t = threadIdx.x, lane = t & 31, wid = t >> 5;
    const int m0 = blockIdx.x * 128;
    const int kslice = blockIdx.y;
    const int head = blockIdx.z;

    const int c0 = kslice * chunksPerSlice;
    const int nch = chunksPerSlice;

    const __nv_bfloat16* Ph = Phi + (size_t)head * pHeadStride;
    const __nv_bfloat16* Pl = Plo + (size_t)head * pHeadStride;
    const __nv_bfloat16* Bh = Bhi + (size_t)head * bHeadStride;
    const __nv_bfloat16* Bl = Blo + (size_t)head * bHeadStride;

    const int wm = (wid & 3) * 32;
    const int wn = (wid >> 2) * 32;

    const uint32_t smem_base = smem_u32(smb);

    const int a_row = (lane & 7) + ((lane >> 3) & 1) * 8;
    const int a_col = (lane >> 4) * 8;
    const int bt_k = lane & 15;

    const int pr = t >> 2, pkg = (t & 3) << 3;
    const int br = t >> 3, bcg = (t & 7) << 3;

    auto issue = [&](int ci, int buf) {
        int k0 = ci << 5;
        uint32_t bb = smem_base + (uint32_t)buf * PGP_BUF * 2;
        cp_async16(bb + (uint32_t)(pr * PGP_PSTR + pkg) * 2,
                   Ph + (size_t)(m0 + pr) * Pld + k0 + pkg);
        cp_async16(bb + (uint32_t)((pr + 64) * PGP_PSTR + pkg) * 2,
                   Ph + (size_t)(m0 + pr + 64) * Pld + k0 + pkg);
        uint32_t pl = bb + PGP_PL * 2;
        cp_async16(pl + (uint32_t)(pr * PGP_PSTR + pkg) * 2,
                   Pl + (size_t)(m0 + pr) * Pld + k0 + pkg);
        cp_async16(pl + (uint32_t)((pr + 64) * PGP_PSTR + pkg) * 2,
                   Pl + (size_t)(m0 + pr + 64) * Pld + k0 + pkg);
        uint32_t bhh = bb + PGP_BH * 2;
        uint32_t bll = bb + PGP_BL * 2;
        cp_async16(bhh + (uint32_t)(br * PGP_BSTR + bcg) * 2,
                   Bh + (size_t)(k0 + br) * 64 + bcg);
        cp_async16(bll + (uint32_t)(br * PGP_BSTR + bcg) * 2,
                   Bl + (size_t)(k0 + br) * 64 + bcg);
    };

    float acc[2][4][4];
#pragma unroll
    for (int i = 0; i < 2; i++)
#pragma unroll
        for (int j = 0; j < 4; j++)
#pragma unroll
            for (int k = 0; k < 4; k++) acc[i][j][k] = 0.f;

    issue(c0, 0); cp_commit();
    if (nch > 1) issue(c0 + 1, 1);
    cp_commit();

    for (int ci = 0; ci < nch; ci++) {
        cp_wait1();
        __syncthreads();
        const int buf = ci & 1;
        uint32_t bb = smem_base + (uint32_t)buf * PGP_BUF * 2;
        uint32_t sPh_u = bb;
        uint32_t sPl_u = bb + PGP_PL * 2;
        uint32_t sBh_u = bb + PGP_BH * 2;
        uint32_t sBl_u = bb + PGP_BL * 2;
#pragma unroll
        for (int ks = 0; ks < 2; ks++) {
            const int kl = ks * 16;
            uint32_t ph[2][4], pl2[2][4];
#pragma unroll
            for (int mt = 0; mt < 2; mt++) {
                uint32_t off = (uint32_t)((wm + mt * 16 + a_row) * PGP_PSTR + kl + a_col) * 2;
                ldsm_x4(ph[mt], sPh_u + off);
                ldsm_x4(pl2[mt], sPl_u + off);
            }
            uint32_t bh[4][2], bl[4][2];
#pragma unroll
            for (int nt = 0; nt < 4; nt++) {
                uint32_t off = (uint32_t)((kl + bt_k) * PGP_BSTR + wn + nt * 8) * 2;
                ldsm_x2_trans(bh[nt], sBh_u + off);
                ldsm_x2_trans(bl[nt], sBl_u + off);
            }
#pragma unroll
            for (int mt = 0; mt < 2; mt++)
#pragma unroll
                for (int nt = 0; nt < 4; nt++) {
                    float* d = acc[mt][nt];
                    mma_bf16(d, ph[mt], bh[nt]);
                    mma_bf16(d, ph[mt], bl[nt]);
                    mma_bf16(d, pl2[mt], bh[nt]);
                }
        }
        __syncthreads();
        if (ci + 2 < nch) issue(c0 + ci + 2, buf);
        cp_commit();
    }

#pragma unroll
    for (int mt = 0; mt < 2; mt++) {
        int rbase = m0 + wm + mt * 16 + (lane >> 2);
#pragma unroll
        for (int nt = 0; nt < 4; nt++) {
            int c0c = wn + nt * 8 + (lane & 3) * 2;
#pragma unroll
            for (int half = 0; half < 2; half++) {
                int row = rbase + half * 8;
                float v0 = acc[mt][nt][half * 2 + 0];
                float v1 = acc[mt][nt][half * 2 + 1];
                if (mode == 0) {
                    size_t o = (((size_t)kslice * NHEADS + head) * MLAND + row) * 64 + c0c;
                    Cout[o] = v0; Cout[o + 1] = v1;
                } else {
                    size_t o = (size_t)row * DMODEL + head * 64 + c0c;
                    Cout[o] = v0; Cout[o + 1] = v1;
                }
            }
        }
    }
}

// ---------------------------------------------------------------------------
// split-K reduction: A3V = sum over 8 slices
// ---------------------------------------------------------------------------
__global__ void pvred_kernel(const float* __restrict__ PVP, float* __restrict__ A3V)
{
    int h = blockIdx.x & 7, seg = blockIdx.x >> 3;
    int idx = seg * 2048 + threadIdx.x * 8;
    for (int j = 0; j < 8; j++) {
        int li = idx + j;
        float s = 0.f;
#pragma unroll
        for (int sl = 0; sl < 8; sl++)
            s += PVP[(((size_t)sl * NHEADS + h) * MLAND * 64) + li];
        A3V[(size_t)h * MLAND * 64 + li] = s;
    }
}

// ---------------------------------------------------------------------------
// p3 softmax: S3 [h][m][NP] -> normalized P hi/lo (block per row)
// ---------------------------------------------------------------------------
__global__ void p3_kernel(const float* __restrict__ S,
                          __nv_bfloat16* __restrict__ PH, __nv_bfloat16* __restrict__ PL)
{
    int m = blockIdx.x, h = blockIdx.y;
    int t = threadIdx.x;
    const float* row = S + ((size_t)h * MLAND + m) * NP;
    float vals[33];
    float mx = -1e30f;
#pragma unroll
    for (int i = 0; i < 33; i++) {
        vals[i] = row[i * 256 + t];
        mx = fmaxf(mx, vals[i]);
    }
    __shared__ float red[256];
    red[t] = mx; __syncthreads();
    for (int o = 128; o > 0; o >>= 1) {
        if (t < o) red[t] = fmaxf(red[t], red[t + o]);
        __syncthreads();
    }
    mx = red[0]; __syncthreads();
    float sum = 0.f;
#pragma unroll
    for (int i = 0; i < 33; i++) {
        vals[i] = __expf(vals[i] - mx);
        sum += vals[i];
    }
    red[t] = sum; __syncthreads();
    for (int o = 128; o > 0; o >>= 1) {
        if (t < o) red[t] += red[t + o];
        __syncthreads();
    }
    float inv = 1.0f / red[0];
    __nv_bfloat16* ph = PH + ((size_t)h * MLAND + m) * NP;
    __nv_bfloat16* pl = PL + ((size_t)h * MLAND + m) * NP;
#pragma unroll
    for (int i = 0; i < 33; i++) {
        float p = vals[i] * inv;
        __nv_bfloat16 hi = __float2bfloat16(p);
        ph[i * 256 + t] = hi;
        pl[i * 256 + t] = __float2bfloat16(p - __bfloat162float(hi));
    }
}

// ---------------------------------------------------------------------------
// Assemble h rows: cls + wrap
// ---------------------------------------------------------------------------
__global__ void assemble_kernel(const float* __restrict__ cls, float* __restrict__ H)
{
    int j = blockIdx.x;
    int c = threadIdx.x;
    if (j == 0) H[c] = cls[c];
    else        H[(size_t)(NTOK + j) * DMODEL + c] = H[(size_t)j * DMODEL + c];
}

// ---------------------------------------------------------------------------
// Landmarks from per-head Q/K hi/lo: means of 33-groups
// ---------------------------------------------------------------------------
__global__ void landmarks_kernel(const __nv_bfloat16* __restrict__ QKH,
                                 const __nv_bfloat16* __restrict__ QKL,
                                 float* __restrict__ QL, float* __restrict__ KL,
                                 __nv_bfloat16* __restrict__ QLH, __nv_bfloat16* __restrict__ QLL,
                                 __nv_bfloat16* __restrict__ KLH, __nv_bfloat16* __restrict__ KLL)
{
    int hm = blockIdx.x;
    int h = hm >> 8, m = hm & 255;
    int tid = threadIdx.x;
    int d = tid & 63;
    int part = (tid < 64) ? 0 : 1;   // 0 = q, 1 = k
    size_t base = (size_t)part * QKOFF + (size_t)h * NP * DH + (size_t)(m * LWIN) * DH + d;
    float s = 0.f;
#pragma unroll
    for (int j = 0; j < LWIN; j++) {
        size_t idx = base + (size_t)j * DH;
        s += __bfloat162float(QKH[idx]) + __bfloat162float(QKL[idx]);
    }
    s *= (1.0f / LWIN);
    __nv_bfloat16 hi = __float2bfloat16(s);
    __nv_bfloat16 lo = __float2bfloat16(s - __bfloat162float(hi));
    size_t o = (size_t)(h * MLAND + m) * DH + d;
    if (part == 0) {
        QL[o] = s; QLH[o] = hi; QLL[o] = lo;
    } else {
        KL[o] = s; KLH[o] = hi; KLL[o] = lo;
    }
}

// ---------------------------------------------------------------------------
// a2 = softmax(q_l @ k_l^T)
// ---------------------------------------------------------------------------
__global__ void a2_kernel(const float* __restrict__ QL, const float* __restrict__ KL,
                          float* __restrict__ A2)
{
    int m = blockIdx.x, h = blockIdx.y;
    int tid = threadIdx.x;
    __shared__ float q[64];
    __shared__ float red[256];
    if (tid < 64) q[tid] = QL[(size_t)(h * MLAND + m) * DH + tid];
    __syncthreads();
    const float* kr = KL + (size_t)(h * MLAND + tid) * DH;
    float s = 0.f;
#pragma unroll
    for (int i = 0; i < 16; i++) {
        float4 kv = reinterpret_cast<const float4*>(kr)[i];
        float4 qv = reinterpret_cast<const float4*>(q)[i];
        s += kv.x * qv.x + kv.y * qv.y + kv.z * qv.z + kv.w * qv.w;
    }
    red[tid] = s; __syncthreads();
    for (int o = 128; o > 0; o >>= 1) {
        if (tid < o) red[tid] = fmaxf(red[tid], red[tid + o]);
        __syncthreads();
    }
    float mx = red[0]; __syncthreads();
    float e = __expf(s - mx);
    red[tid] = e; __syncthreads();
    for (int o = 128; o > 0; o >>= 1) {
        if (tid < o) red[tid] += red[tid + o];
        __syncthreads();
    }
    float sm = red[0];
    A2[(size_t)(h * MLAND + m) * MLAND + tid] = e / sm;
}

// ---------------------------------------------------------------------------
// pinv chain
// ---------------------------------------------------------------------------
__global__ void pinv_scale_kernel(const float* __restrict__ A2, float* __restrict__ PS)
{
    int h = blockIdx.x;
    int t = threadIdx.x;
    int w = t >> 5, lane = t & 31;
    const float* Ah = A2 + (size_t)h * 65536;
    __shared__ float rs[256];
    __shared__ float cs2[256];
    for (int r = w; r < 256; r += 8) {
        float s = 0.f;
        for (int j = lane; j < 256; j += 32) s += fabsf(Ah[r * 256 + j]);
        for (int o = 16; o > 0; o >>= 1) s += __shfl_xor_sync(0xffffffffu, s, o);
        if (lane == 0) rs[r] = s;
    }
    float cs = 0.f;
    for (int i = 0; i < 256; i++) cs += fabsf(Ah[i * 256 + t]);
    cs2[t] = cs;
    __syncthreads();
    for (int o = 128; o > 0; o >>= 1) {
        if (t < o) { rs[t] = fmaxf(rs[t], rs[t + o]); cs2[t] = fmaxf(cs2[t], cs2[t + o]); }
        __syncthreads();
    }
    if (t == 0) PS[h] = 1.0f / (rs[0] * cs2[0]);
}

__global__ void pinv_tr_kernel(const float* __restrict__ A2, const float* __restrict__ PS,
                               float* __restrict__ Z0)
{
    __shared__ float tl[64][65];
    int h = blockIdx.y;
    int seg = blockIdx.x;
    int bi = (seg >> 2) * 64, bj = (seg & 3) * 64;
    int t = threadIdx.x;
    float inv = PS[h];
    const float* Ah = A2 + (size_t)h * 65536;
    float* Zh = Z0 + (size_t)h * 65536;
    for (int lin = t; lin < 4096; lin += 256) {
        int r = lin >> 6, c = lin & 63;
        tl[r][c] = Ah[(size_t)(bi + r) * 256 + bj + c];
    }
    __syncthreads();
    for (int lin = t; lin < 4096; lin += 256) {
        int r = lin >> 6, c = lin & 63;
        Zh[(size_t)(bj + r) * 256 + bi + c] = tl[c][r] * inv;
    }
}

__global__ void nk256_kernel(const float* __restrict__ A, const float* __restrict__ B,
                             float* __restrict__ C, float alpha, float gamma)
{
    const float* Ah = A + (size_t)blockIdx.z * 65536;
    const float* Bh = B + (size_t)blockIdx.z * 65536;
    float* Ch = C + (size_t)blockIdx.z * 65536;
    __shared__ float As[16][64];
    __shared__ float Bs[16][64];
    const int bm = blockIdx.y * 64;
    const int bn = blockIdx.x * 64;
    const int tid = threadIdx.x;
    const int tx = tid & 15, ty = tid >> 4;
    const int row0 = ty * 4, col0 = tx * 4;
    float acc[4][4];
#pragma unroll
    for (int i = 0; i < 4; i++)
#pragma unroll
        for (int j = 0; j < 4; j++) acc[i][j] = 0.f;

    for (int k0 = 0; k0 < 256; k0 += 16) {
        {
            int ar = tid >> 2;
            int ac = (tid & 3) << 2;
            float4 v = *reinterpret_cast<const float4*>(Ah + (size_t)(bm + ar) * 256 + k0 + ac);
            As[ac + 0][ar] = v.x; As[ac + 1][ar] = v.y;
            As[ac + 2][ar] = v.z; As[ac + 3][ar] = v.w;
        }
        {
            int br = tid >> 4;
            int bc = (tid & 15) << 2;
            float4 v = *reinterpret_cast<const float4*>(Bh + (size_t)(k0 + br) * 256 + bn + bc);
            *reinterpret_cast<float4*>(&Bs[br][bc]) = v;
        }
        __syncthreads();
#pragma unroll
        for (int k = 0; k < 16; k++) {
            float a[4], b[4];
            *reinterpret_cast<float4*>(a) = *reinterpret_cast<const float4*>(&As[k][row0]);
            *reinterpret_cast<float4*>(b) = *reinterpret_cast<const float4*>(&Bs[k][col0]);
#pragma unroll
            for (int i = 0; i < 4; i++)
#pragma unroll
                for (int j = 0; j < 4; j++) acc[i][j] += a[i] * b[j];
        }
        __syncthreads();
    }
#pragma unroll
    for (int i = 0; i < 4; i++)
#pragma unroll
        for (int j = 0; j < 4; j++) {
            size_t o = (size_t)(bm + row0 + i) * 256 + bn + col0 + j;
            Ch[o] = alpha * acc[i][j] + gamma * Ah[o];
        }
}

// ---------------------------------------------------------------------------
// Bm = pinv(a2) @ a3v  -> bf16 hi/lo
// ---------------------------------------------------------------------------
__global__ void bmat_kernel(const float* __restrict__ Z, const float* __restrict__ A3V,
                            __nv_bfloat16* __restrict__ BmH, __nv_bfloat16* __restrict__ BmL)
{
    int h = blockIdx.y;
    int m0 = blockIdx.x * 4;
    __shared__ float zs[4][256];
    int tid = threadIdx.x;
    int r = tid >> 6, d = tid & 63;
    for (int lin = tid; lin < 1024; lin += 256) {
        int rr = lin >> 8, k = lin & 255;
        zs[rr][k] = Z[(size_t)h * 65536 + (size_t)(m0 + rr) * 256 + k];
    }
    __syncthreads();
    float acc = 0.f;
    for (int k = 0; k < 256; k++)
        acc += zs[r][k] * A3V[(size_t)(h * MLAND + k) * DH + d];
    size_t o = (size_t)(h * MLAND + m0 + r) * DH + d;
    __nv_bfloat16 hi = __float2bfloat16(acc);
    BmH[o] = hi;
    BmL[o] = __float2bfloat16(acc - __bfloat162float(hi));
}

// ---------------------------------------------------------------------------
// Fused conv + out-proj A staging: AHout = (O + dwconv(V)) as bf16 hi/lo at
// row (n - PADF). Rows n < PADF skipped; AH rows >= NHTOK left stale (masked
// by out-proj epilogue).
// ---------------------------------------------------------------------------
__global__ void convout_kernel(const __nv_bfloat16* __restrict__ VH,
                               const __nv_bfloat16* __restrict__ VL,
                               const float* __restrict__ O, const float* __restrict__ W,
                               __nv_bfloat16* __restrict__ Ahi, __nv_bfloat16* __restrict__ Alo)
{
    __shared__ float vs[160 * 64];
    __shared__ float ws[33];
    int h = blockIdx.y;
    int n0 = blockIdx.x * 128;
    int t = threadIdx.x;
    if (t < 33) ws[t] = W[h * LWIN + t];
    for (int lin = t; lin < 160 * 64; lin += 256) {
        int r = lin >> 6, c = lin & 63;
        int n = n0 + r - 16;
        float v = 0.f;
        if (n >= 0 && n < NP) {
            size_t o = (size_t)h * NP * DH + (size_t)n * DH + c;
            v = __bfloat162float(VH[o]) + __bfloat162float(VL[o]);
        }
        vs[lin] = v;
    }
    __syncthreads();
    int c = t & 63, rg = t >> 6;
    for (int q = 0; q < 32; q++) {
        int r = rg * 32 + q;
        int n = n0 + r;
        if (n < PADF) continue;
        float acc = 0.f;
#pragma unroll
        for (int k = 0; k < LWIN; k++) acc += ws[k] * vs[(r + k) * 64 + c];
        float v = O[(size_t)n * DMODEL + h * DH + c] + acc;
        size_t o = (size_t)(n - PADF) * DMODEL + h * DH + c;
        __nv_bfloat16 hi = __float2bfloat16(v);
        Ahi[o] = hi;
        Alo[o] = __float2bfloat16(v - __bfloat162float(hi));
    }
}

// ---------------------------------------------------------------------------
// PPEG tiled
// ---------------------------------------------------------------------------
#define PPEG_TILE (14 * 14 * 64)
#define PPEG_W7   PPEG_TILE
#define PPEG_W5   (PPEG_W7 + 64 * 49)
#define PPEG_W3   (PPEG_W5 + 64 * 25)
#define PPEG_TOT  (PPEG_W3 + 64 * 9)

__global__ void ppeg_tile_kernel(const float* __restrict__ Hin, float* __restrict__ Hout,
                                 const float* __restrict__ w7, const float* __restrict__ b7,
                                 const float* __restrict__ w5, const float* __restrict__ b5,
                                 const float* __restrict__ w3, const float* __restrict__ b3)
{
    extern __shared__ float sm[];
    float* tile = sm;
    float* ws7 = sm + PPEG_W7;
    float* ws5 = sm + PPEG_W5;
    float* ws3 = sm + PPEG_W3;

    int ti = blockIdx.x;
    int ty0 = (ti / 12) * 8, tx0 = (ti % 12) * 8;
    int cg = blockIdx.y * 64;
    int t = threadIdx.x;

    for (int lin = t; lin < PPEG_TILE; lin += 256) {
        int p = lin >> 6, c = lin & 63;
        int gy = ty0 + p / 14 - 3;
        int gx = tx0 + p % 14 - 3;
        float v = 0.f;
        if ((unsigned)gy < (unsigned)HSQ && (unsigned)gx < (unsigned)HSQ)
            v = Hin[(size_t)(1 + gy * HSQ + gx) * DMODEL + cg + c];
        tile[lin] = v;
    }
    for (int lin = t; lin < 64 * 49; lin += 256) ws7[lin] = w7[(size_t)cg * 49 + lin];
    for (int lin = t; lin < 64 * 25; lin += 256) ws5[lin] = w5[(size_t)cg * 25 + lin];
    for (int lin = t; lin < 64 * 9;  lin += 256) ws3[lin] = w3[(size_t)cg * 9 + lin];
    __syncthreads();

    int c = t & 63, pg = t >> 6;
    float bsum = b7[cg + c] + b5[cg + c] + b3[cg + c];
    for (int q = 0; q < 16; q++) {
        int p = pg * 16 + q;
        int oy = p >> 3, ox = p & 7;
        int gy = ty0 + oy, gx = tx0 + ox;
        if (gy >= HSQ || gx >= HSQ) continue;
        float acc = tile[((oy + 3) * 14 + ox + 3) * 64 + c] + bsum;
#pragma unroll
        for (int a = 0; a < 7; a++)
#pragma unroll
            for (int bq = 0; bq < 7; bq++)
                acc += ws7[c * 49 + a * 7 + bq] * tile[((oy + a) * 14 + ox + bq) * 64 + c];
#pragma unroll
        for (int a = 0; a < 5; a++)
#pragma unroll
            for (int bq = 0; bq < 5; bq++)
                acc += ws5[c * 25 + a * 5 + bq] * tile[((oy + a + 1) * 14 + ox + bq + 1) * 64 + c];
#pragma unroll
        for (int a = 0; a < 3; a++)
#pragma unroll
            for (int bq = 0; bq < 3; bq++)
                acc += ws3[c * 9 + a * 3 + bq] * tile[((oy + a + 2) * 14 + ox + bq + 2) * 64 + c];
        Hout[(size_t)(1 + gy * HSQ + gx) * DMODEL + cg + c] = acc;
    }
}

__global__ void copy_row0_kernel(const float* __restrict__ Hin, float* __restrict__ Hout)
{
    Hout[threadIdx.x] = Hin[threadIdx.x];
}

// ---------------------------------------------------------------------------
// Final head
// ---------------------------------------------------------------------------
__global__ void final_kernel(const float* __restrict__ H, const float* __restrict__ g,
                             const float* __restrict__ b, const float* __restrict__ w,
                             const float* __restrict__ bias2, float* __restrict__ out,
                             int out_size)
{
    int c = threadIdx.x;
    __shared__ float s1[512], s2[512];
    float x = H[c];
    s1[c] = x; s2[c] = x * x;
    __syncthreads();
    for (int o = 256; o > 0; o >>= 1) {
        if (c < o) { s1[c] += s1[c + o]; s2[c] += s2[c + o]; }
        __syncthreads();
    }
    float mean = s1[0] * (1.f / DMODEL);
    float var  = s2[0] * (1.f / DMODEL) - mean * mean;
    float e = (x - mean) * rsqrtf(var + EPSLN) * g[c] + b[c];
    __syncthreads();
    s1[c] = e * w[c * 2 + 0];
    s2[c] = e * w[c * 2 + 1];
    __syncthreads();
    for (int o = 256; o > 0; o >>= 1) {
        if (c < o) { s1[c] += s1[c + o]; s2[c] += s2[c + o]; }
        __syncthreads();
    }
    float l0 = s1[0] + bias2[0];
    float l1 = s2[0] + bias2[1];
    if (c == 0) {
        float m = fmaxf(l0, l1);
        float e0 = expf(l0 - m), e1 = expf(l1 - m);
        float ss = e0 + e1;
        if (out_size > 0) out[0] = l0;
        if (out_size > 1) out[1] = l1;
        if (out_size > 2) out[2] = e0 / ss;
        if (out_size > 3) out[3] = e1 / ss;
        if (out_size > 4) out[4] = (l1 > l0) ? 1.0f : 0.0f;
    }
    if (5 + c < out_size) out[5 + c] = e;
}

// ---------------------------------------------------------------------------
// Host orchestration
// ---------------------------------------------------------------------------
static float* symaddr(const void* sym)
{
    void* p = nullptr;
    cudaGetSymbolAddress(&p, sym);
    return (float*)p;
}
static __nv_bfloat16* symaddr_bf(const void* sym)
{
    void* p = nullptr;
    cudaGetSymbolAddress(&p, sym);
    return (__nv_bfloat16*)p;
}

static cudaStream_t g_side = nullptr;
static cudaEvent_t  g_evf  = nullptr;
static cudaEvent_t  g_evj  = nullptr;

extern "C" void kernel_launch(void* const* d_in, const int* in_sizes, int n_in,
                              void* d_out, int out_size)
{
    if (!g_side) {
        cudaStreamCreateWithFlags(&g_side, cudaStreamNonBlocking);
        cudaEventCreateWithFlags(&g_evf, cudaEventDisableTiming);
        cudaEventCreateWithFlags(&g_evj, cudaEventDisableTiming);
    }

    const float* x       = (const float*)d_in[0];
    const float* fc1_w   = (const float*)d_in[1];
    const float* fc1_b   = (const float*)d_in[2];
    const float* cls     = (const float*)d_in[3];
    const float* ln1_g   = (const float*)d_in[4];
    const float* ln1_b   = (const float*)d_in[5];
    const float* qkv1_w  = (const float*)d_in[6];
    const float* out1_w  = (const float*)d_in[7];
    const float* out1_b  = (const float*)d_in[8];
    const float* conv1_w = (const float*)d_in[9];
    const float* ln2_g   = (const float*)d_in[10];
    const float* ln2_b   = (const float*)d_in[11];
    const float* qkv2_w  = (const float*)d_in[12];
    const float* out2_w  = (const float*)d_in[13];
    const float* out2_b  = (const float*)d_in[14];
    const float* conv2_w = (const float*)d_in[15];
    const float* pg7_w   = (const float*)d_in[16];
    const float* pg7_b   = (const float*)d_in[17];
    const float* pg5_w   = (const float*)d_in[18];
    const float* pg5_b   = (const float*)d_in[19];
    const float* pg3_w   = (const float*)d_in[20];
    const float* pg3_b   = (const float*)d_in[21];
    const float* norm_g  = (const float*)d_in[22];
    const float* norm_b  = (const float*)d_in[23];
    const float* fc2_w   = (const float*)d_in[24];
    const float* fc2_b   = (const float*)d_in[25];

    float* H   = symaddr(g_H);
    float* H2  = symaddr(g_H2);
    float* QL  = symaddr(g_QL);
    float* KL  = symaddr(g_KL);
    float* A2  = symaddr(g_A2);
    float* Z0  = symaddr(g_Z0);
    float* Z1  = symaddr(g_Z1);
    float* W1  = symaddr(g_W1);
    float* W2  = symaddr(g_W2);
    float* W3  = symaddr(g_W3);
    float* PS  = symaddr(g_PS);
    float* A3V = symaddr(g_A3V);
    float* O   = symaddr(g_O);
    float* S   = symaddr(g_S);
    float* PVP = symaddr(g_PVP);
    __nv_bfloat16* AH  = symaddr_bf(g_AH);
    __nv_bfloat16* AL  = symaddr_bf(g_AL);
    __nv_bfloat16* QKH = symaddr_bf(g_QKH);
    __nv_bfloat16* QKL = symaddr_bf(g_QKL);
    __nv_bfloat16* WH  = symaddr_bf(g_WH);
    __nv_bfloat16* WL  = symaddr_bf(g_WL);
    __nv_bfloat16* QLH = symaddr_bf(g_QLH);
    __nv_bfloat16* QLL = symaddr_bf(g_QLL);
    __nv_bfloat16* KLH = symaddr_bf(g_KLH);
    __nv_bfloat16* KLL = symaddr_bf(g_KLL);
    __nv_bfloat16* VH  = symaddr_bf(g_VH);
    __nv_bfloat16* VL  = symaddr_bf(g_VL);
    __nv_bfloat16* PH  = symaddr_bf(g_PH);
    __nv_bfloat16* PL  = symaddr_bf(g_PL);
    __nv_bfloat16* BmH = symaddr_bf(g_BmH);
    __nv_bfloat16* BmL = symaddr_bf(g_BmL);

    const int PPEG_SMEM = PPEG_TOT * 4;
    cudaFuncSetAttribute(ppeg_tile_kernel, cudaFuncAttributeMaxDynamicSharedMemorySize, PPEG_SMEM);
    cudaFuncSetAttribute(tc_gemm_kernel,  cudaFuncAttributeMaxDynamicSharedMemorySize, TCG_SMEM);
    cudaFuncSetAttribute(slogits_kernel,  cudaFuncAttributeMaxDynamicSharedMemorySize, SLOG_SMEM);
    cudaFuncSetAttribute(pgemm_kernel,    cudaFuncAttributeMaxDynamicSharedMemorySize, PG_SMEM);
    cudaFuncSetAttribute(s1fused_kernel,  cudaFuncAttributeMaxDynamicSharedMemorySize, S1F_SMEM);

    // ---- fc1 + relu via tensor cores ----
    wconv_kernel<<<dim3(DMODEL / 32, INDIM / 32), 256>>>(fc1_w, WH, WL, INDIM, DMODEL);
    aconv_kernel<<<NTOK, 128>>>(x, AH, AL, NTOK, INDIM);
    tc_gemm_kernel<<<dim3(DMODEL / 128, NTOK / 128), 256, TCG_SMEM>>>(
        AH, AL, WH, WL, H + DMODEL, fc1_b, nullptr, nullptr, nullptr, nullptr,
        NTOK, DMODEL, INDIM, FLAG_RELU, 0, 1.f);
    assemble_kernel<<<NWRAP + 1, DMODEL>>>(cls, H);

    auto attn = [&](float* Hbuf, const float* lng, const float* lnb, const float* qkvw,
                    const float* outw, const float* outb, const float* convw) {
        // fused LN + hi/lo conversion straight into AH/AL
        lnconv_kernel<<<NP, 256>>>(Hbuf, AH, AL, lng, lnb);
        wconv_kernel<<<dim3(3 * DMODEL / 32, DMODEL / 32), 256>>>(qkvw, WH, WL, DMODEL, 3 * DMODEL);
        // qkv GEMM: split epilogue writes per-head Q/K/V hi/lo directly
        tc_gemm_kernel<<<dim3(3 * DMODEL / 128, NP / 128), 256, TCG_SMEM>>>(
            AH, AL, WH, WL, nullptr, nullptr, QKH, QKL, VH, VL,
            NP, 3 * DMODEL, DMODEL, FLAG_SPLIT, DMODEL, 0.125f);
        landmarks_kernel<<<NHEADS * MLAND, 128>>>(QKH, QKL, QL, KL, QLH, QLL, KLH, KLL);
        a2_kernel<<<dim3(MLAND, NHEADS), 256>>>(QL, KL, A2);

        // fork: pinv chain on side stream
        cudaEventRecord(g_evf, 0);
        cudaStreamWaitEvent(g_side, g_evf, 0);
        pinv_scale_kernel<<<NHEADS, 256, 0, g_side>>>(A2, PS);
        pinv_tr_kernel<<<dim3(16, NHEADS), 256, 0, g_side>>>(A2, PS, Z0);
        float* zi = Z0;
        float* zo = Z1;
        for (int it = 0; it < 6; it++) {
            nk256_kernel<<<dim3(4, 4, NHEADS), 256, 0, g_side>>>(A2, zi, W1, 1.f, 0.f);
            nk256_kernel<<<dim3(4, 4, NHEADS), 256, 0, g_side>>>(W1, W1, W2, -1.f, 7.f);
            nk256_kernel<<<dim3(4, 4, NHEADS), 256, 0, g_side>>>(W1, W2, W3, -1.f, 15.f);
            nk256_kernel<<<dim3(4, 4, NHEADS), 256, 0, g_side>>>(zi, W3, zo, -0.25f, 3.25f);
            float* t = zi; zi = zo; zo = t;
        }
        cudaEventRecord(g_evj, g_side);

        // S3 = QL @ K^T -> softmax -> A3V = P3 @ V (split-K MMA, 33 k32-chunks/slice)
        slogits_kernel<<<dim3(NP / 128, MLAND / 128, NHEADS), 256, SLOG_SMEM>>>(
            QLH, QLL, QKH + QKOFF, QKL + QKOFF, S,
            (size_t)MLAND * DH, (size_t)NP * DH, (size_t)MLAND * NP, NP);
        p3_kernel<<<dim3(MLAND, NHEADS), 256>>>(S, PH, PL);
        pgemm_kernel<<<dim3(MLAND / 128, 8, NHEADS), 256, PG_SMEM>>>(
            PH, PL, VH, VL, PVP, NP, (size_t)MLAND * NP, (size_t)NP * DH, 33, 0);
        pvred_kernel<<<64, 256>>>(PVP, A3V);

        // S1 logits + softmax fused -> P1 hi/lo (overwrites PH/PL after pgemm0)
        s1fused_kernel<<<dim3(NP / 64, NHEADS), 256, S1F_SMEM>>>(
            QKH, QKL, KLH, KLL, PH, PL);

        // join pinv; Bm; O = P1 @ Bm (8 k32-chunks); conv+staging fused
        cudaStreamWaitEvent(0, g_evj, 0);
        bmat_kernel<<<dim3(MLAND / 4, NHEADS), 256>>>(zi, A3V, BmH, BmL);
        pgemm_kernel<<<dim3(NP / 128, 1, NHEADS), 256, PG_SMEM>>>(
            PH, PL, BmH, BmL, O, MLAND, (size_t)NP * MLAND, (size_t)MLAND * DH, 8, 1);
        convout_kernel<<<dim3(NP / 128, NHEADS), 256>>>(VH, VL, O, convw, AH, AL);

        // out projection (accumulate into Hbuf) straight from AH/AL
        wconv_kernel<<<dim3(DMODEL / 32, DMODEL / 32), 256>>>(outw, WH, WL, DMODEL, DMODEL);
        tc_gemm_kernel<<<dim3(DMODEL / 128, 65), 256, TCG_SMEM>>>(
            AH, AL, WH, WL, Hbuf, outb, nullptr, nullptr, nullptr, nullptr,
            NHTOK, DMODEL, DMODEL, FLAG_ACC, 0, 1.f);
    };

    attn(H, ln1_g, ln1_b, qkv1_w, out1_w, out1_b, conv1_w);

    ppeg_tile_kernel<<<dim3(144, NHEADS), 256, PPEG_SMEM>>>(
        H, H2, pg7_w, pg7_b, pg5_w, pg5_b, pg3_w, pg3_b);
    copy_row0_kernel<<<1, DMODEL>>>(H, H2);

    attn(H2, ln2_g, ln2_b, qkv2_w, out2_w, out2_b, conv2_w);

    final_kernel<<<1, DMODEL>>>(H2, norm_g, norm_b, fc2_w, fc2_b, (float*)d_out, out_size);
}